// round 8
// baseline (speedup 1.0000x reference)
#include <cuda_runtime.h>
#include <cuda_bf16.h>
#include <stdint.h>
#include <math.h>

// Problem constants
#define TT 65536
#define DD 256
#define LL 3

// GEMM tiling
#define BM 64
#define BN 128
#define KC 32
#define NCHUNK (DD / KC)   // 8

#define ROWB 80                     // padded smem row stride (bytes)
#define PLA (64 * ROWB)             // A plane: 5120 B
#define PLB (128 * ROWB)            // B plane: 10240 B
#define BOFF (6 * PLA)              // 30720
#define BUFSZ (6 * PLA + 6 * PLB)   // 92160
#define SM_BIAS (2 * BUFSZ)         // 184320
#define SMEM_TOTAL (SM_BIAS + 1024 + 64)
#define SM_SEG (2 * 64 * 132 * 4)   // 67584 (after smA/smB, inside buf0)

// Scan blocking (block = gemm CTA M-tile)
#define CS 64
#define NB (TT / CS)  // 1024

// ---------------------------------------------------------------------------
// Scratch
// ---------------------------------------------------------------------------
__device__ __align__(256) float g_af[TT * DD];
__device__ __align__(256) float g_bf[TT * DD];
__device__ __align__(256) float g_ab[TT * DD];
__device__ __align__(256) float g_bb[TT * DD];
__device__ __align__(256) float g_aggA_f[NB * DD];
__device__ __align__(256) float g_aggB_f[NB * DD];
__device__ __align__(256) float g_hex_f[NB * DD];
__device__ __align__(256) float g_aggA_b[NB * DD];
__device__ __align__(256) float g_aggB_b[NB * DD];
__device__ __align__(256) float g_hex_b[NB * DD];
// bf16 hi/lo operand planes
__device__ __align__(256) __nv_bfloat16 g_xh[TT * DD];
__device__ __align__(256) __nv_bfloat16 g_xl[TT * DD];
__device__ __align__(256) __nv_bfloat16 g_qh[TT * DD];
__device__ __align__(256) __nv_bfloat16 g_ql[TT * DD];
__device__ __align__(256) __nv_bfloat16 g_uh[TT * DD];
__device__ __align__(256) __nv_bfloat16 g_ul[TT * DD];
// pre-transposed hi/lo-split weights: [5 layer-dirs][3 mats][256 n][256 k]
__device__ __align__(256) __nv_bfloat16 g_whi[5 * 3 * DD * DD];
__device__ __align__(256) __nv_bfloat16 g_wlo[5 * 3 * DD * DD];
// layer-0 effective h-bias (bh + Whq^T q0): [2 dirs][256]
__device__ __align__(256) float g_bheff[2 * DD];

__device__ __forceinline__ float tanh_fast(float v) {
    float r;
    asm("tanh.approx.f32 %0, %1;" : "=f"(r) : "f"(v));
    return r;
}
__device__ __forceinline__ uint32_t smem_u32(const void* p) {
    uint32_t a;
    asm("{ .reg .u64 t; cvta.to.shared.u64 t, %1; cvt.u32.u64 %0, t; }"
        : "=r"(a) : "l"(p));
    return a;
}
__device__ __forceinline__ void ldsm4(uint32_t addr, uint32_t* r) {
    asm volatile("ldmatrix.sync.aligned.m8n8.x4.shared.b16 {%0,%1,%2,%3}, [%4];"
                 : "=r"(r[0]), "=r"(r[1]), "=r"(r[2]), "=r"(r[3]) : "r"(addr));
}
__device__ __forceinline__ void mma16816(float* c, const uint32_t* a,
                                         const uint32_t* b) {
    asm volatile(
        "mma.sync.aligned.m16n8k16.row.col.f32.bf16.bf16.f32 "
        "{%0,%1,%2,%3}, {%4,%5,%6,%7}, {%8,%9}, {%0,%1,%2,%3};"
        : "+f"(c[0]), "+f"(c[1]), "+f"(c[2]), "+f"(c[3])
        : "r"(a[0]), "r"(a[1]), "r"(a[2]), "r"(a[3]), "r"(b[0]), "r"(b[1]));
}
// L1-allocating async copy (the .cg L1 bypass was the R7 regression)
__device__ __forceinline__ void cpa16(uint32_t dst, const void* src) {
    asm volatile("cp.async.ca.shared.global [%0], [%1], 16;"
                 :: "r"(dst), "l"(src) : "memory");
}

// hi/lo bf16 split of a float4; one 8B store each
__device__ __forceinline__ void split_store(float4 v, char* hi, char* lo) {
    __nv_bfloat16 h0 = __float2bfloat16_rn(v.x);
    __nv_bfloat16 h1 = __float2bfloat16_rn(v.y);
    __nv_bfloat16 h2 = __float2bfloat16_rn(v.z);
    __nv_bfloat16 h3 = __float2bfloat16_rn(v.w);
    __nv_bfloat162 H0; H0.x = h0; H0.y = h1;
    __nv_bfloat162 H1; H1.x = h2; H1.y = h3;
    __nv_bfloat162 L0, L1;
    L0.x = __float2bfloat16_rn(v.x - __bfloat162float(h0));
    L0.y = __float2bfloat16_rn(v.y - __bfloat162float(h1));
    L1.x = __float2bfloat16_rn(v.z - __bfloat162float(h2));
    L1.y = __float2bfloat16_rn(v.w - __bfloat162float(h3));
    uint2 H; H.x = *(uint32_t*)&H0; H.y = *(uint32_t*)&H1;
    uint2 L; L.x = *(uint32_t*)&L0; L.y = *(uint32_t*)&L1;
    *(uint2*)hi = H;
    *(uint2*)lo = L;
}

// ---------------------------------------------------------------------------
// prep_weights_all: all 5 layer-dirs in ONE launch. grid (256 n, 3 mats, 5 slots)
// ---------------------------------------------------------------------------
__global__ void prep_weights_all(const float* __restrict__ Wz_f,
                                 const float* __restrict__ Wh_f,
                                 const float* __restrict__ Wz_b,
                                 const float* __restrict__ Wh_b,
                                 __nv_bfloat16* __restrict__ whi,
                                 __nv_bfloat16* __restrict__ wlo) {
    int n = blockIdx.x, m = blockIdx.y, s = blockIdx.z, k = threadIdx.x;
    const float* Wz;
    const float* Wh;
    if (s < 3) { Wz = Wz_f + s * DD * DD; Wh = Wh_f + s * 2 * DD * DD; }
    else       { Wz = Wz_b + (s - 3) * DD * DD; Wh = Wh_b + (s - 3) * 2 * DD * DD; }
    float v = (m == 0) ? Wz[k * DD + n]
            : (m == 1) ? Wh[k * DD + n]
                       : Wh[(DD + k) * DD + n];
    __nv_bfloat16 hi = __float2bfloat16_rn(v);
    __nv_bfloat16 lo = __float2bfloat16_rn(v - __bfloat162float(hi));
    size_t o = (size_t)(s * 3 + m) * DD * DD + (size_t)n * DD + k;
    whi[o] = hi;
    wlo[o] = lo;
}

// ---------------------------------------------------------------------------
// prep_x: split story -> (xh,xl); u0 = story*q0 -> (uh,ul)
// ---------------------------------------------------------------------------
__global__ void prep_x(const float* __restrict__ story,
                       const float* __restrict__ question,
                       __nv_bfloat16* __restrict__ xh, __nv_bfloat16* __restrict__ xl,
                       __nv_bfloat16* __restrict__ uh, __nv_bfloat16* __restrict__ ul)
{
    int idx = blockIdx.x * 256 + threadIdx.x;   // float4 index
    int c = (idx & 63) << 2;
    float4 xv = ((const float4*)story)[idx];
    float4 qv = *(const float4*)(question + c);
    float4 uv = make_float4(xv.x * qv.x, xv.y * qv.y, xv.z * qv.z, xv.w * qv.w);
    split_store(xv, (char*)xh + (size_t)idx * 8, (char*)xl + (size_t)idx * 8);
    split_store(uv, (char*)uh + (size_t)idx * 8, (char*)ul + (size_t)idx * 8);
}

// ---------------------------------------------------------------------------
// prep_bias: bheff[dir][n] = bh[n] + sum_k q0[k] * Whq[k][n]   (layer 0)
// ---------------------------------------------------------------------------
__global__ void prep_bias(const float* __restrict__ question,
                          const float* __restrict__ Wh_f, const float* __restrict__ bh_f,
                          const float* __restrict__ Wh_b, const float* __restrict__ bh_b,
                          float* __restrict__ bheff)
{
    __shared__ float red[256];
    int n = blockIdx.x, k = threadIdx.x;
    const float* Wh = blockIdx.y ? Wh_b : Wh_f;
    const float* bh = blockIdx.y ? bh_b : bh_f;
    red[k] = question[k] * Wh[(DD + k) * DD + n];
    __syncthreads();
    for (int s = 128; s > 0; s >>= 1) {
        if (k < s) red[k] += red[k + s];
        __syncthreads();
    }
    if (k == 0) bheff[blockIdx.y * DD + n] = bh[n] + red[0];
}

// ---------------------------------------------------------------------------
// Fused GEMM (mma.sync bf16, 3-pass hi/lo) + activation + block-local scan.
// CTA tile: 64 timesteps x 128 channels. Warp layout 2M x 4N, warp tile 32x32.
// ---------------------------------------------------------------------------
__global__ void __launch_bounds__(256, 1) gemm_mma(
    const __nv_bfloat16* __restrict__ uh, const __nv_bfloat16* __restrict__ ul,
    const __nv_bfloat16* __restrict__ xh, const __nv_bfloat16* __restrict__ xl,
    const __nv_bfloat16* __restrict__ qh, const __nv_bfloat16* __restrict__ ql,
    int use_q, int rev,
    const __nv_bfloat16* __restrict__ whi, const __nv_bfloat16* __restrict__ wlo,
    const float* __restrict__ bz, const float* __restrict__ bh,
    float* __restrict__ outA, float* __restrict__ outB,
    float* __restrict__ aggA, float* __restrict__ aggB)
{
    extern __shared__ char smem[];
    const int tid = threadIdx.x;
    const int wid = tid >> 5;
    const int lane = tid & 31;
    const int wm = wid & 1;        // 2 M warp-tiles of 32 rows
    const int wn = wid >> 1;       // 4 N warp-tiles of 32 cols
    const int tbase = blockIdx.x * BM;
    const int nbase = blockIdx.y * BN;
    const uint32_t sb = smem_u32(smem);

    float* bzs = (float*)(smem + SM_BIAS);
    float* bhs = bzs + 128;
    if (tid < 128) {
        bzs[tid] = bz[nbase + tid];
        bhs[tid] = bh[nbase + tid];
    }

    const __nv_bfloat16* a6[6] = { uh, ul, xh, xl, qh, ql };
    const __nv_bfloat16* w6[6] = {
        whi, wlo, whi + DD * DD, wlo + DD * DD, whi + 2 * DD * DD, wlo + 2 * DD * DD
    };
    const int np = use_q ? 6 : 4;

    float acc[2][2][4][4];
    #pragma unroll
    for (int zh = 0; zh < 2; ++zh)
        #pragma unroll
        for (int mt = 0; mt < 2; ++mt)
            #pragma unroll
            for (int nt = 0; nt < 4; ++nt)
                #pragma unroll
                for (int j = 0; j < 4; ++j) acc[zh][mt][nt][j] = 0.f;

    const int jrow = tid >> 2;   // 0..63
    const int seg4 = tid & 3;    // 16B segment within 64B k-slice

    auto stage_chunk = [&](int c) {
        const uint32_t base = sb + (c & 1) * BUFSZ;
        const int k0 = c * KC;
        #pragma unroll
        for (int p = 0; p < 6; ++p) {
            if (p < np) {
                int tg = rev ? (TT - 1 - (tbase + jrow)) : (tbase + jrow);
                cpa16(base + p * PLA + jrow * ROWB + seg4 * 16,
                      a6[p] + (size_t)tg * DD + k0 + seg4 * 8);
                #pragma unroll
                for (int h = 0; h < 2; ++h) {
                    int row = jrow + h * 64;
                    cpa16(base + BOFF + p * PLB + row * ROWB + seg4 * 16,
                          w6[p] + (size_t)(nbase + row) * DD + k0 + seg4 * 8);
                }
            }
        }
    };

    stage_chunk(0);
    asm volatile("cp.async.commit_group;" ::: "memory");

    const int r = lane & 7, g = lane >> 3;
    #pragma unroll 1
    for (int c = 0; c < NCHUNK; ++c) {
        asm volatile("cp.async.wait_group 0;" ::: "memory");
        __syncthreads();
        if (c < NCHUNK - 1) {
            stage_chunk(c + 1);
            asm volatile("cp.async.commit_group;" ::: "memory");
        }
        const uint32_t abuf = sb + (c & 1) * BUFSZ;
        const uint32_t bbuf = abuf + BOFF;

        #pragma unroll
        for (int ks = 0; ks < 2; ++ks) {
            const uint32_t kso = ks * 32;
            uint32_t af[6][2][4];
            #pragma unroll
            for (int o = 0; o < 6; ++o)
                if (o < np) {
                    #pragma unroll
                    for (int mt = 0; mt < 2; ++mt) {
                        uint32_t addr = abuf + o * PLA
                            + (wm * 32 + mt * 16 + (g & 1) * 8 + r) * ROWB
                            + (g >> 1) * 16 + kso;
                        ldsm4(addr, af[o][mt]);
                    }
                }
            uint32_t bf[6][4][2];
            #pragma unroll
            for (int m6 = 0; m6 < 6; ++m6)
                if (m6 < np) {
                    #pragma unroll
                    for (int j = 0; j < 2; ++j) {
                        uint32_t tmp[4];
                        uint32_t addr = bbuf + m6 * PLB
                            + (wn * 32 + (2 * j + (g >> 1)) * 8 + r) * ROWB
                            + (g & 1) * 16 + kso;
                        ldsm4(addr, tmp);
                        bf[m6][2 * j][0] = tmp[0]; bf[m6][2 * j][1] = tmp[1];
                        bf[m6][2 * j + 1][0] = tmp[2]; bf[m6][2 * j + 1][1] = tmp[3];
                    }
                }
            #pragma unroll
            for (int mt = 0; mt < 2; ++mt)
                #pragma unroll
                for (int nt = 0; nt < 4; ++nt) {
                    mma16816(acc[0][mt][nt], af[0][mt], bf[0][nt]);
                    mma16816(acc[0][mt][nt], af[0][mt], bf[1][nt]);
                    mma16816(acc[0][mt][nt], af[1][mt], bf[0][nt]);
                    mma16816(acc[1][mt][nt], af[2][mt], bf[2][nt]);
                    mma16816(acc[1][mt][nt], af[2][mt], bf[3][nt]);
                    mma16816(acc[1][mt][nt], af[3][mt], bf[2][nt]);
                    if (use_q) {
                        mma16816(acc[1][mt][nt], af[4][mt], bf[4][nt]);
                        mma16816(acc[1][mt][nt], af[4][mt], bf[5][nt]);
                        mma16816(acc[1][mt][nt], af[5][mt], bf[4][nt]);
                    }
                }
        }
    }

    // --- epilogue: activations -> smem transpose (64 rows x 132 stride) ----
    float* smA = (float*)smem;
    float* smB = smA + 64 * 132;
    #pragma unroll
    for (int mt = 0; mt < 2; ++mt)
        #pragma unroll
        for (int nt = 0; nt < 4; ++nt) {
            int col = wn * 32 + nt * 8 + 2 * (lane & 3);
            int row0 = wm * 32 + mt * 16 + (lane >> 2);
            #pragma unroll
            for (int h8 = 0; h8 < 2; ++h8) {
                int row = row0 + h8 * 8;
                float z0 = 0.5f * tanh_fast(0.5f * (acc[0][mt][nt][2*h8+0] + bzs[col]))   + 0.5f;
                float z1 = 0.5f * tanh_fast(0.5f * (acc[0][mt][nt][2*h8+1] + bzs[col+1])) + 0.5f;
                float t0 = tanh_fast(acc[1][mt][nt][2*h8+0] + bhs[col]);
                float t1 = tanh_fast(acc[1][mt][nt][2*h8+1] + bhs[col+1]);
                *(float2*)(smA + row * 132 + col) = make_float2(1.f - z0, 1.f - z1);
                *(float2*)(smB + row * 132 + col) = make_float2(z0 * t0, z1 * t1);
            }
        }
    __syncthreads();

    // --- fused block-local scan over 64 rows (2 segments x 32) -------------
    float* segA = (float*)(smem + SM_SEG);        // [2][128]
    float* segB = segA + 2 * 128;
    {
        const int col = tid & 127;
        const int sg = tid >> 7;                   // 0..1
        const int rbase = sg * 32;
        float Ap = 1.f, hl = 0.f;
        #pragma unroll 8
        for (int i = 0; i < 32; ++i) {
            int off = (rbase + i) * 132 + col;
            float a = smA[off], b = smB[off];
            Ap *= a;
            hl = fmaf(a, hl, b);
            smA[off] = Ap;
            smB[off] = hl;
        }
        segA[sg * 128 + col] = Ap;
        segB[sg * 128 + col] = hl;
        __syncthreads();
        if (sg == 1) {
            float Ain = segA[col], Hin = segB[col];
            #pragma unroll 8
            for (int i = 0; i < 32; ++i) {
                int off = (rbase + i) * 132 + col;
                float Al = smA[off], Bl = smB[off];
                smA[off] = Ain * Al;
                smB[off] = fmaf(Al, Hin, Bl);
            }
            aggA[(size_t)blockIdx.x * DD + nbase + col] = Ain * Ap;
            aggB[(size_t)blockIdx.x * DD + nbase + col] = fmaf(Ap, Hin, hl);
        }
    }
    __syncthreads();

    // --- coalesced global stores -------------------------------------------
    #pragma unroll
    for (int it = 0; it < 8; ++it) {
        int j = tid + it * 256;
        int row = j >> 5, cf = j & 31;
        size_t go = (size_t)(tbase + row) * DD + nbase + cf * 4;
        *(float4*)(outA + go) = *(const float4*)(smA + row * 132 + cf * 4);
        *(float4*)(outB + go) = *(const float4*)(smB + row * 132 + cf * 4);
    }
}

// ---------------------------------------------------------------------------
// scan2: exclusive scan over NB block aggregates, batched register prefetch.
// ---------------------------------------------------------------------------
__global__ void scan2_kernel(const float* __restrict__ aggA,
                             const float* __restrict__ aggB,
                             float* __restrict__ hex)
{
    const int d = threadIdx.x;
    float H = 0.f;
    for (int b0 = 0; b0 < NB; b0 += 16) {
        float a[16], bb[16];
        #pragma unroll
        for (int i = 0; i < 16; ++i) {
            a[i]  = aggA[(size_t)(b0 + i) * DD + d];
            bb[i] = aggB[(size_t)(b0 + i) * DD + d];
        }
        #pragma unroll
        for (int i = 0; i < 16; ++i) {
            hex[(size_t)(b0 + i) * DD + d] = H;
            H = fmaf(a[i], H, bb[i]);
        }
    }
}

// ---------------------------------------------------------------------------
// combine: q = h_fwd + h_bwd_rev; write (qh,ql) and (uh,ul) with u = story*q.
// ---------------------------------------------------------------------------
__global__ void combine_kernel(
    const float* __restrict__ Af, const float* __restrict__ Bf,
    const float* __restrict__ hexf,
    const float* __restrict__ Ab, const float* __restrict__ Bb,
    const float* __restrict__ hexb,
    const float* __restrict__ story,
    __nv_bfloat16* __restrict__ qh, __nv_bfloat16* __restrict__ ql,
    __nv_bfloat16* __restrict__ uh, __nv_bfloat16* __restrict__ ul)
{
    int idx = blockIdx.x * blockDim.x + threadIdx.x;   // float4 index
    int t = idx >> 6;
    int c = (idx & 63) << 2;
    int tr = TT - 1 - t;
    int blf = t >> 6;        // CS = 64
    int blb = tr >> 6;

    float4 af = *(const float4*)(Af + (size_t)t * DD + c);
    float4 bfv = *(const float4*)(Bf + (size_t)t * DD + c);
    float4 hf = *(const float4*)(hexf + (size_t)blf * DD + c);
    float4 ab = *(const float4*)(Ab + (size_t)tr * DD + c);
    float4 bb = *(const float4*)(Bb + (size_t)tr * DD + c);
    float4 hb = *(const float4*)(hexb + (size_t)blb * DD + c);

    float4 q4;
    q4.x = fmaf(af.x, hf.x, bfv.x) + fmaf(ab.x, hb.x, bb.x);
    q4.y = fmaf(af.y, hf.y, bfv.y) + fmaf(ab.y, hb.y, bb.y);
    q4.z = fmaf(af.z, hf.z, bfv.z) + fmaf(ab.z, hb.z, bb.z);
    q4.w = fmaf(af.w, hf.w, bfv.w) + fmaf(ab.w, hb.w, bb.w);

    float4 xv = *(const float4*)(story + (size_t)t * DD + c);
    float4 u4 = make_float4(xv.x * q4.x, xv.y * q4.y, xv.z * q4.z, xv.w * q4.w);

    split_store(q4, (char*)qh + (size_t)idx * 8, (char*)ql + (size_t)idx * 8);
    split_store(u4, (char*)uh + (size_t)idx * 8, (char*)ul + (size_t)idx * 8);
}

__global__ void final_kernel(const float* __restrict__ Af,
                             const float* __restrict__ Bf,
                             const float* __restrict__ hexf,
                             float* __restrict__ out)
{
    const int d = threadIdx.x;
    out[d] = fmaf(Af[(size_t)(TT - 1) * DD + d], hexf[(size_t)(NB - 1) * DD + d],
                  Bf[(size_t)(TT - 1) * DD + d]);
}

// ---------------------------------------------------------------------------
// Host orchestration
// ---------------------------------------------------------------------------
extern "C" void kernel_launch(void* const* d_in, const int* in_sizes, int n_in,
                              void* d_out, int out_size)
{
    const float* story    = (const float*)d_in[0];
    const float* question = (const float*)d_in[1];
    const float* Wz_f = (const float*)d_in[2];
    const float* bz_f = (const float*)d_in[3];
    const float* Wh_f = (const float*)d_in[4];
    const float* bh_f = (const float*)d_in[5];
    const float* Wz_b = (const float*)d_in[6];
    const float* bz_b = (const float*)d_in[7];
    const float* Wh_b = (const float*)d_in[8];
    const float* bh_b = (const float*)d_in[9];
    float* out = (float*)d_out;

    float *af, *bf, *ab, *bb, *aggAf, *aggBf, *hexf, *aggAb, *aggBb, *hexb, *bheff;
    __nv_bfloat16 *whi, *wlo, *xh, *xl, *qh, *ql, *uh, *ul;
    cudaGetSymbolAddress((void**)&af,    g_af);
    cudaGetSymbolAddress((void**)&bf,    g_bf);
    cudaGetSymbolAddress((void**)&ab,    g_ab);
    cudaGetSymbolAddress((void**)&bb,    g_bb);
    cudaGetSymbolAddress((void**)&aggAf, g_aggA_f);
    cudaGetSymbolAddress((void**)&aggBf, g_aggB_f);
    cudaGetSymbolAddress((void**)&hexf,  g_hex_f);
    cudaGetSymbolAddress((void**)&aggAb, g_aggA_b);
    cudaGetSymbolAddress((void**)&aggBb, g_aggB_b);
    cudaGetSymbolAddress((void**)&hexb,  g_hex_b);
    cudaGetSymbolAddress((void**)&whi,   g_whi);
    cudaGetSymbolAddress((void**)&wlo,   g_wlo);
    cudaGetSymbolAddress((void**)&xh,    g_xh);
    cudaGetSymbolAddress((void**)&xl,    g_xl);
    cudaGetSymbolAddress((void**)&qh,    g_qh);
    cudaGetSymbolAddress((void**)&ql,    g_ql);
    cudaGetSymbolAddress((void**)&uh,    g_uh);
    cudaGetSymbolAddress((void**)&ul,    g_ul);
    cudaGetSymbolAddress((void**)&bheff, g_bheff);

    static int smem_set = 0;
    if (!smem_set) {
        cudaFuncSetAttribute(gemm_mma, cudaFuncAttributeMaxDynamicSharedMemorySize,
                             SMEM_TOTAL);
        smem_set = 1;
    }

    // Launch 0: merged weight prep; 1: prep_x; 2: prep_bias.
    // (Keeps gemm_mma within the ncu -s 5 -c 1 capture window.)
    prep_weights_all<<<dim3(DD, 3, 5), 256>>>(Wz_f, Wh_f, Wz_b, Wh_b, whi, wlo);
    prep_x<<<TT * DD / 4 / 256, 256>>>(story, question, xh, xl, uh, ul);
    prep_bias<<<dim3(DD, 2), 256>>>(question, Wh_f, bh_f, Wh_b, bh_b, bheff);

    const int MSZ = 3 * DD * DD;
    dim3 ggrid(TT / BM, DD / BN);  // (1024, 2)

    for (int l = 0; l < LL; ++l) {
        const int uq = (l == 0) ? 0 : 1;
        const float* bhf_eff = (l == 0) ? bheff : bh_f + l * DD;
        const float* bhb_eff = (l == 0) ? bheff + DD : bh_b + l * DD;

        gemm_mma<<<ggrid, 256, SMEM_TOTAL>>>(
            uh, ul, xh, xl, qh, ql, uq, 0,
            whi + l * MSZ, wlo + l * MSZ,
            bz_f + l * DD, bhf_eff, af, bf, aggAf, aggBf);
        scan2_kernel<<<1, 256>>>(aggAf, aggBf, hexf);

        if (l < LL - 1) {
            gemm_mma<<<ggrid, 256, SMEM_TOTAL>>>(
                uh, ul, xh, xl, qh, ql, uq, 1,
                whi + (3 + l) * MSZ, wlo + (3 + l) * MSZ,
                bz_b + l * DD, bhb_eff, ab, bb, aggAb, aggBb);
            scan2_kernel<<<1, 256>>>(aggAb, aggBb, hexb);

            combine_kernel<<<TT * DD / 4 / 256, 256>>>(
                af, bf, hexf, ab, bb, hexb, story, qh, ql, uh, ul);
        } else {
            final_kernel<<<1, 256>>>(af, bf, hexf, out);
        }
    }
}

// round 9
// speedup vs baseline: 1.2507x; 1.2507x over previous
#include <cuda_runtime.h>
#include <cuda_bf16.h>
#include <stdint.h>
#include <math.h>

// Problem constants
#define TT 65536
#define DD 256
#define LL 3

// GEMM tiling (R5 geometry: BM=128, BN=64, KC=32)
#define BM 128
#define BN 64
#define KC 32
#define NCHUNK (DD / KC)   // 8

#define ROWB 80                     // padded smem row stride (bytes)
#define A_TILE (128 * ROWB)         // 10240 B
#define B_TILE (64 * ROWB)          // 5120 B
#define BUFSZ  (6 * A_TILE + 6 * B_TILE)  // 92160 B
#define SM_BIAS (2 * BUFSZ)         // 184320
#define SMEM_TOTAL (SM_BIAS + 512 + 64)
#define SM_SEG (2 * 128 * 68 * 4)   // 69632 (epilogue seg aggregates)

// Scan blocking (block = gemm CTA M-tile)
#define CS 128
#define NB (TT / CS)  // 512

// ---------------------------------------------------------------------------
// Scratch
// ---------------------------------------------------------------------------
__device__ __align__(256) float g_q[TT * DD];     // fp32 next-layer question
__device__ __align__(256) float g_af[TT * DD];
__device__ __align__(256) float g_bf[TT * DD];
__device__ __align__(256) float g_ab[TT * DD];
__device__ __align__(256) float g_bb[TT * DD];
__device__ __align__(256) float g_aggA_f[NB * DD];
__device__ __align__(256) float g_aggB_f[NB * DD];
__device__ __align__(256) float g_hex_f[NB * DD];
__device__ __align__(256) float g_aggA_b[NB * DD];
__device__ __align__(256) float g_aggB_b[NB * DD];
__device__ __align__(256) float g_hex_b[NB * DD];
// pre-transposed hi/lo-split weights: [5 layer-dirs][3 mats][256 n][256 k]
__device__ __align__(256) __nv_bfloat16 g_whi[5 * 3 * DD * DD];
__device__ __align__(256) __nv_bfloat16 g_wlo[5 * 3 * DD * DD];
// layer-0 effective h-bias (bh + Whq^T q0): [2 dirs][256]
__device__ __align__(256) float g_bheff[2 * DD];

__device__ __forceinline__ float tanh_fast(float v) {
    float r;
    asm("tanh.approx.f32 %0, %1;" : "=f"(r) : "f"(v));
    return r;
}
__device__ __forceinline__ uint32_t smem_u32(const void* p) {
    uint32_t a;
    asm("{ .reg .u64 t; cvta.to.shared.u64 t, %1; cvt.u32.u64 %0, t; }"
        : "=r"(a) : "l"(p));
    return a;
}
__device__ __forceinline__ void ldsm4(uint32_t addr, uint32_t* r) {
    asm volatile("ldmatrix.sync.aligned.m8n8.x4.shared.b16 {%0,%1,%2,%3}, [%4];"
                 : "=r"(r[0]), "=r"(r[1]), "=r"(r[2]), "=r"(r[3]) : "r"(addr));
}
__device__ __forceinline__ void mma16816(float* c, const uint32_t* a,
                                         const uint32_t* b) {
    asm volatile(
        "mma.sync.aligned.m16n8k16.row.col.f32.bf16.bf16.f32 "
        "{%0,%1,%2,%3}, {%4,%5,%6,%7}, {%8,%9}, {%0,%1,%2,%3};"
        : "+f"(c[0]), "+f"(c[1]), "+f"(c[2]), "+f"(c[3])
        : "r"(a[0]), "r"(a[1]), "r"(a[2]), "r"(a[3]), "r"(b[0]), "r"(b[1]));
}

// hi/lo bf16 split of a float4; one 8B store each
__device__ __forceinline__ void split_store(float4 v, char* hi, char* lo) {
    __nv_bfloat16 h0 = __float2bfloat16_rn(v.x);
    __nv_bfloat16 h1 = __float2bfloat16_rn(v.y);
    __nv_bfloat16 h2 = __float2bfloat16_rn(v.z);
    __nv_bfloat16 h3 = __float2bfloat16_rn(v.w);
    __nv_bfloat162 H0; H0.x = h0; H0.y = h1;
    __nv_bfloat162 H1; H1.x = h2; H1.y = h3;
    __nv_bfloat162 L0, L1;
    L0.x = __float2bfloat16_rn(v.x - __bfloat162float(h0));
    L0.y = __float2bfloat16_rn(v.y - __bfloat162float(h1));
    L1.x = __float2bfloat16_rn(v.z - __bfloat162float(h2));
    L1.y = __float2bfloat16_rn(v.w - __bfloat162float(h3));
    uint2 H; H.x = *(uint32_t*)&H0; H.y = *(uint32_t*)&H1;
    uint2 L; L.x = *(uint32_t*)&L0; L.y = *(uint32_t*)&L1;
    *(uint2*)hi = H;
    *(uint2*)lo = L;
}

// ---------------------------------------------------------------------------
// prep_all: one launch. z-slots 0..4 = weight transpose+split (5 layer-dirs),
// z-slot 5 = layer-0 effective h-bias (bh + Whq^T q0) for both directions.
// grid (256, 3, 6), block 256.
// ---------------------------------------------------------------------------
__global__ void prep_all(const float* __restrict__ Wz_f, const float* __restrict__ Wh_f,
                         const float* __restrict__ Wz_b, const float* __restrict__ Wh_b,
                         const float* __restrict__ question,
                         const float* __restrict__ bh_f, const float* __restrict__ bh_b,
                         __nv_bfloat16* __restrict__ whi, __nv_bfloat16* __restrict__ wlo,
                         float* __restrict__ bheff)
{
    int n = blockIdx.x, m = blockIdx.y, s = blockIdx.z, k = threadIdx.x;
    if (s == 5) {
        if (m >= 2) return;
        __shared__ float red[256];
        const float* Wh = m ? Wh_b : Wh_f;
        const float* bh = m ? bh_b : bh_f;
        red[k] = question[k] * Wh[(DD + k) * DD + n];
        __syncthreads();
        for (int st = 128; st > 0; st >>= 1) {
            if (k < st) red[k] += red[k + st];
            __syncthreads();
        }
        if (k == 0) bheff[m * DD + n] = bh[n] + red[0];
        return;
    }
    const float* Wz;
    const float* Wh;
    if (s < 3) { Wz = Wz_f + s * DD * DD; Wh = Wh_f + s * 2 * DD * DD; }
    else       { Wz = Wz_b + (s - 3) * DD * DD; Wh = Wh_b + (s - 3) * 2 * DD * DD; }
    float v = (m == 0) ? Wz[k * DD + n]
            : (m == 1) ? Wh[k * DD + n]
                       : Wh[(DD + k) * DD + n];
    __nv_bfloat16 hi = __float2bfloat16_rn(v);
    __nv_bfloat16 lo = __float2bfloat16_rn(v - __bfloat162float(hi));
    size_t o = (size_t)(s * 3 + m) * DD * DD + (size_t)n * DD + k;
    whi[o] = hi;
    wlo[o] = lo;
}

// ---------------------------------------------------------------------------
// Fused GEMM (mma.sync bf16, 3-pass hi/lo, R5 staging) + activation +
// block-local scan. grid (DD/BN=4, TT/BM=512): N on x (L2 reuse of x/q).
// ---------------------------------------------------------------------------
__global__ void __launch_bounds__(256, 1) gemm_mma(
    const float* __restrict__ x, const float* __restrict__ qp, int qstride,
    int use_q, int rev,
    const __nv_bfloat16* __restrict__ whi, const __nv_bfloat16* __restrict__ wlo,
    const float* __restrict__ bz, const float* __restrict__ bh,
    float* __restrict__ outA, float* __restrict__ outB,
    float* __restrict__ aggA, float* __restrict__ aggB)
{
    extern __shared__ char smem[];
    const int tid = threadIdx.x;
    const int wid = tid >> 5;
    const int lane = tid & 31;
    const int wm = wid & 3;        // 4 M warp-tiles of 32 rows
    const int wn = wid >> 2;       // 2 N warp-tiles of 32 cols
    const int nbase = blockIdx.x * BN;      // N varies fastest -> L2 reuse
    const int tbase = blockIdx.y * BM;
    const int mblk  = blockIdx.y;           // scan block index
    const uint32_t sb = smem_u32(smem);

    float* bzs = (float*)(smem + SM_BIAS);
    float* bhs = bzs + 64;
    if (tid < 64) {
        bzs[tid] = bz[nbase + tid];
        bhs[tid] = bh[nbase + tid];
    }

    const __nv_bfloat16* w6[6] = {
        whi, wlo, whi + DD * DD, wlo + DD * DD, whi + 2 * DD * DD, wlo + 2 * DD * DD
    };
    const int np = use_q ? 6 : 4;

    float acc[2][2][4][4];
    #pragma unroll
    for (int zh = 0; zh < 2; ++zh)
        #pragma unroll
        for (int mt = 0; mt < 2; ++mt)
            #pragma unroll
            for (int nt = 0; nt < 4; ++nt)
                #pragma unroll
                for (int j = 0; j < 4; ++j) acc[zh][mt][nt][j] = 0.f;

    // --- R5 staging: gmem->regs prefetch, in-kernel split, double buffer ----
    float4 pxv[4], pqv[4];
    auto load_xq = [&](int k0) {
        #pragma unroll
        for (int it = 0; it < 4; ++it) {
            int j = tid + it * 256;
            int m = j >> 3, kq = j & 7;
            int tg = rev ? (TT - 1 - (tbase + m)) : (tbase + m);
            pxv[it] = *(const float4*)(x + (size_t)tg * DD + k0 + kq * 4);
            pqv[it] = *(const float4*)(qp + (size_t)tg * qstride + k0 + kq * 4);
        }
    };
    auto stage_A = [&](int buf) {
        char* base = smem + buf * BUFSZ;
        #pragma unroll
        for (int it = 0; it < 4; ++it) {
            int j = tid + it * 256;
            int m = j >> 3, kq = j & 7;
            int off = m * ROWB + kq * 8;
            float4 xv = pxv[it], qv = pqv[it];
            float4 uv = make_float4(xv.x * qv.x, xv.y * qv.y, xv.z * qv.z, xv.w * qv.w);
            split_store(uv, base + 0 * A_TILE + off, base + 1 * A_TILE + off);
            split_store(xv, base + 2 * A_TILE + off, base + 3 * A_TILE + off);
            if (use_q)
                split_store(qv, base + 4 * A_TILE + off, base + 5 * A_TILE + off);
        }
    };
    auto stage_W = [&](int k0, int buf) {
        char* base = smem + buf * BUFSZ + 6 * A_TILE;
        int n = tid >> 2, s = tid & 3;
        #pragma unroll
        for (int m6 = 0; m6 < 6; ++m6)
            if (m6 < np) {
                uint4 v = *(const uint4*)(w6[m6] + (size_t)(nbase + n) * DD + k0 + s * 8);
                *(uint4*)(base + m6 * B_TILE + n * ROWB + s * 16) = v;
            }
    };

    load_xq(0);
    stage_A(0);
    stage_W(0, 0);
    __syncthreads();

    const int r = lane & 7, g = lane >> 3;
    #pragma unroll 1
    for (int c = 0; c < NCHUNK; ++c) {
        if (c < NCHUNK - 1) load_xq((c + 1) * KC);   // gmem prefetch to regs

        const uint32_t abuf = sb + (c & 1) * BUFSZ;
        const uint32_t bbuf = abuf + 6 * A_TILE;

        #pragma unroll
        for (int ks = 0; ks < 2; ++ks) {
            const uint32_t kso = ks * 32;
            uint32_t af[6][2][4];
            #pragma unroll
            for (int o = 0; o < 6; ++o)
                if (o < np) {
                    #pragma unroll
                    for (int mt = 0; mt < 2; ++mt) {
                        uint32_t addr = abuf + o * A_TILE
                            + (wm * 32 + mt * 16 + (g & 1) * 8 + r) * ROWB
                            + (g >> 1) * 16 + kso;
                        ldsm4(addr, af[o][mt]);
                    }
                }
            uint32_t bf[6][4][2];
            #pragma unroll
            for (int m6 = 0; m6 < 6; ++m6)
                if (m6 < np) {
                    #pragma unroll
                    for (int j = 0; j < 2; ++j) {
                        uint32_t tmp[4];
                        uint32_t addr = bbuf + m6 * B_TILE
                            + (wn * 32 + (2 * j + (g >> 1)) * 8 + r) * ROWB
                            + (g & 1) * 16 + kso;
                        ldsm4(addr, tmp);
                        bf[m6][2 * j][0] = tmp[0]; bf[m6][2 * j][1] = tmp[1];
                        bf[m6][2 * j + 1][0] = tmp[2]; bf[m6][2 * j + 1][1] = tmp[3];
                    }
                }
            #pragma unroll
            for (int mt = 0; mt < 2; ++mt)
                #pragma unroll
                for (int nt = 0; nt < 4; ++nt) {
                    mma16816(acc[0][mt][nt], af[0][mt], bf[0][nt]);
                    mma16816(acc[0][mt][nt], af[0][mt], bf[1][nt]);
                    mma16816(acc[0][mt][nt], af[1][mt], bf[0][nt]);
                    mma16816(acc[1][mt][nt], af[2][mt], bf[2][nt]);
                    mma16816(acc[1][mt][nt], af[2][mt], bf[3][nt]);
                    mma16816(acc[1][mt][nt], af[3][mt], bf[2][nt]);
                    if (use_q) {
                        mma16816(acc[1][mt][nt], af[4][mt], bf[4][nt]);
                        mma16816(acc[1][mt][nt], af[4][mt], bf[5][nt]);
                        mma16816(acc[1][mt][nt], af[5][mt], bf[4][nt]);
                    }
                }
        }
        __syncthreads();
        if (c < NCHUNK - 1) {
            stage_A((c + 1) & 1);
            stage_W((c + 1) * KC, (c + 1) & 1);
            __syncthreads();
        }
    }

    // --- epilogue: activations -> smem transpose ---------------------------
    float* smA = (float*)smem;              // [128][68]
    float* smB = smA + 128 * 68;
    #pragma unroll
    for (int mt = 0; mt < 2; ++mt)
        #pragma unroll
        for (int nt = 0; nt < 4; ++nt) {
            int col = wn * 32 + nt * 8 + 2 * (lane & 3);
            int row0 = wm * 32 + mt * 16 + (lane >> 2);
            #pragma unroll
            for (int h8 = 0; h8 < 2; ++h8) {
                int row = row0 + h8 * 8;
                float z0 = 0.5f * tanh_fast(0.5f * (acc[0][mt][nt][2*h8+0] + bzs[col]))   + 0.5f;
                float z1 = 0.5f * tanh_fast(0.5f * (acc[0][mt][nt][2*h8+1] + bzs[col+1])) + 0.5f;
                float t0 = tanh_fast(acc[1][mt][nt][2*h8+0] + bhs[col]);
                float t1 = tanh_fast(acc[1][mt][nt][2*h8+1] + bhs[col+1]);
                *(float2*)(smA + row * 68 + col) = make_float2(1.f - z0, 1.f - z1);
                *(float2*)(smB + row * 68 + col) = make_float2(z0 * t0, z1 * t1);
            }
        }
    __syncthreads();

    // --- fused block-local scan over 128 rows (4 segments x 32) ------------
    float* segA = (float*)(smem + SM_SEG);        // [4][64]
    float* segB = segA + 4 * 64;
    {
        const int col = tid & 63;
        const int sg = tid >> 6;                   // 0..3
        const int rbase = sg * 32;
        float Ap = 1.f, hl = 0.f;
        #pragma unroll 8
        for (int i = 0; i < 32; ++i) {
            int off = (rbase + i) * 68 + col;
            float a = smA[off], b = smB[off];
            Ap *= a;
            hl = fmaf(a, hl, b);
            smA[off] = Ap;
            smB[off] = hl;
        }
        segA[sg * 64 + col] = Ap;
        segB[sg * 64 + col] = hl;
        __syncthreads();
        float Ain = 1.f, Hin = 0.f;
        #pragma unroll
        for (int s = 0; s < 3; ++s)
            if (s < sg) {
                float sa = segA[s * 64 + col], sbv = segB[s * 64 + col];
                Ain *= sa;
                Hin = fmaf(sa, Hin, sbv);
            }
        #pragma unroll 8
        for (int i = 0; i < 32; ++i) {
            int off = (rbase + i) * 68 + col;
            float Al = smA[off], Bl = smB[off];
            smA[off] = Ain * Al;
            smB[off] = fmaf(Al, Hin, Bl);
        }
        if (sg == 3) {
            aggA[(size_t)mblk * DD + nbase + col] = Ain * Ap;
            aggB[(size_t)mblk * DD + nbase + col] = fmaf(Ap, Hin, hl);
        }
    }
    __syncthreads();

    // --- coalesced global stores -------------------------------------------
    #pragma unroll
    for (int it = 0; it < 8; ++it) {
        int j = tid + it * 256;
        int row = j >> 4, cf = j & 15;
        size_t go = (size_t)(tbase + row) * DD + nbase + cf * 4;
        *(float4*)(outA + go) = *(const float4*)(smA + row * 68 + cf * 4);
        *(float4*)(outB + go) = *(const float4*)(smB + row * 68 + cf * 4);
    }
}

// ---------------------------------------------------------------------------
// scan2: exclusive scan over NB aggregates, batched prefetch (MLP=16).
// grid.x selects forward (0) / backward (1).
// ---------------------------------------------------------------------------
__global__ void scan2_kernel(const float* __restrict__ aggAf, const float* __restrict__ aggBf,
                             float* __restrict__ hexf,
                             const float* __restrict__ aggAb, const float* __restrict__ aggBb,
                             float* __restrict__ hexb)
{
    const float* aggA = blockIdx.x ? aggAb : aggAf;
    const float* aggB = blockIdx.x ? aggBb : aggBf;
    float* hex = blockIdx.x ? hexb : hexf;
    const int d = threadIdx.x;
    float H = 0.f;
    for (int b0 = 0; b0 < NB; b0 += 16) {
        float a[16], bb[16];
        #pragma unroll
        for (int i = 0; i < 16; ++i) {
            a[i]  = aggA[(size_t)(b0 + i) * DD + d];
            bb[i] = aggB[(size_t)(b0 + i) * DD + d];
        }
        #pragma unroll
        for (int i = 0; i < 16; ++i) {
            hex[(size_t)(b0 + i) * DD + d] = H;
            H = fmaf(a[i], H, bb[i]);
        }
    }
}

// ---------------------------------------------------------------------------
// combine: q = h_fwd + h_bwd_rev (cross-block fixup on the fly) -> fp32 qout.
// ---------------------------------------------------------------------------
__global__ void combine_kernel(
    const float* __restrict__ Af, const float* __restrict__ Bf,
    const float* __restrict__ hexf,
    const float* __restrict__ Ab, const float* __restrict__ Bb,
    const float* __restrict__ hexb,
    float* __restrict__ qout)
{
    int idx = blockIdx.x * blockDim.x + threadIdx.x;   // float4 index
    int t = idx >> 6;
    int c = (idx & 63) << 2;
    int tr = TT - 1 - t;
    int blf = t >> 7;        // CS = 128
    int blb = tr >> 7;

    float4 af = *(const float4*)(Af + (size_t)t * DD + c);
    float4 bfv = *(const float4*)(Bf + (size_t)t * DD + c);
    float4 hf = *(const float4*)(hexf + (size_t)blf * DD + c);
    float4 ab = *(const float4*)(Ab + (size_t)tr * DD + c);
    float4 bb = *(const float4*)(Bb + (size_t)tr * DD + c);
    float4 hb = *(const float4*)(hexb + (size_t)blb * DD + c);

    float4 q4;
    q4.x = fmaf(af.x, hf.x, bfv.x) + fmaf(ab.x, hb.x, bb.x);
    q4.y = fmaf(af.y, hf.y, bfv.y) + fmaf(ab.y, hb.y, bb.y);
    q4.z = fmaf(af.z, hf.z, bfv.z) + fmaf(ab.z, hb.z, bb.z);
    q4.w = fmaf(af.w, hf.w, bfv.w) + fmaf(ab.w, hb.w, bb.w);

    *(float4*)(qout + (size_t)t * DD + c) = q4;
}

__global__ void final_kernel(const float* __restrict__ Af,
                             const float* __restrict__ Bf,
                             const float* __restrict__ hexf,
                             float* __restrict__ out)
{
    const int d = threadIdx.x;
    out[d] = fmaf(Af[(size_t)(TT - 1) * DD + d], hexf[(size_t)(NB - 1) * DD + d],
                  Bf[(size_t)(TT - 1) * DD + d]);
}

// ---------------------------------------------------------------------------
// Host orchestration
// ---------------------------------------------------------------------------
extern "C" void kernel_launch(void* const* d_in, const int* in_sizes, int n_in,
                              void* d_out, int out_size)
{
    const float* story    = (const float*)d_in[0];
    const float* question = (const float*)d_in[1];
    const float* Wz_f = (const float*)d_in[2];
    const float* bz_f = (const float*)d_in[3];
    const float* Wh_f = (const float*)d_in[4];
    const float* bh_f = (const float*)d_in[5];
    const float* Wz_b = (const float*)d_in[6];
    const float* bz_b = (const float*)d_in[7];
    const float* Wh_b = (const float*)d_in[8];
    const float* bh_b = (const float*)d_in[9];
    float* out = (float*)d_out;

    float *qbuf, *af, *bf, *ab, *bb;
    float *aggAf, *aggBf, *hexf, *aggAb, *aggBb, *hexb, *bheff;
    __nv_bfloat16 *whi, *wlo;
    cudaGetSymbolAddress((void**)&qbuf,  g_q);
    cudaGetSymbolAddress((void**)&af,    g_af);
    cudaGetSymbolAddress((void**)&bf,    g_bf);
    cudaGetSymbolAddress((void**)&ab,    g_ab);
    cudaGetSymbolAddress((void**)&bb,    g_bb);
    cudaGetSymbolAddress((void**)&aggAf, g_aggA_f);
    cudaGetSymbolAddress((void**)&aggBf, g_aggB_f);
    cudaGetSymbolAddress((void**)&hexf,  g_hex_f);
    cudaGetSymbolAddress((void**)&aggAb, g_aggA_b);
    cudaGetSymbolAddress((void**)&aggBb, g_aggB_b);
    cudaGetSymbolAddress((void**)&hexb,  g_hex_b);
    cudaGetSymbolAddress((void**)&whi,   g_whi);
    cudaGetSymbolAddress((void**)&wlo,   g_wlo);
    cudaGetSymbolAddress((void**)&bheff, g_bheff);

    static int smem_set = 0;
    if (!smem_set) {
        cudaFuncSetAttribute(gemm_mma, cudaFuncAttributeMaxDynamicSharedMemorySize,
                             SMEM_TOTAL);
        smem_set = 1;
    }

    // Launch 0: all prep (weights + layer-0 bias fold) in one launch.
    prep_all<<<dim3(DD, 3, 6), 256>>>(Wz_f, Wh_f, Wz_b, Wh_b,
                                      question, bh_f, bh_b, whi, wlo, bheff);

    const int MSZ = 3 * DD * DD;
    dim3 ggrid(DD / BN, TT / BM);   // (4, 512): N fastest -> x/q L2 reuse

    for (int l = 0; l < LL; ++l) {
        const int uq = (l == 0) ? 0 : 1;
        const float* qp = (l == 0) ? question : qbuf;
        const int qstride = (l == 0) ? 0 : DD;
        const float* bhf_eff = (l == 0) ? bheff : bh_f + l * DD;
        const float* bhb_eff = (l == 0) ? bheff + DD : bh_b + l * DD;

        gemm_mma<<<ggrid, 256, SMEM_TOTAL>>>(
            story, qp, qstride, uq, 0,
            whi + l * MSZ, wlo + l * MSZ,
            bz_f + l * DD, bhf_eff, af, bf, aggAf, aggBf);

        if (l < LL - 1) {
            gemm_mma<<<ggrid, 256, SMEM_TOTAL>>>(
                story, qp, qstride, uq, 1,
                whi + (3 + l) * MSZ, wlo + (3 + l) * MSZ,
                bz_b + l * DD, bhb_eff, ab, bb, aggAb, aggBb);

            scan2_kernel<<<2, 256>>>(aggAf, aggBf, hexf, aggAb, aggBb, hexb);

            combine_kernel<<<TT * DD / 4 / 256, 256>>>(
                af, bf, hexf, ab, bb, hexb, qbuf);
        } else {
            scan2_kernel<<<1, 256>>>(aggAf, aggBf, hexf, aggAb, aggBb, hexb);
            final_kernel<<<1, 256>>>(af, bf, hexf, out);
        }
    }
}

// round 10
// speedup vs baseline: 1.3587x; 1.0864x over previous
#include <cuda_runtime.h>
#include <cuda_bf16.h>
#include <stdint.h>
#include <math.h>

// Problem constants
#define TT 65536
#define DD 256
#define LL 3

// GEMM tiling (R5 geometry: BM=128, BN=64, KC=32)
#define BM 128
#define BN 64
#define KC 32
#define NCHUNK (DD / KC)   // 8

#define ROWB 80                     // padded smem row stride (bytes)
#define A_TILE (128 * ROWB)         // 10240 B
#define B_TILE (64 * ROWB)          // 5120 B
#define BUFSZ  (6 * A_TILE + 6 * B_TILE)  // 92160 B
#define SM_BIAS (2 * BUFSZ)         // 184320
#define SMEM_TOTAL (SM_BIAS + 512 + 64)
#define SM_SEG (2 * 128 * 68 * 4)   // 69632 (epilogue seg aggregates)

// Scan blocking
#define CS 128
#define NB (TT / CS)   // 512
#define SBLK 16        // blocks per super-block
#define NSUP (NB / SBLK)  // 32

// ---------------------------------------------------------------------------
// Scratch
// ---------------------------------------------------------------------------
__device__ __align__(256) float g_q[TT * DD];
__device__ __align__(256) float g_af[TT * DD];
__device__ __align__(256) float g_bf[TT * DD];
__device__ __align__(256) float g_ab[TT * DD];
__device__ __align__(256) float g_bb[TT * DD];
__device__ __align__(256) float g_aggA_f[NB * DD];
__device__ __align__(256) float g_aggB_f[NB * DD];
__device__ __align__(256) float g_hex_f[NB * DD];
__device__ __align__(256) float g_apre_f[NB * DD];
__device__ __align__(256) float g_aggA_b[NB * DD];
__device__ __align__(256) float g_aggB_b[NB * DD];
__device__ __align__(256) float g_hex_b[NB * DD];
__device__ __align__(256) float g_apre_b[NB * DD];
__device__ __align__(256) float g_supA_f[NSUP * DD];
__device__ __align__(256) float g_supB_f[NSUP * DD];
__device__ __align__(256) float g_hsup_f[NSUP * DD];
__device__ __align__(256) float g_supA_b[NSUP * DD];
__device__ __align__(256) float g_supB_b[NSUP * DD];
__device__ __align__(256) float g_hsup_b[NSUP * DD];
// pre-transposed hi/lo-split weights: [5 layer-dirs][3 mats][256 n][256 k]
__device__ __align__(256) __nv_bfloat16 g_whi[5 * 3 * DD * DD];
__device__ __align__(256) __nv_bfloat16 g_wlo[5 * 3 * DD * DD];
// layer-0 effective h-bias (bh + Whq^T q0): [2 dirs][256]
__device__ __align__(256) float g_bheff[2 * DD];

__device__ __forceinline__ float tanh_fast(float v) {
    float r;
    asm("tanh.approx.f32 %0, %1;" : "=f"(r) : "f"(v));
    return r;
}
__device__ __forceinline__ uint32_t smem_u32(const void* p) {
    uint32_t a;
    asm("{ .reg .u64 t; cvta.to.shared.u64 t, %1; cvt.u32.u64 %0, t; }"
        : "=r"(a) : "l"(p));
    return a;
}
__device__ __forceinline__ void ldsm4(uint32_t addr, uint32_t* r) {
    asm volatile("ldmatrix.sync.aligned.m8n8.x4.shared.b16 {%0,%1,%2,%3}, [%4];"
                 : "=r"(r[0]), "=r"(r[1]), "=r"(r[2]), "=r"(r[3]) : "r"(addr));
}
__device__ __forceinline__ void mma16816(float* c, const uint32_t* a,
                                         const uint32_t* b) {
    asm volatile(
        "mma.sync.aligned.m16n8k16.row.col.f32.bf16.bf16.f32 "
        "{%0,%1,%2,%3}, {%4,%5,%6,%7}, {%8,%9}, {%0,%1,%2,%3};"
        : "+f"(c[0]), "+f"(c[1]), "+f"(c[2]), "+f"(c[3])
        : "r"(a[0]), "r"(a[1]), "r"(a[2]), "r"(a[3]), "r"(b[0]), "r"(b[1]));
}

// hi/lo bf16 split of a float4; one 8B store each
__device__ __forceinline__ void split_store(float4 v, char* hi, char* lo) {
    __nv_bfloat16 h0 = __float2bfloat16_rn(v.x);
    __nv_bfloat16 h1 = __float2bfloat16_rn(v.y);
    __nv_bfloat16 h2 = __float2bfloat16_rn(v.z);
    __nv_bfloat16 h3 = __float2bfloat16_rn(v.w);
    __nv_bfloat162 H0; H0.x = h0; H0.y = h1;
    __nv_bfloat162 H1; H1.x = h2; H1.y = h3;
    __nv_bfloat162 L0, L1;
    L0.x = __float2bfloat16_rn(v.x - __bfloat162float(h0));
    L0.y = __float2bfloat16_rn(v.y - __bfloat162float(h1));
    L1.x = __float2bfloat16_rn(v.z - __bfloat162float(h2));
    L1.y = __float2bfloat16_rn(v.w - __bfloat162float(h3));
    uint2 H; H.x = *(uint32_t*)&H0; H.y = *(uint32_t*)&H1;
    uint2 L; L.x = *(uint32_t*)&L0; L.y = *(uint32_t*)&L1;
    *(uint2*)hi = H;
    *(uint2*)lo = L;
}

// ---------------------------------------------------------------------------
// prep_all: z-slots 0..4 = weight transpose+split; z-slot 5 = layer-0 bias fold
// ---------------------------------------------------------------------------
__global__ void prep_all(const float* __restrict__ Wz_f, const float* __restrict__ Wh_f,
                         const float* __restrict__ Wz_b, const float* __restrict__ Wh_b,
                         const float* __restrict__ question,
                         const float* __restrict__ bh_f, const float* __restrict__ bh_b,
                         __nv_bfloat16* __restrict__ whi, __nv_bfloat16* __restrict__ wlo,
                         float* __restrict__ bheff)
{
    int n = blockIdx.x, m = blockIdx.y, s = blockIdx.z, k = threadIdx.x;
    if (s == 5) {
        if (m >= 2) return;
        __shared__ float red[256];
        const float* Wh = m ? Wh_b : Wh_f;
        const float* bh = m ? bh_b : bh_f;
        red[k] = question[k] * Wh[(DD + k) * DD + n];
        __syncthreads();
        for (int st = 128; st > 0; st >>= 1) {
            if (k < st) red[k] += red[k + st];
            __syncthreads();
        }
        if (k == 0) bheff[m * DD + n] = bh[n] + red[0];
        return;
    }
    const float* Wz;
    const float* Wh;
    if (s < 3) { Wz = Wz_f + s * DD * DD; Wh = Wh_f + s * 2 * DD * DD; }
    else       { Wz = Wz_b + (s - 3) * DD * DD; Wh = Wh_b + (s - 3) * 2 * DD * DD; }
    float v = (m == 0) ? Wz[k * DD + n]
            : (m == 1) ? Wh[k * DD + n]
                       : Wh[(DD + k) * DD + n];
    __nv_bfloat16 hi = __float2bfloat16_rn(v);
    __nv_bfloat16 lo = __float2bfloat16_rn(v - __bfloat162float(hi));
    size_t o = (size_t)(s * 3 + m) * DD * DD + (size_t)n * DD + k;
    whi[o] = hi;
    wlo[o] = lo;
}

// ---------------------------------------------------------------------------
// Fused GEMM (mma.sync bf16, 3-pass hi/lo) + activation + block-local scan.
// do_store=0: only block aggregates are produced (last layer).
// ---------------------------------------------------------------------------
__global__ void __launch_bounds__(256, 1) gemm_mma(
    const float* __restrict__ x, const float* __restrict__ qp, int qstride,
    int use_q, int rev, int do_store,
    const __nv_bfloat16* __restrict__ whi, const __nv_bfloat16* __restrict__ wlo,
    const float* __restrict__ bz, const float* __restrict__ bh,
    float* __restrict__ outA, float* __restrict__ outB,
    float* __restrict__ aggA, float* __restrict__ aggB)
{
    extern __shared__ char smem[];
    const int tid = threadIdx.x;
    const int wid = tid >> 5;
    const int lane = tid & 31;
    const int wm = wid & 3;
    const int wn = wid >> 2;
    const int nbase = blockIdx.x * BN;      // N fastest -> x/q L2 reuse
    const int tbase = blockIdx.y * BM;
    const int mblk  = blockIdx.y;
    const uint32_t sb = smem_u32(smem);

    float* bzs = (float*)(smem + SM_BIAS);
    float* bhs = bzs + 64;
    if (tid < 64) {
        bzs[tid] = bz[nbase + tid];
        bhs[tid] = bh[nbase + tid];
    }

    const __nv_bfloat16* w6[6] = {
        whi, wlo, whi + DD * DD, wlo + DD * DD, whi + 2 * DD * DD, wlo + 2 * DD * DD
    };
    const int np = use_q ? 6 : 4;

    float acc[2][2][4][4];
    #pragma unroll
    for (int zh = 0; zh < 2; ++zh)
        #pragma unroll
        for (int mt = 0; mt < 2; ++mt)
            #pragma unroll
            for (int nt = 0; nt < 4; ++nt)
                #pragma unroll
                for (int j = 0; j < 4; ++j) acc[zh][mt][nt][j] = 0.f;

    float4 pxv[4], pqv[4];
    auto load_xq = [&](int k0) {
        #pragma unroll
        for (int it = 0; it < 4; ++it) {
            int j = tid + it * 256;
            int m = j >> 3, kq = j & 7;
            int tg = rev ? (TT - 1 - (tbase + m)) : (tbase + m);
            pxv[it] = *(const float4*)(x + (size_t)tg * DD + k0 + kq * 4);
            pqv[it] = *(const float4*)(qp + (size_t)tg * qstride + k0 + kq * 4);
        }
    };
    auto stage_A = [&](int buf) {
        char* base = smem + buf * BUFSZ;
        #pragma unroll
        for (int it = 0; it < 4; ++it) {
            int j = tid + it * 256;
            int m = j >> 3, kq = j & 7;
            int off = m * ROWB + kq * 8;
            float4 xv = pxv[it], qv = pqv[it];
            float4 uv = make_float4(xv.x * qv.x, xv.y * qv.y, xv.z * qv.z, xv.w * qv.w);
            split_store(uv, base + 0 * A_TILE + off, base + 1 * A_TILE + off);
            split_store(xv, base + 2 * A_TILE + off, base + 3 * A_TILE + off);
            if (use_q)
                split_store(qv, base + 4 * A_TILE + off, base + 5 * A_TILE + off);
        }
    };
    auto stage_W = [&](int k0, int buf) {
        char* base = smem + buf * BUFSZ + 6 * A_TILE;
        int n = tid >> 2, s = tid & 3;
        #pragma unroll
        for (int m6 = 0; m6 < 6; ++m6)
            if (m6 < np) {
                uint4 v = *(const uint4*)(w6[m6] + (size_t)(nbase + n) * DD + k0 + s * 8);
                *(uint4*)(base + m6 * B_TILE + n * ROWB + s * 16) = v;
            }
    };

    load_xq(0);
    stage_A(0);
    stage_W(0, 0);
    __syncthreads();

    const int r = lane & 7, g = lane >> 3;
    #pragma unroll 1
    for (int c = 0; c < NCHUNK; ++c) {
        if (c < NCHUNK - 1) load_xq((c + 1) * KC);

        const uint32_t abuf = sb + (c & 1) * BUFSZ;
        const uint32_t bbuf = abuf + 6 * A_TILE;

        #pragma unroll
        for (int ks = 0; ks < 2; ++ks) {
            const uint32_t kso = ks * 32;
            uint32_t af[6][2][4];
            #pragma unroll
            for (int o = 0; o < 6; ++o)
                if (o < np) {
                    #pragma unroll
                    for (int mt = 0; mt < 2; ++mt) {
                        uint32_t addr = abuf + o * A_TILE
                            + (wm * 32 + mt * 16 + (g & 1) * 8 + r) * ROWB
                            + (g >> 1) * 16 + kso;
                        ldsm4(addr, af[o][mt]);
                    }
                }
            uint32_t bf[6][4][2];
            #pragma unroll
            for (int m6 = 0; m6 < 6; ++m6)
                if (m6 < np) {
                    #pragma unroll
                    for (int j = 0; j < 2; ++j) {
                        uint32_t tmp[4];
                        uint32_t addr = bbuf + m6 * B_TILE
                            + (wn * 32 + (2 * j + (g >> 1)) * 8 + r) * ROWB
                            + (g & 1) * 16 + kso;
                        ldsm4(addr, tmp);
                        bf[m6][2 * j][0] = tmp[0]; bf[m6][2 * j][1] = tmp[1];
                        bf[m6][2 * j + 1][0] = tmp[2]; bf[m6][2 * j + 1][1] = tmp[3];
                    }
                }
            #pragma unroll
            for (int mt = 0; mt < 2; ++mt)
                #pragma unroll
                for (int nt = 0; nt < 4; ++nt) {
                    mma16816(acc[0][mt][nt], af[0][mt], bf[0][nt]);
                    mma16816(acc[0][mt][nt], af[0][mt], bf[1][nt]);
                    mma16816(acc[0][mt][nt], af[1][mt], bf[0][nt]);
                    mma16816(acc[1][mt][nt], af[2][mt], bf[2][nt]);
                    mma16816(acc[1][mt][nt], af[2][mt], bf[3][nt]);
                    mma16816(acc[1][mt][nt], af[3][mt], bf[2][nt]);
                    if (use_q) {
                        mma16816(acc[1][mt][nt], af[4][mt], bf[4][nt]);
                        mma16816(acc[1][mt][nt], af[4][mt], bf[5][nt]);
                        mma16816(acc[1][mt][nt], af[5][mt], bf[4][nt]);
                    }
                }
        }
        __syncthreads();
        if (c < NCHUNK - 1) {
            stage_A((c + 1) & 1);
            stage_W((c + 1) * KC, (c + 1) & 1);
            __syncthreads();
        }
    }

    // --- epilogue: activations -> smem transpose ---------------------------
    float* smA = (float*)smem;              // [128][68]
    float* smB = smA + 128 * 68;
    #pragma unroll
    for (int mt = 0; mt < 2; ++mt)
        #pragma unroll
        for (int nt = 0; nt < 4; ++nt) {
            int col = wn * 32 + nt * 8 + 2 * (lane & 3);
            int row0 = wm * 32 + mt * 16 + (lane >> 2);
            #pragma unroll
            for (int h8 = 0; h8 < 2; ++h8) {
                int row = row0 + h8 * 8;
                float z0 = 0.5f * tanh_fast(0.5f * (acc[0][mt][nt][2*h8+0] + bzs[col]))   + 0.5f;
                float z1 = 0.5f * tanh_fast(0.5f * (acc[0][mt][nt][2*h8+1] + bzs[col+1])) + 0.5f;
                float t0 = tanh_fast(acc[1][mt][nt][2*h8+0] + bhs[col]);
                float t1 = tanh_fast(acc[1][mt][nt][2*h8+1] + bhs[col+1]);
                *(float2*)(smA + row * 68 + col) = make_float2(1.f - z0, 1.f - z1);
                *(float2*)(smB + row * 68 + col) = make_float2(z0 * t0, z1 * t1);
            }
        }
    __syncthreads();

    // --- fused block-local scan over 128 rows (4 segments x 32) ------------
    float* segA = (float*)(smem + SM_SEG);        // [4][64]
    float* segB = segA + 4 * 64;
    {
        const int col = tid & 63;
        const int sg = tid >> 6;                   // 0..3
        const int rbase = sg * 32;
        float Ap = 1.f, hl = 0.f;
        #pragma unroll 8
        for (int i = 0; i < 32; ++i) {
            int off = (rbase + i) * 68 + col;
            float a = smA[off], b = smB[off];
            Ap *= a;
            hl = fmaf(a, hl, b);
            if (do_store) { smA[off] = Ap; smB[off] = hl; }
        }
        segA[sg * 64 + col] = Ap;
        segB[sg * 64 + col] = hl;
        __syncthreads();
        float Ain = 1.f, Hin = 0.f;
        #pragma unroll
        for (int s = 0; s < 3; ++s)
            if (s < sg) {
                float sa = segA[s * 64 + col], sbv = segB[s * 64 + col];
                Ain *= sa;
                Hin = fmaf(sa, Hin, sbv);
            }
        if (do_store) {
            #pragma unroll 8
            for (int i = 0; i < 32; ++i) {
                int off = (rbase + i) * 68 + col;
                float Al = smA[off], Bl = smB[off];
                smA[off] = Ain * Al;
                smB[off] = fmaf(Al, Hin, Bl);
            }
        }
        if (sg == 3) {
            aggA[(size_t)mblk * DD + nbase + col] = Ain * Ap;
            aggB[(size_t)mblk * DD + nbase + col] = fmaf(Ap, Hin, hl);
        }
    }

    if (do_store) {
        __syncthreads();
        #pragma unroll
        for (int it = 0; it < 8; ++it) {
            int j = tid + it * 256;
            int row = j >> 4, cf = j & 15;
            size_t go = (size_t)(tbase + row) * DD + nbase + cf * 4;
            *(float4*)(outA + go) = *(const float4*)(smA + row * 68 + cf * 4);
            *(float4*)(outB + go) = *(const float4*)(smB + row * 68 + cf * 4);
        }
    }
}

// ---------------------------------------------------------------------------
// scan2a: per super-block (16 blocks) local scan. grid (NSUP, ndirs).
// hexL[b] = local state entering b (0-based), APre[b] = local prefix product,
// sup[s] = super-block aggregate.
// ---------------------------------------------------------------------------
__global__ void scan2a_kernel(
    const float* __restrict__ aggAf, const float* __restrict__ aggBf,
    float* __restrict__ hexf, float* __restrict__ apref,
    float* __restrict__ supAf, float* __restrict__ supBf,
    const float* __restrict__ aggAb, const float* __restrict__ aggBb,
    float* __restrict__ hexb, float* __restrict__ apreb,
    float* __restrict__ supAb, float* __restrict__ supBb)
{
    const int dirb = blockIdx.y;
    const float* aggA = dirb ? aggAb : aggAf;
    const float* aggB = dirb ? aggBb : aggBf;
    float* hex  = dirb ? hexb : hexf;
    float* apre = dirb ? apreb : apref;
    float* supA = dirb ? supAb : supAf;
    float* supB = dirb ? supBb : supBf;

    const int s = blockIdx.x, d = threadIdx.x;
    float a[SBLK], b[SBLK];
    #pragma unroll
    for (int i = 0; i < SBLK; ++i) {
        size_t o = (size_t)(s * SBLK + i) * DD + d;
        a[i] = aggA[o];
        b[i] = aggB[o];
    }
    float H = 0.f, A = 1.f;
    #pragma unroll
    for (int i = 0; i < SBLK; ++i) {
        size_t o = (size_t)(s * SBLK + i) * DD + d;
        hex[o] = H;
        apre[o] = A;
        H = fmaf(a[i], H, b[i]);
        A *= a[i];
    }
    supA[(size_t)s * DD + d] = A;
    supB[(size_t)s * DD + d] = H;
}

// ---------------------------------------------------------------------------
// scan2b: scan over NSUP super-aggregates. grid(ndirs).
// Hsup[s] = state entering super-block s. If out != null (last layer, fwd
// only), writes the terminal state (= h[T-1]) to out.
// ---------------------------------------------------------------------------
__global__ void scan2b_kernel(
    const float* __restrict__ supAf, const float* __restrict__ supBf,
    float* __restrict__ hsupf,
    const float* __restrict__ supAb, const float* __restrict__ supBb,
    float* __restrict__ hsupb,
    float* __restrict__ out)
{
    const int dirb = blockIdx.x;
    const float* supA = dirb ? supAb : supAf;
    const float* supB = dirb ? supBb : supBf;
    float* hsup = dirb ? hsupb : hsupf;
    const int d = threadIdx.x;

    float a[NSUP / 2], b[NSUP / 2];
    float H = 0.f;
    #pragma unroll
    for (int half = 0; half < 2; ++half) {
        #pragma unroll
        for (int i = 0; i < NSUP / 2; ++i) {
            size_t o = (size_t)(half * (NSUP / 2) + i) * DD + d;
            a[i] = supA[o];
            b[i] = supB[o];
        }
        #pragma unroll
        for (int i = 0; i < NSUP / 2; ++i) {
            hsup[(size_t)(half * (NSUP / 2) + i) * DD + d] = H;
            H = fmaf(a[i], H, b[i]);
        }
    }
    if (out && dirb == 0) out[d] = H;
}

// ---------------------------------------------------------------------------
// scan2c: hex[b] = APre[b] * Hsup[b/16] + hexL[b]  (in place). grid(128, 2).
// ---------------------------------------------------------------------------
__global__ void scan2c_kernel(
    float* __restrict__ hexf, const float* __restrict__ apref,
    const float* __restrict__ hsupf,
    float* __restrict__ hexb, const float* __restrict__ apreb,
    const float* __restrict__ hsupb)
{
    const int dirb = blockIdx.y;
    float* hex = dirb ? hexb : hexf;
    const float* apre = dirb ? apreb : apref;
    const float* hsup = dirb ? hsupb : hsupf;

    int idx = blockIdx.x * 256 + threadIdx.x;   // float4 index
    int bblk = idx >> 6;
    int c = (idx & 63) << 2;
    int sup = bblk >> 4;

    float4 ap = *(const float4*)(apre + (size_t)bblk * DD + c);
    float4 hs = *(const float4*)(hsup + (size_t)sup * DD + c);
    float4 hx = *(const float4*)(hex + (size_t)bblk * DD + c);
    hx.x = fmaf(ap.x, hs.x, hx.x);
    hx.y = fmaf(ap.y, hs.y, hx.y);
    hx.z = fmaf(ap.z, hs.z, hx.z);
    hx.w = fmaf(ap.w, hs.w, hx.w);
    *(float4*)(hex + (size_t)bblk * DD + c) = hx;
}

// ---------------------------------------------------------------------------
// combine: q = h_fwd + h_bwd_rev (cross-block fixup on the fly) -> fp32 qout.
// ---------------------------------------------------------------------------
__global__ void combine_kernel(
    const float* __restrict__ Af, const float* __restrict__ Bf,
    const float* __restrict__ hexf,
    const float* __restrict__ Ab, const float* __restrict__ Bb,
    const float* __restrict__ hexb,
    float* __restrict__ qout)
{
    int idx = blockIdx.x * blockDim.x + threadIdx.x;   // float4 index
    int t = idx >> 6;
    int c = (idx & 63) << 2;
    int tr = TT - 1 - t;
    int blf = t >> 7;        // CS = 128
    int blb = tr >> 7;

    float4 af = *(const float4*)(Af + (size_t)t * DD + c);
    float4 bfv = *(const float4*)(Bf + (size_t)t * DD + c);
    float4 hf = *(const float4*)(hexf + (size_t)blf * DD + c);
    float4 ab = *(const float4*)(Ab + (size_t)tr * DD + c);
    float4 bb = *(const float4*)(Bb + (size_t)tr * DD + c);
    float4 hb = *(const float4*)(hexb + (size_t)blb * DD + c);

    float4 q4;
    q4.x = fmaf(af.x, hf.x, bfv.x) + fmaf(ab.x, hb.x, bb.x);
    q4.y = fmaf(af.y, hf.y, bfv.y) + fmaf(ab.y, hb.y, bb.y);
    q4.z = fmaf(af.z, hf.z, bfv.z) + fmaf(ab.z, hb.z, bb.z);
    q4.w = fmaf(af.w, hf.w, bfv.w) + fmaf(ab.w, hb.w, bb.w);

    *(float4*)(qout + (size_t)t * DD + c) = q4;
}

// ---------------------------------------------------------------------------
// Host orchestration
// ---------------------------------------------------------------------------
extern "C" void kernel_launch(void* const* d_in, const int* in_sizes, int n_in,
                              void* d_out, int out_size)
{
    const float* story    = (const float*)d_in[0];
    const float* question = (const float*)d_in[1];
    const float* Wz_f = (const float*)d_in[2];
    const float* bz_f = (const float*)d_in[3];
    const float* Wh_f = (const float*)d_in[4];
    const float* bh_f = (const float*)d_in[5];
    const float* Wz_b = (const float*)d_in[6];
    const float* bz_b = (const float*)d_in[7];
    const float* Wh_b = (const float*)d_in[8];
    const float* bh_b = (const float*)d_in[9];
    float* out = (float*)d_out;

    float *qbuf, *af, *bf, *ab, *bb;
    float *aggAf, *aggBf, *hexf, *apref, *aggAb, *aggBb, *hexb, *apreb;
    float *supAf, *supBf, *hsupf, *supAb, *supBb, *hsupb, *bheff;
    __nv_bfloat16 *whi, *wlo;
    cudaGetSymbolAddress((void**)&qbuf,  g_q);
    cudaGetSymbolAddress((void**)&af,    g_af);
    cudaGetSymbolAddress((void**)&bf,    g_bf);
    cudaGetSymbolAddress((void**)&ab,    g_ab);
    cudaGetSymbolAddress((void**)&bb,    g_bb);
    cudaGetSymbolAddress((void**)&aggAf, g_aggA_f);
    cudaGetSymbolAddress((void**)&aggBf, g_aggB_f);
    cudaGetSymbolAddress((void**)&hexf,  g_hex_f);
    cudaGetSymbolAddress((void**)&apref, g_apre_f);
    cudaGetSymbolAddress((void**)&aggAb, g_aggA_b);
    cudaGetSymbolAddress((void**)&aggBb, g_aggB_b);
    cudaGetSymbolAddress((void**)&hexb,  g_hex_b);
    cudaGetSymbolAddress((void**)&apreb, g_apre_b);
    cudaGetSymbolAddress((void**)&supAf, g_supA_f);
    cudaGetSymbolAddress((void**)&supBf, g_supB_f);
    cudaGetSymbolAddress((void**)&hsupf, g_hsup_f);
    cudaGetSymbolAddress((void**)&supAb, g_supA_b);
    cudaGetSymbolAddress((void**)&supBb, g_supB_b);
    cudaGetSymbolAddress((void**)&hsupb, g_hsup_b);
    cudaGetSymbolAddress((void**)&whi,   g_whi);
    cudaGetSymbolAddress((void**)&wlo,   g_wlo);
    cudaGetSymbolAddress((void**)&bheff, g_bheff);

    static int smem_set = 0;
    if (!smem_set) {
        cudaFuncSetAttribute(gemm_mma, cudaFuncAttributeMaxDynamicSharedMemorySize,
                             SMEM_TOTAL);
        smem_set = 1;
    }

    prep_all<<<dim3(DD, 3, 6), 256>>>(Wz_f, Wh_f, Wz_b, Wh_b,
                                      question, bh_f, bh_b, whi, wlo, bheff);

    const int MSZ = 3 * DD * DD;
    dim3 ggrid(DD / BN, TT / BM);   // (4, 512): N fastest -> x/q L2 reuse

    for (int l = 0; l < LL; ++l) {
        const int uq = (l == 0) ? 0 : 1;
        const float* qp = (l == 0) ? question : qbuf;
        const int qstride = (l == 0) ? 0 : DD;
        const float* bhf_eff = (l == 0) ? bheff : bh_f + l * DD;
        const float* bhb_eff = (l == 0) ? bheff + DD : bh_b + l * DD;

        if (l < LL - 1) {
            gemm_mma<<<ggrid, 256, SMEM_TOTAL>>>(
                story, qp, qstride, uq, 0, 1,
                whi + l * MSZ, wlo + l * MSZ,
                bz_f + l * DD, bhf_eff, af, bf, aggAf, aggBf);
            gemm_mma<<<ggrid, 256, SMEM_TOTAL>>>(
                story, qp, qstride, uq, 1, 1,
                whi + (3 + l) * MSZ, wlo + (3 + l) * MSZ,
                bz_b + l * DD, bhb_eff, ab, bb, aggAb, aggBb);

            scan2a_kernel<<<dim3(NSUP, 2), 256>>>(
                aggAf, aggBf, hexf, apref, supAf, supBf,
                aggAb, aggBb, hexb, apreb, supAb, supBb);
            scan2b_kernel<<<2, 256>>>(supAf, supBf, hsupf,
                                      supAb, supBb, hsupb, nullptr);
            scan2c_kernel<<<dim3(NB * DD / 4 / 256, 2), 256>>>(
                hexf, apref, hsupf, hexb, apreb, hsupb);

            combine_kernel<<<TT * DD / 4 / 256, 256>>>(
                af, bf, hexf, ab, bb, hexb, qbuf);
        } else {
            // last layer: aggregates only; final h comes out of the super-scan
            gemm_mma<<<ggrid, 256, SMEM_TOTAL>>>(
                story, qp, qstride, uq, 0, 0,
                whi + l * MSZ, wlo + l * MSZ,
                bz_f + l * DD, bhf_eff, af, bf, aggAf, aggBf);
            scan2a_kernel<<<dim3(NSUP, 1), 256>>>(
                aggAf, aggBf, hexf, apref, supAf, supBf,
                aggAb, aggBb, hexb, apreb, supAb, supBb);
            scan2b_kernel<<<1, 256>>>(supAf, supBf, hsupf,
                                      supAb, supBb, hsupb, out);
        }
    }
}

// round 11
// speedup vs baseline: 1.3680x; 1.0069x over previous
#include <cuda_runtime.h>
#include <cuda_bf16.h>
#include <stdint.h>
#include <math.h>

// Problem constants
#define TT 65536
#define DD 256
#define LL 3

// GEMM tiling (BM=128, BN=64, KC=32)
#define BM 128
#define BN 64
#define KC 32
#define NCHUNK (DD / KC)   // 8

#define ROWB 80                     // padded smem row stride (bytes)
#define A_TILE (128 * ROWB)         // 10240 B
#define B_TILE (64 * ROWB)          // 5120 B
#define BUFSZ  (6 * A_TILE + 6 * B_TILE)  // 92160 B
#define SM_BIAS (2 * BUFSZ)         // 184320
#define SMEM_TOTAL (SM_BIAS + 512 + 64)
#define SM_SEG (2 * 128 * 68 * 4)   // 69632 (epilogue seg aggregates)

// Scan blocking
#define CS 128
#define NB (TT / CS)   // 512
#define SBLK 16
#define NSUP (NB / SBLK)  // 32

// ---------------------------------------------------------------------------
// Scratch
// ---------------------------------------------------------------------------
__device__ __align__(256) float g_q[TT * DD];
__device__ __align__(256) float g_af[TT * DD];
__device__ __align__(256) float g_bf[TT * DD];
__device__ __align__(256) float g_ab[TT * DD];
__device__ __align__(256) float g_bb[TT * DD];
__device__ __align__(256) float g_aggA_f[NB * DD];
__device__ __align__(256) float g_aggB_f[NB * DD];
__device__ __align__(256) float g_hex_f[NB * DD];
__device__ __align__(256) float g_apre_f[NB * DD];
__device__ __align__(256) float g_aggA_b[NB * DD];
__device__ __align__(256) float g_aggB_b[NB * DD];
__device__ __align__(256) float g_hex_b[NB * DD];
__device__ __align__(256) float g_apre_b[NB * DD];
__device__ __align__(256) float g_supA_f[NSUP * DD];
__device__ __align__(256) float g_supB_f[NSUP * DD];
__device__ __align__(256) float g_hsup_f[NSUP * DD];
__device__ __align__(256) float g_supA_b[NSUP * DD];
__device__ __align__(256) float g_supB_b[NSUP * DD];
__device__ __align__(256) float g_hsup_b[NSUP * DD];
__device__ __align__(256) __nv_bfloat16 g_whi[5 * 3 * DD * DD];
__device__ __align__(256) __nv_bfloat16 g_wlo[5 * 3 * DD * DD];
__device__ __align__(256) float g_bheff[2 * DD];

__device__ __forceinline__ float tanh_fast(float v) {
    float r;
    asm("tanh.approx.f32 %0, %1;" : "=f"(r) : "f"(v));
    return r;
}
__device__ __forceinline__ uint32_t smem_u32(const void* p) {
    uint32_t a;
    asm("{ .reg .u64 t; cvta.to.shared.u64 t, %1; cvt.u32.u64 %0, t; }"
        : "=r"(a) : "l"(p));
    return a;
}
__device__ __forceinline__ void ldsm4(uint32_t addr, uint32_t* r) {
    asm volatile("ldmatrix.sync.aligned.m8n8.x4.shared.b16 {%0,%1,%2,%3}, [%4];"
                 : "=r"(r[0]), "=r"(r[1]), "=r"(r[2]), "=r"(r[3]) : "r"(addr));
}
__device__ __forceinline__ void mma16816(float* c, const uint32_t* a,
                                         const uint32_t* b) {
    asm volatile(
        "mma.sync.aligned.m16n8k16.row.col.f32.bf16.bf16.f32 "
        "{%0,%1,%2,%3}, {%4,%5,%6,%7}, {%8,%9}, {%0,%1,%2,%3};"
        : "+f"(c[0]), "+f"(c[1]), "+f"(c[2]), "+f"(c[3])
        : "r"(a[0]), "r"(a[1]), "r"(a[2]), "r"(a[3]), "r"(b[0]), "r"(b[1]));
}

// hi/lo bf16 split of a float4; one 8B store each
__device__ __forceinline__ void split_store(float4 v, char* hi, char* lo) {
    __nv_bfloat16 h0 = __float2bfloat16_rn(v.x);
    __nv_bfloat16 h1 = __float2bfloat16_rn(v.y);
    __nv_bfloat16 h2 = __float2bfloat16_rn(v.z);
    __nv_bfloat16 h3 = __float2bfloat16_rn(v.w);
    __nv_bfloat162 H0; H0.x = h0; H0.y = h1;
    __nv_bfloat162 H1; H1.x = h2; H1.y = h3;
    __nv_bfloat162 L0, L1;
    L0.x = __float2bfloat16_rn(v.x - __bfloat162float(h0));
    L0.y = __float2bfloat16_rn(v.y - __bfloat162float(h1));
    L1.x = __float2bfloat16_rn(v.z - __bfloat162float(h2));
    L1.y = __float2bfloat16_rn(v.w - __bfloat162float(h3));
    uint2 H; H.x = *(uint32_t*)&H0; H.y = *(uint32_t*)&H1;
    uint2 L; L.x = *(uint32_t*)&L0; L.y = *(uint32_t*)&L1;
    *(uint2*)hi = H;
    *(uint2*)lo = L;
}

// ---------------------------------------------------------------------------
// prep_all: z-slots 0..4 = weight transpose+split; z-slot 5 = layer-0 bias fold
// ---------------------------------------------------------------------------
__global__ void prep_all(const float* __restrict__ Wz_f, const float* __restrict__ Wh_f,
                         const float* __restrict__ Wz_b, const float* __restrict__ Wh_b,
                         const float* __restrict__ question,
                         const float* __restrict__ bh_f, const float* __restrict__ bh_b,
                         __nv_bfloat16* __restrict__ whi, __nv_bfloat16* __restrict__ wlo,
                         float* __restrict__ bheff)
{
    int n = blockIdx.x, m = blockIdx.y, s = blockIdx.z, k = threadIdx.x;
    if (s == 5) {
        if (m >= 2) return;
        __shared__ float red[256];
        const float* Wh = m ? Wh_b : Wh_f;
        const float* bh = m ? bh_b : bh_f;
        red[k] = question[k] * Wh[(DD + k) * DD + n];
        __syncthreads();
        for (int st = 128; st > 0; st >>= 1) {
            if (k < st) red[k] += red[k + st];
            __syncthreads();
        }
        if (k == 0) bheff[m * DD + n] = bh[n] + red[0];
        return;
    }
    const float* Wz;
    const float* Wh;
    if (s < 3) { Wz = Wz_f + s * DD * DD; Wh = Wh_f + s * 2 * DD * DD; }
    else       { Wz = Wz_b + (s - 3) * DD * DD; Wh = Wh_b + (s - 3) * 2 * DD * DD; }
    float v = (m == 0) ? Wz[k * DD + n]
            : (m == 1) ? Wh[k * DD + n]
                       : Wh[(DD + k) * DD + n];
    __nv_bfloat16 hi = __float2bfloat16_rn(v);
    __nv_bfloat16 lo = __float2bfloat16_rn(v - __bfloat162float(hi));
    size_t o = (size_t)(s * 3 + m) * DD * DD + (size_t)n * DD + k;
    whi[o] = hi;
    wlo[o] = lo;
}

// ---------------------------------------------------------------------------
// Fused GEMM + activation + block-local scan. blockIdx.z = direction
// (0 = forward, 1 = backward/reversed). One __syncthreads per K chunk;
// both x/q AND weights are register-prefetched one chunk ahead.
// ---------------------------------------------------------------------------
__global__ void __launch_bounds__(256, 1) gemm_mma(
    const float* __restrict__ x, const float* __restrict__ qp, int qstride,
    int use_q, int do_store,
    const __nv_bfloat16* __restrict__ whi_f, const __nv_bfloat16* __restrict__ wlo_f,
    const __nv_bfloat16* __restrict__ whi_b, const __nv_bfloat16* __restrict__ wlo_b,
    const float* __restrict__ bz_f, const float* __restrict__ bh_f,
    const float* __restrict__ bz_b, const float* __restrict__ bh_b,
    float* __restrict__ outA_f, float* __restrict__ outB_f,
    float* __restrict__ aggA_f, float* __restrict__ aggB_f,
    float* __restrict__ outA_b, float* __restrict__ outB_b,
    float* __restrict__ aggA_b, float* __restrict__ aggB_b)
{
    extern __shared__ char smem[];
    const int tid = threadIdx.x;
    const int wid = tid >> 5;
    const int lane = tid & 31;
    const int wm = wid & 3;
    const int wn = wid >> 2;
    const int nbase = blockIdx.x * BN;      // N fastest -> x/q L2 reuse
    const int tbase = blockIdx.y * BM;
    const int mblk  = blockIdx.y;
    const int rev   = blockIdx.z;
    const uint32_t sb = smem_u32(smem);

    const __nv_bfloat16* whi = rev ? whi_b : whi_f;
    const __nv_bfloat16* wlo = rev ? wlo_b : wlo_f;
    const float* bz = rev ? bz_b : bz_f;
    const float* bh = rev ? bh_b : bh_f;
    float* outA = rev ? outA_b : outA_f;
    float* outB = rev ? outB_b : outB_f;
    float* aggA = rev ? aggA_b : aggA_f;
    float* aggB = rev ? aggB_b : aggB_f;

    float* bzs = (float*)(smem + SM_BIAS);
    float* bhs = bzs + 64;
    if (tid < 64) {
        bzs[tid] = bz[nbase + tid];
        bhs[tid] = bh[nbase + tid];
    }

    const __nv_bfloat16* w6[6] = {
        whi, wlo, whi + DD * DD, wlo + DD * DD, whi + 2 * DD * DD, wlo + 2 * DD * DD
    };
    const int np = use_q ? 6 : 4;

    float acc[2][2][4][4];
    #pragma unroll
    for (int zh = 0; zh < 2; ++zh)
        #pragma unroll
        for (int mt = 0; mt < 2; ++mt)
            #pragma unroll
            for (int nt = 0; nt < 4; ++nt)
                #pragma unroll
                for (int j = 0; j < 4; ++j) acc[zh][mt][nt][j] = 0.f;

    // --- staging with full register prefetch (x, q, AND weights) ----------
    float4 pxv[4], pqv[4];
    uint4 wv[6];
    const int wrow = tid >> 2;   // 0..63 weight row
    const int wseg = tid & 3;    // 16B segment

    auto load_xq = [&](int k0) {
        #pragma unroll
        for (int it = 0; it < 4; ++it) {
            int j = tid + it * 256;
            int m = j >> 3, kq = j & 7;
            int tg = rev ? (TT - 1 - (tbase + m)) : (tbase + m);
            pxv[it] = *(const float4*)(x + (size_t)tg * DD + k0 + kq * 4);
            pqv[it] = *(const float4*)(qp + (size_t)tg * qstride + k0 + kq * 4);
        }
    };
    auto load_W = [&](int k0) {
        #pragma unroll
        for (int m6 = 0; m6 < 6; ++m6)
            if (m6 < np)
                wv[m6] = *(const uint4*)(w6[m6] + (size_t)(nbase + wrow) * DD + k0 + wseg * 8);
    };
    auto stage_A = [&](int buf) {
        char* base = smem + buf * BUFSZ;
        #pragma unroll
        for (int it = 0; it < 4; ++it) {
            int j = tid + it * 256;
            int m = j >> 3, kq = j & 7;
            int off = m * ROWB + kq * 8;
            float4 xv = pxv[it], qv = pqv[it];
            float4 uv = make_float4(xv.x * qv.x, xv.y * qv.y, xv.z * qv.z, xv.w * qv.w);
            split_store(uv, base + 0 * A_TILE + off, base + 1 * A_TILE + off);
            split_store(xv, base + 2 * A_TILE + off, base + 3 * A_TILE + off);
            if (use_q)
                split_store(qv, base + 4 * A_TILE + off, base + 5 * A_TILE + off);
        }
    };
    auto store_W = [&](int buf) {
        char* base = smem + buf * BUFSZ + 6 * A_TILE;
        #pragma unroll
        for (int m6 = 0; m6 < 6; ++m6)
            if (m6 < np)
                *(uint4*)(base + m6 * B_TILE + wrow * ROWB + wseg * 16) = wv[m6];
    };

    load_xq(0);
    load_W(0);
    stage_A(0);
    store_W(0);
    __syncthreads();

    const int r = lane & 7, g = lane >> 3;
    #pragma unroll 1
    for (int c = 0; c < NCHUNK; ++c) {
        if (c < NCHUNK - 1) {
            load_xq((c + 1) * KC);   // gmem prefetch to regs (overlaps MMA)
            load_W((c + 1) * KC);
        }

        const uint32_t abuf = sb + (c & 1) * BUFSZ;
        const uint32_t bbuf = abuf + 6 * A_TILE;

        #pragma unroll
        for (int ks = 0; ks < 2; ++ks) {
            const uint32_t kso = ks * 32;
            uint32_t af[6][2][4];
            #pragma unroll
            for (int o = 0; o < 6; ++o)
                if (o < np) {
                    #pragma unroll
                    for (int mt = 0; mt < 2; ++mt) {
                        uint32_t addr = abuf + o * A_TILE
                            + (wm * 32 + mt * 16 + (g & 1) * 8 + r) * ROWB
                            + (g >> 1) * 16 + kso;
                        ldsm4(addr, af[o][mt]);
                    }
                }
            uint32_t bf[6][4][2];
            #pragma unroll
            for (int m6 = 0; m6 < 6; ++m6)
                if (m6 < np) {
                    #pragma unroll
                    for (int j = 0; j < 2; ++j) {
                        uint32_t tmp[4];
                        uint32_t addr = bbuf + m6 * B_TILE
                            + (wn * 32 + (2 * j + (g >> 1)) * 8 + r) * ROWB
                            + (g & 1) * 16 + kso;
                        ldsm4(addr, tmp);
                        bf[m6][2 * j][0] = tmp[0]; bf[m6][2 * j][1] = tmp[1];
                        bf[m6][2 * j + 1][0] = tmp[2]; bf[m6][2 * j + 1][1] = tmp[3];
                    }
                }
            #pragma unroll
            for (int mt = 0; mt < 2; ++mt)
                #pragma unroll
                for (int nt = 0; nt < 4; ++nt) {
                    mma16816(acc[0][mt][nt], af[0][mt], bf[0][nt]);
                    mma16816(acc[0][mt][nt], af[0][mt], bf[1][nt]);
                    mma16816(acc[0][mt][nt], af[1][mt], bf[0][nt]);
                    mma16816(acc[1][mt][nt], af[2][mt], bf[2][nt]);
                    mma16816(acc[1][mt][nt], af[2][mt], bf[3][nt]);
                    mma16816(acc[1][mt][nt], af[3][mt], bf[2][nt]);
                    if (use_q) {
                        mma16816(acc[1][mt][nt], af[4][mt], bf[4][nt]);
                        mma16816(acc[1][mt][nt], af[4][mt], bf[5][nt]);
                        mma16816(acc[1][mt][nt], af[5][mt], bf[4][nt]);
                    }
                }
        }
        // single barrier per chunk: stores go to the other buffer (WAR-safe
        // via the previous chunk's barrier); this barrier publishes them.
        if (c < NCHUNK - 1) {
            stage_A((c + 1) & 1);
            store_W((c + 1) & 1);
        }
        __syncthreads();
    }

    // --- epilogue: activations -> smem transpose ---------------------------
    float* smA = (float*)smem;              // [128][68]
    float* smB = smA + 128 * 68;
    #pragma unroll
    for (int mt = 0; mt < 2; ++mt)
        #pragma unroll
        for (int nt = 0; nt < 4; ++nt) {
            int col = wn * 32 + nt * 8 + 2 * (lane & 3);
            int row0 = wm * 32 + mt * 16 + (lane >> 2);
            #pragma unroll
            for (int h8 = 0; h8 < 2; ++h8) {
                int row = row0 + h8 * 8;
                float z0 = 0.5f * tanh_fast(0.5f * (acc[0][mt][nt][2*h8+0] + bzs[col]))   + 0.5f;
                float z1 = 0.5f * tanh_fast(0.5f * (acc[0][mt][nt][2*h8+1] + bzs[col+1])) + 0.5f;
                float t0 = tanh_fast(acc[1][mt][nt][2*h8+0] + bhs[col]);
                float t1 = tanh_fast(acc[1][mt][nt][2*h8+1] + bhs[col+1]);
                *(float2*)(smA + row * 68 + col) = make_float2(1.f - z0, 1.f - z1);
                *(float2*)(smB + row * 68 + col) = make_float2(z0 * t0, z1 * t1);
            }
        }
    __syncthreads();

    // --- fused block-local scan over 128 rows (4 segments x 32) ------------
    float* segA = (float*)(smem + SM_SEG);        // [4][64]
    float* segB = segA + 4 * 64;
    {
        const int col = tid & 63;
        const int sg = tid >> 6;
        const int rbase = sg * 32;
        float Ap = 1.f, hl = 0.f;
        #pragma unroll 8
        for (int i = 0; i < 32; ++i) {
            int off = (rbase + i) * 68 + col;
            float a = smA[off], b = smB[off];
            Ap *= a;
            hl = fmaf(a, hl, b);
            if (do_store) { smA[off] = Ap; smB[off] = hl; }
        }
        segA[sg * 64 + col] = Ap;
        segB[sg * 64 + col] = hl;
        __syncthreads();
        float Ain = 1.f, Hin = 0.f;
        #pragma unroll
        for (int s = 0; s < 3; ++s)
            if (s < sg) {
                float sa = segA[s * 64 + col], sbv = segB[s * 64 + col];
                Ain *= sa;
                Hin = fmaf(sa, Hin, sbv);
            }
        if (do_store) {
            #pragma unroll 8
            for (int i = 0; i < 32; ++i) {
                int off = (rbase + i) * 68 + col;
                float Al = smA[off], Bl = smB[off];
                smA[off] = Ain * Al;
                smB[off] = fmaf(Al, Hin, Bl);
            }
        }
        if (sg == 3) {
            aggA[(size_t)mblk * DD + nbase + col] = Ain * Ap;
            aggB[(size_t)mblk * DD + nbase + col] = fmaf(Ap, Hin, hl);
        }
    }

    if (do_store) {
        __syncthreads();
        #pragma unroll
        for (int it = 0; it < 8; ++it) {
            int j = tid + it * 256;
            int row = j >> 4, cf = j & 15;
            size_t go = (size_t)(tbase + row) * DD + nbase + cf * 4;
            *(float4*)(outA + go) = *(const float4*)(smA + row * 68 + cf * 4);
            *(float4*)(outB + go) = *(const float4*)(smB + row * 68 + cf * 4);
        }
    }
}

// ---------------------------------------------------------------------------
// scan2a: per super-block (16 blocks) local scan. grid (NSUP, ndirs).
// ---------------------------------------------------------------------------
__global__ void scan2a_kernel(
    const float* __restrict__ aggAf, const float* __restrict__ aggBf,
    float* __restrict__ hexf, float* __restrict__ apref,
    float* __restrict__ supAf, float* __restrict__ supBf,
    const float* __restrict__ aggAb, const float* __restrict__ aggBb,
    float* __restrict__ hexb, float* __restrict__ apreb,
    float* __restrict__ supAb, float* __restrict__ supBb)
{
    const int dirb = blockIdx.y;
    const float* aggA = dirb ? aggAb : aggAf;
    const float* aggB = dirb ? aggBb : aggBf;
    float* hex  = dirb ? hexb : hexf;
    float* apre = dirb ? apreb : apref;
    float* supA = dirb ? supAb : supAf;
    float* supB = dirb ? supBb : supBf;

    const int s = blockIdx.x, d = threadIdx.x;
    float a[SBLK], b[SBLK];
    #pragma unroll
    for (int i = 0; i < SBLK; ++i) {
        size_t o = (size_t)(s * SBLK + i) * DD + d;
        a[i] = aggA[o];
        b[i] = aggB[o];
    }
    float H = 0.f, A = 1.f;
    #pragma unroll
    for (int i = 0; i < SBLK; ++i) {
        size_t o = (size_t)(s * SBLK + i) * DD + d;
        hex[o] = H;
        apre[o] = A;
        H = fmaf(a[i], H, b[i]);
        A *= a[i];
    }
    supA[(size_t)s * DD + d] = A;
    supB[(size_t)s * DD + d] = H;
}

// ---------------------------------------------------------------------------
// scan2b: scan over NSUP super-aggregates; optional final-state output.
// ---------------------------------------------------------------------------
__global__ void scan2b_kernel(
    const float* __restrict__ supAf, const float* __restrict__ supBf,
    float* __restrict__ hsupf,
    const float* __restrict__ supAb, const float* __restrict__ supBb,
    float* __restrict__ hsupb,
    float* __restrict__ out)
{
    const int dirb = blockIdx.x;
    const float* supA = dirb ? supAb : supAf;
    const float* supB = dirb ? supBb : supBf;
    float* hsup = dirb ? hsupb : hsupf;
    const int d = threadIdx.x;

    float a[NSUP / 2], b[NSUP / 2];
    float H = 0.f;
    #pragma unroll
    for (int half = 0; half < 2; ++half) {
        #pragma unroll
        for (int i = 0; i < NSUP / 2; ++i) {
            size_t o = (size_t)(half * (NSUP / 2) + i) * DD + d;
            a[i] = supA[o];
            b[i] = supB[o];
        }
        #pragma unroll
        for (int i = 0; i < NSUP / 2; ++i) {
            hsup[(size_t)(half * (NSUP / 2) + i) * DD + d] = H;
            H = fmaf(a[i], H, b[i]);
        }
    }
    if (out && dirb == 0) out[d] = H;
}

// ---------------------------------------------------------------------------
// scan2c: hex[b] = APre[b] * Hsup[b/16] + hexL[b]  (in place). grid(128, 2).
// ---------------------------------------------------------------------------
__global__ void scan2c_kernel(
    float* __restrict__ hexf, const float* __restrict__ apref,
    const float* __restrict__ hsupf,
    float* __restrict__ hexb, const float* __restrict__ apreb,
    const float* __restrict__ hsupb)
{
    const int dirb = blockIdx.y;
    float* hex = dirb ? hexb : hexf;
    const float* apre = dirb ? apreb : apref;
    const float* hsup = dirb ? hsupb : hsupf;

    int idx = blockIdx.x * 256 + threadIdx.x;
    int bblk = idx >> 6;
    int c = (idx & 63) << 2;
    int sup = bblk >> 4;

    float4 ap = *(const float4*)(apre + (size_t)bblk * DD + c);
    float4 hs = *(const float4*)(hsup + (size_t)sup * DD + c);
    float4 hx = *(const float4*)(hex + (size_t)bblk * DD + c);
    hx.x = fmaf(ap.x, hs.x, hx.x);
    hx.y = fmaf(ap.y, hs.y, hx.y);
    hx.z = fmaf(ap.z, hs.z, hx.z);
    hx.w = fmaf(ap.w, hs.w, hx.w);
    *(float4*)(hex + (size_t)bblk * DD + c) = hx;
}

// ---------------------------------------------------------------------------
// combine: q = h_fwd + h_bwd_rev (cross-block fixup on the fly) -> fp32 qout.
// ---------------------------------------------------------------------------
__global__ void combine_kernel(
    const float* __restrict__ Af, const float* __restrict__ Bf,
    const float* __restrict__ hexf,
    const float* __restrict__ Ab, const float* __restrict__ Bb,
    const float* __restrict__ hexb,
    float* __restrict__ qout)
{
    int idx = blockIdx.x * blockDim.x + threadIdx.x;
    int t = idx >> 6;
    int c = (idx & 63) << 2;
    int tr = TT - 1 - t;
    int blf = t >> 7;
    int blb = tr >> 7;

    float4 af = *(const float4*)(Af + (size_t)t * DD + c);
    float4 bfv = *(const float4*)(Bf + (size_t)t * DD + c);
    float4 hf = *(const float4*)(hexf + (size_t)blf * DD + c);
    float4 ab = *(const float4*)(Ab + (size_t)tr * DD + c);
    float4 bb = *(const float4*)(Bb + (size_t)tr * DD + c);
    float4 hb = *(const float4*)(hexb + (size_t)blb * DD + c);

    float4 q4;
    q4.x = fmaf(af.x, hf.x, bfv.x) + fmaf(ab.x, hb.x, bb.x);
    q4.y = fmaf(af.y, hf.y, bfv.y) + fmaf(ab.y, hb.y, bb.y);
    q4.z = fmaf(af.z, hf.z, bfv.z) + fmaf(ab.z, hb.z, bb.z);
    q4.w = fmaf(af.w, hf.w, bfv.w) + fmaf(ab.w, hb.w, bb.w);

    *(float4*)(qout + (size_t)t * DD + c) = q4;
}

// ---------------------------------------------------------------------------
// Host orchestration
// ---------------------------------------------------------------------------
extern "C" void kernel_launch(void* const* d_in, const int* in_sizes, int n_in,
                              void* d_out, int out_size)
{
    const float* story    = (const float*)d_in[0];
    const float* question = (const float*)d_in[1];
    const float* Wz_f = (const float*)d_in[2];
    const float* bz_f = (const float*)d_in[3];
    const float* Wh_f = (const float*)d_in[4];
    const float* bh_f = (const float*)d_in[5];
    const float* Wz_b = (const float*)d_in[6];
    const float* bz_b = (const float*)d_in[7];
    const float* Wh_b = (const float*)d_in[8];
    const float* bh_b = (const float*)d_in[9];
    float* out = (float*)d_out;

    float *qbuf, *af, *bf, *ab, *bb;
    float *aggAf, *aggBf, *hexf, *apref, *aggAb, *aggBb, *hexb, *apreb;
    float *supAf, *supBf, *hsupf, *supAb, *supBb, *hsupb, *bheff;
    __nv_bfloat16 *whi, *wlo;
    cudaGetSymbolAddress((void**)&qbuf,  g_q);
    cudaGetSymbolAddress((void**)&af,    g_af);
    cudaGetSymbolAddress((void**)&bf,    g_bf);
    cudaGetSymbolAddress((void**)&ab,    g_ab);
    cudaGetSymbolAddress((void**)&bb,    g_bb);
    cudaGetSymbolAddress((void**)&aggAf, g_aggA_f);
    cudaGetSymbolAddress((void**)&aggBf, g_aggB_f);
    cudaGetSymbolAddress((void**)&hexf,  g_hex_f);
    cudaGetSymbolAddress((void**)&apref, g_apre_f);
    cudaGetSymbolAddress((void**)&aggAb, g_aggA_b);
    cudaGetSymbolAddress((void**)&aggBb, g_aggB_b);
    cudaGetSymbolAddress((void**)&hexb,  g_hex_b);
    cudaGetSymbolAddress((void**)&apreb, g_apre_b);
    cudaGetSymbolAddress((void**)&supAf, g_supA_f);
    cudaGetSymbolAddress((void**)&supBf, g_supB_f);
    cudaGetSymbolAddress((void**)&hsupf, g_hsup_f);
    cudaGetSymbolAddress((void**)&supAb, g_supA_b);
    cudaGetSymbolAddress((void**)&supBb, g_supB_b);
    cudaGetSymbolAddress((void**)&hsupb, g_hsup_b);
    cudaGetSymbolAddress((void**)&whi,   g_whi);
    cudaGetSymbolAddress((void**)&wlo,   g_wlo);
    cudaGetSymbolAddress((void**)&bheff, g_bheff);

    static int smem_set = 0;
    if (!smem_set) {
        cudaFuncSetAttribute(gemm_mma, cudaFuncAttributeMaxDynamicSharedMemorySize,
                             SMEM_TOTAL);
        smem_set = 1;
    }

    prep_all<<<dim3(DD, 3, 6), 256>>>(Wz_f, Wh_f, Wz_b, Wh_b,
                                      question, bh_f, bh_b, whi, wlo, bheff);

    const int MSZ = 3 * DD * DD;

    for (int l = 0; l < LL; ++l) {
        const int uq = (l == 0) ? 0 : 1;
        const float* qp = (l == 0) ? question : qbuf;
        const int qstride = (l == 0) ? 0 : DD;
        const float* bhf_eff = (l == 0) ? bheff : bh_f + l * DD;
        const float* bhb_eff = (l == 0) ? bheff + DD : bh_b + l * DD;

        if (l < LL - 1) {
            // fwd + bwd in one launch (blockIdx.z = direction)
            dim3 ggrid(DD / BN, TT / BM, 2);
            gemm_mma<<<ggrid, 256, SMEM_TOTAL>>>(
                story, qp, qstride, uq, 1,
                whi + l * MSZ, wlo + l * MSZ,
                whi + (3 + l) * MSZ, wlo + (3 + l) * MSZ,
                bz_f + l * DD, bhf_eff, bz_b + l * DD, bhb_eff,
                af, bf, aggAf, aggBf, ab, bb, aggAb, aggBb);

            scan2a_kernel<<<dim3(NSUP, 2), 256>>>(
                aggAf, aggBf, hexf, apref, supAf, supBf,
                aggAb, aggBb, hexb, apreb, supAb, supBb);
            scan2b_kernel<<<2, 256>>>(supAf, supBf, hsupf,
                                      supAb, supBb, hsupb, nullptr);
            scan2c_kernel<<<dim3(NB * DD / 4 / 256, 2), 256>>>(
                hexf, apref, hsupf, hexb, apreb, hsupb);

            combine_kernel<<<TT * DD / 4 / 256, 256>>>(
                af, bf, hexf, ab, bb, hexb, qbuf);
        } else {
            // last layer: forward only, aggregates only
            dim3 ggrid(DD / BN, TT / BM, 1);
            gemm_mma<<<ggrid, 256, SMEM_TOTAL>>>(
                story, qp, qstride, uq, 0,
                whi + l * MSZ, wlo + l * MSZ,
                whi + l * MSZ, wlo + l * MSZ,
                bz_f + l * DD, bhf_eff, bz_f + l * DD, bhf_eff,
                af, bf, aggAf, aggBf, af, bf, aggAf, aggBf);
            scan2a_kernel<<<dim3(NSUP, 1), 256>>>(
                aggAf, aggBf, hexf, apref, supAf, supBf,
                aggAb, aggBb, hexb, apreb, supAb, supBb);
            scan2b_kernel<<<1, 256>>>(supAf, supBf, hsupf,
                                      supAb, supBb, hsupb, out);
        }
    }
}

// round 12
// speedup vs baseline: 2.3093x; 1.6881x over previous
#include <cuda_runtime.h>
#include <cuda_bf16.h>
#include <cuda_fp16.h>
#include <stdint.h>
#include <math.h>

// Problem constants
#define TT 65536
#define DD 256
#define LL 3

// GEMM tiling (BM=128, BN=64, KC=32), fp16 single-plane operands
#define BM 128
#define BN 64
#define KC 32
#define NCHUNK (DD / KC)   // 8

#define ROWB 80                     // padded smem row stride (bytes)
#define A_TILE (128 * ROWB)         // 10240 B
#define B_TILE (64 * ROWB)          // 5120 B
#define BUFSZ  (3 * A_TILE + 3 * B_TILE)  // 46080 B
#define SM_BIAS (2 * BUFSZ)         // 92160
#define SMEM_TOTAL (SM_BIAS + 512 + 64)
#define SM_SEG (2 * 128 * 68 * 4)   // 69632 (< BUFSZ*2, reuses buffers)

// Scan blocking
#define CS 128
#define NB (TT / CS)   // 512
#define SBLK 16
#define NSUP (NB / SBLK)  // 32

// ---------------------------------------------------------------------------
// Scratch
// ---------------------------------------------------------------------------
__device__ __align__(256) float g_q[TT * DD];
__device__ __align__(256) float g_af[TT * DD];
__device__ __align__(256) float g_bf[TT * DD];
__device__ __align__(256) float g_ab[TT * DD];
__device__ __align__(256) float g_bb[TT * DD];
__device__ __align__(256) float g_aggA_f[NB * DD];
__device__ __align__(256) float g_aggB_f[NB * DD];
__device__ __align__(256) float g_hex_f[NB * DD];
__device__ __align__(256) float g_apre_f[NB * DD];
__device__ __align__(256) float g_aggA_b[NB * DD];
__device__ __align__(256) float g_aggB_b[NB * DD];
__device__ __align__(256) float g_hex_b[NB * DD];
__device__ __align__(256) float g_apre_b[NB * DD];
__device__ __align__(256) float g_supA_f[NSUP * DD];
__device__ __align__(256) float g_supB_f[NSUP * DD];
__device__ __align__(256) float g_hsup_f[NSUP * DD];
__device__ __align__(256) float g_supA_b[NSUP * DD];
__device__ __align__(256) float g_supB_b[NSUP * DD];
__device__ __align__(256) float g_hsup_b[NSUP * DD];
// fp16 pre-transposed weights: [5 layer-dirs][3 mats][256 n][256 k]
__device__ __align__(256) __half g_wh16[5 * 3 * DD * DD];
__device__ __align__(256) float g_bheff[2 * DD];

__device__ __forceinline__ float tanh_fast(float v) {
    float r;
    asm("tanh.approx.f32 %0, %1;" : "=f"(r) : "f"(v));
    return r;
}
__device__ __forceinline__ uint32_t smem_u32(const void* p) {
    uint32_t a;
    asm("{ .reg .u64 t; cvta.to.shared.u64 t, %1; cvt.u32.u64 %0, t; }"
        : "=r"(a) : "l"(p));
    return a;
}
__device__ __forceinline__ void ldsm4(uint32_t addr, uint32_t* r) {
    asm volatile("ldmatrix.sync.aligned.m8n8.x4.shared.b16 {%0,%1,%2,%3}, [%4];"
                 : "=r"(r[0]), "=r"(r[1]), "=r"(r[2]), "=r"(r[3]) : "r"(addr));
}
__device__ __forceinline__ void mma16816(float* c, const uint32_t* a,
                                         const uint32_t* b) {
    asm volatile(
        "mma.sync.aligned.m16n8k16.row.col.f32.f16.f16.f32 "
        "{%0,%1,%2,%3}, {%4,%5,%6,%7}, {%8,%9}, {%0,%1,%2,%3};"
        : "+f"(c[0]), "+f"(c[1]), "+f"(c[2]), "+f"(c[3])
        : "r"(a[0]), "r"(a[1]), "r"(a[2]), "r"(a[3]), "r"(b[0]), "r"(b[1]));
}

// fp16 convert+store of a float4 (one 8B store)
__device__ __forceinline__ void h_store(float4 v, char* dst) {
    __half2 p0 = __floats2half2_rn(v.x, v.y);
    __half2 p1 = __floats2half2_rn(v.z, v.w);
    uint2 P;
    P.x = *(uint32_t*)&p0;
    P.y = *(uint32_t*)&p1;
    *(uint2*)dst = P;
}

// ---------------------------------------------------------------------------
// prep_all: z-slots 0..4 = weight transpose to fp16 [n][k]; z-slot 5 =
// layer-0 effective h-bias (bh + Whq^T q0) for both directions.
// ---------------------------------------------------------------------------
__global__ void prep_all(const float* __restrict__ Wz_f, const float* __restrict__ Wh_f,
                         const float* __restrict__ Wz_b, const float* __restrict__ Wh_b,
                         const float* __restrict__ question,
                         const float* __restrict__ bh_f, const float* __restrict__ bh_b,
                         __half* __restrict__ wh16, float* __restrict__ bheff)
{
    int n = blockIdx.x, m = blockIdx.y, s = blockIdx.z, k = threadIdx.x;
    if (s == 5) {
        if (m >= 2) return;
        __shared__ float red[256];
        const float* Wh = m ? Wh_b : Wh_f;
        const float* bh = m ? bh_b : bh_f;
        red[k] = question[k] * Wh[(DD + k) * DD + n];
        __syncthreads();
        for (int st = 128; st > 0; st >>= 1) {
            if (k < st) red[k] += red[k + st];
            __syncthreads();
        }
        if (k == 0) bheff[m * DD + n] = bh[n] + red[0];
        return;
    }
    const float* Wz;
    const float* Wh;
    if (s < 3) { Wz = Wz_f + s * DD * DD; Wh = Wh_f + s * 2 * DD * DD; }
    else       { Wz = Wz_b + (s - 3) * DD * DD; Wh = Wh_b + (s - 3) * 2 * DD * DD; }
    float v = (m == 0) ? Wz[k * DD + n]
            : (m == 1) ? Wh[k * DD + n]
                       : Wh[(DD + k) * DD + n];
    wh16[(size_t)(s * 3 + m) * DD * DD + (size_t)n * DD + k] = __float2half_rn(v);
}

// ---------------------------------------------------------------------------
// Fused GEMM (fp16 mma.sync, single plane per operand) + activation +
// block-local scan. blockIdx.z = direction.
// ---------------------------------------------------------------------------
__global__ void __launch_bounds__(256, 1) gemm_mma(
    const float* __restrict__ x, const float* __restrict__ qp, int qstride,
    int use_q, int do_store,
    const __half* __restrict__ wh_f, const __half* __restrict__ wh_b,
    const float* __restrict__ bz_f, const float* __restrict__ bh_f,
    const float* __restrict__ bz_b, const float* __restrict__ bh_b,
    float* __restrict__ outA_f, float* __restrict__ outB_f,
    float* __restrict__ aggA_f, float* __restrict__ aggB_f,
    float* __restrict__ outA_b, float* __restrict__ outB_b,
    float* __restrict__ aggA_b, float* __restrict__ aggB_b)
{
    extern __shared__ char smem[];
    const int tid = threadIdx.x;
    const int wid = tid >> 5;
    const int lane = tid & 31;
    const int wm = wid & 3;
    const int wn = wid >> 2;
    const int nbase = blockIdx.x * BN;      // N fastest -> x/q L2 reuse
    const int tbase = blockIdx.y * BM;
    const int mblk  = blockIdx.y;
    const int rev   = blockIdx.z;
    const uint32_t sb = smem_u32(smem);

    const __half* wh = rev ? wh_b : wh_f;
    const float* bz = rev ? bz_b : bz_f;
    const float* bh = rev ? bh_b : bh_f;
    float* outA = rev ? outA_b : outA_f;
    float* outB = rev ? outB_b : outB_f;
    float* aggA = rev ? aggA_b : aggA_f;
    float* aggB = rev ? aggB_b : aggB_f;

    float* bzs = (float*)(smem + SM_BIAS);
    float* bhs = bzs + 64;
    if (tid < 64) {
        bzs[tid] = bz[nbase + tid];
        bhs[tid] = bh[nbase + tid];
    }

    const __half* w3[3] = { wh, wh + DD * DD, wh + 2 * DD * DD };  // Wz, Whx, Whq
    const int np = use_q ? 3 : 2;

    float acc[2][2][4][4];
    #pragma unroll
    for (int zh = 0; zh < 2; ++zh)
        #pragma unroll
        for (int mt = 0; mt < 2; ++mt)
            #pragma unroll
            for (int nt = 0; nt < 4; ++nt)
                #pragma unroll
                for (int j = 0; j < 4; ++j) acc[zh][mt][nt][j] = 0.f;

    // --- staging with register prefetch (x, q, weights) --------------------
    float4 pxv[4], pqv[4];
    uint4 wv[3];
    const int wrow = tid >> 2;
    const int wseg = tid & 3;

    auto load_xq = [&](int k0) {
        #pragma unroll
        for (int it = 0; it < 4; ++it) {
            int j = tid + it * 256;
            int m = j >> 3, kq = j & 7;
            int tg = rev ? (TT - 1 - (tbase + m)) : (tbase + m);
            pxv[it] = *(const float4*)(x + (size_t)tg * DD + k0 + kq * 4);
            pqv[it] = *(const float4*)(qp + (size_t)tg * qstride + k0 + kq * 4);
        }
    };
    auto load_W = [&](int k0) {
        #pragma unroll
        for (int m3 = 0; m3 < 3; ++m3)
            if (m3 < np)
                wv[m3] = *(const uint4*)(w3[m3] + (size_t)(nbase + wrow) * DD + k0 + wseg * 8);
    };
    auto stage_A = [&](int buf) {
        char* base = smem + buf * BUFSZ;
        #pragma unroll
        for (int it = 0; it < 4; ++it) {
            int j = tid + it * 256;
            int m = j >> 3, kq = j & 7;
            int off = m * ROWB + kq * 8;
            float4 xv = pxv[it], qv = pqv[it];
            float4 uv = make_float4(xv.x * qv.x, xv.y * qv.y, xv.z * qv.z, xv.w * qv.w);
            h_store(uv, base + 0 * A_TILE + off);
            h_store(xv, base + 1 * A_TILE + off);
            if (use_q) h_store(qv, base + 2 * A_TILE + off);
        }
    };
    auto store_W = [&](int buf) {
        char* base = smem + buf * BUFSZ + 3 * A_TILE;
        #pragma unroll
        for (int m3 = 0; m3 < 3; ++m3)
            if (m3 < np)
                *(uint4*)(base + m3 * B_TILE + wrow * ROWB + wseg * 16) = wv[m3];
    };

    load_xq(0);
    load_W(0);
    stage_A(0);
    store_W(0);
    __syncthreads();

    const int r = lane & 7, g = lane >> 3;
    #pragma unroll 1
    for (int c = 0; c < NCHUNK; ++c) {
        if (c < NCHUNK - 1) {
            load_xq((c + 1) * KC);
            load_W((c + 1) * KC);
        }

        const uint32_t abuf = sb + (c & 1) * BUFSZ;
        const uint32_t bbuf = abuf + 3 * A_TILE;

        #pragma unroll
        for (int ks = 0; ks < 2; ++ks) {
            const uint32_t kso = ks * 32;
            uint32_t af[3][2][4];
            #pragma unroll
            for (int o = 0; o < 3; ++o)
                if (o < np) {
                    #pragma unroll
                    for (int mt = 0; mt < 2; ++mt) {
                        uint32_t addr = abuf + o * A_TILE
                            + (wm * 32 + mt * 16 + (g & 1) * 8 + r) * ROWB
                            + (g >> 1) * 16 + kso;
                        ldsm4(addr, af[o][mt]);
                    }
                }
            uint32_t bf[3][4][2];
            #pragma unroll
            for (int m3 = 0; m3 < 3; ++m3)
                if (m3 < np) {
                    #pragma unroll
                    for (int j = 0; j < 2; ++j) {
                        uint32_t tmp[4];
                        uint32_t addr = bbuf + m3 * B_TILE
                            + (wn * 32 + (2 * j + (g >> 1)) * 8 + r) * ROWB
                            + (g & 1) * 16 + kso;
                        ldsm4(addr, tmp);
                        bf[m3][2 * j][0] = tmp[0]; bf[m3][2 * j][1] = tmp[1];
                        bf[m3][2 * j + 1][0] = tmp[2]; bf[m3][2 * j + 1][1] = tmp[3];
                    }
                }
            #pragma unroll
            for (int mt = 0; mt < 2; ++mt)
                #pragma unroll
                for (int nt = 0; nt < 4; ++nt) {
                    mma16816(acc[0][mt][nt], af[0][mt], bf[0][nt]);   // U @ Wz
                    mma16816(acc[1][mt][nt], af[1][mt], bf[1][nt]);   // X @ Whx
                    if (use_q)
                        mma16816(acc[1][mt][nt], af[2][mt], bf[2][nt]); // Q @ Whq
                }
        }
        if (c < NCHUNK - 1) {
            stage_A((c + 1) & 1);
            store_W((c + 1) & 1);
        }
        __syncthreads();
    }

    // --- epilogue: activations -> smem transpose ---------------------------
    float* smA = (float*)smem;              // [128][68]
    float* smB = smA + 128 * 68;
    #pragma unroll
    for (int mt = 0; mt < 2; ++mt)
        #pragma unroll
        for (int nt = 0; nt < 4; ++nt) {
            int col = wn * 32 + nt * 8 + 2 * (lane & 3);
            int row0 = wm * 32 + mt * 16 + (lane >> 2);
            #pragma unroll
            for (int h8 = 0; h8 < 2; ++h8) {
                int row = row0 + h8 * 8;
                float z0 = 0.5f * tanh_fast(0.5f * (acc[0][mt][nt][2*h8+0] + bzs[col]))   + 0.5f;
                float z1 = 0.5f * tanh_fast(0.5f * (acc[0][mt][nt][2*h8+1] + bzs[col+1])) + 0.5f;
                float t0 = tanh_fast(acc[1][mt][nt][2*h8+0] + bhs[col]);
                float t1 = tanh_fast(acc[1][mt][nt][2*h8+1] + bhs[col+1]);
                *(float2*)(smA + row * 68 + col) = make_float2(1.f - z0, 1.f - z1);
                *(float2*)(smB + row * 68 + col) = make_float2(z0 * t0, z1 * t1);
            }
        }
    __syncthreads();

    // --- fused block-local scan over 128 rows (4 segments x 32) ------------
    float* segA = (float*)(smem + SM_SEG);        // [4][64]
    float* segB = segA + 4 * 64;
    {
        const int col = tid & 63;
        const int sg = tid >> 6;
        const int rbase = sg * 32;
        float Ap = 1.f, hl = 0.f;
        #pragma unroll 8
        for (int i = 0; i < 32; ++i) {
            int off = (rbase + i) * 68 + col;
            float a = smA[off], b = smB[off];
            Ap *= a;
            hl = fmaf(a, hl, b);
            if (do_store) { smA[off] = Ap; smB[off] = hl; }
        }
        segA[sg * 64 + col] = Ap;
        segB[sg * 64 + col] = hl;
        __syncthreads();
        float Ain = 1.f, Hin = 0.f;
        #pragma unroll
        for (int s = 0; s < 3; ++s)
            if (s < sg) {
                float sa = segA[s * 64 + col], sbv = segB[s * 64 + col];
                Ain *= sa;
                Hin = fmaf(sa, Hin, sbv);
            }
        if (do_store) {
            #pragma unroll 8
            for (int i = 0; i < 32; ++i) {
                int off = (rbase + i) * 68 + col;
                float Al = smA[off], Bl = smB[off];
                smA[off] = Ain * Al;
                smB[off] = fmaf(Al, Hin, Bl);
            }
        }
        if (sg == 3) {
            aggA[(size_t)mblk * DD + nbase + col] = Ain * Ap;
            aggB[(size_t)mblk * DD + nbase + col] = fmaf(Ap, Hin, hl);
        }
    }

    if (do_store) {
        __syncthreads();
        #pragma unroll
        for (int it = 0; it < 8; ++it) {
            int j = tid + it * 256;
            int row = j >> 4, cf = j & 15;
            size_t go = (size_t)(tbase + row) * DD + nbase + cf * 4;
            *(float4*)(outA + go) = *(const float4*)(smA + row * 68 + cf * 4);
            *(float4*)(outB + go) = *(const float4*)(smB + row * 68 + cf * 4);
        }
    }
}

// ---------------------------------------------------------------------------
// scan2a: per super-block (16 blocks) local scan. grid (NSUP, ndirs).
// ---------------------------------------------------------------------------
__global__ void scan2a_kernel(
    const float* __restrict__ aggAf, const float* __restrict__ aggBf,
    float* __restrict__ hexf, float* __restrict__ apref,
    float* __restrict__ supAf, float* __restrict__ supBf,
    const float* __restrict__ aggAb, const float* __restrict__ aggBb,
    float* __restrict__ hexb, float* __restrict__ apreb,
    float* __restrict__ supAb, float* __restrict__ supBb)
{
    const int dirb = blockIdx.y;
    const float* aggA = dirb ? aggAb : aggAf;
    const float* aggB = dirb ? aggBb : aggBf;
    float* hex  = dirb ? hexb : hexf;
    float* apre = dirb ? apreb : apref;
    float* supA = dirb ? supAb : supAf;
    float* supB = dirb ? supBb : supBf;

    const int s = blockIdx.x, d = threadIdx.x;
    float a[SBLK], b[SBLK];
    #pragma unroll
    for (int i = 0; i < SBLK; ++i) {
        size_t o = (size_t)(s * SBLK + i) * DD + d;
        a[i] = aggA[o];
        b[i] = aggB[o];
    }
    float H = 0.f, A = 1.f;
    #pragma unroll
    for (int i = 0; i < SBLK; ++i) {
        size_t o = (size_t)(s * SBLK + i) * DD + d;
        hex[o] = H;
        apre[o] = A;
        H = fmaf(a[i], H, b[i]);
        A *= a[i];
    }
    supA[(size_t)s * DD + d] = A;
    supB[(size_t)s * DD + d] = H;
}

// ---------------------------------------------------------------------------
// scan2b: scan over NSUP super-aggregates; optional final-state output.
// ---------------------------------------------------------------------------
__global__ void scan2b_kernel(
    const float* __restrict__ supAf, const float* __restrict__ supBf,
    float* __restrict__ hsupf,
    const float* __restrict__ supAb, const float* __restrict__ supBb,
    float* __restrict__ hsupb,
    float* __restrict__ out)
{
    const int dirb = blockIdx.x;
    const float* supA = dirb ? supAb : supAf;
    const float* supB = dirb ? supBb : supBf;
    float* hsup = dirb ? hsupb : hsupf;
    const int d = threadIdx.x;

    float a[NSUP / 2], b[NSUP / 2];
    float H = 0.f;
    #pragma unroll
    for (int half = 0; half < 2; ++half) {
        #pragma unroll
        for (int i = 0; i < NSUP / 2; ++i) {
            size_t o = (size_t)(half * (NSUP / 2) + i) * DD + d;
            a[i] = supA[o];
            b[i] = supB[o];
        }
        #pragma unroll
        for (int i = 0; i < NSUP / 2; ++i) {
            hsup[(size_t)(half * (NSUP / 2) + i) * DD + d] = H;
            H = fmaf(a[i], H, b[i]);
        }
    }
    if (out && dirb == 0) out[d] = H;
}

// ---------------------------------------------------------------------------
// scan2c: hex[b] = APre[b] * Hsup[b/16] + hexL[b]  (in place). grid(128, 2).
// ---------------------------------------------------------------------------
__global__ void scan2c_kernel(
    float* __restrict__ hexf, const float* __restrict__ apref,
    const float* __restrict__ hsupf,
    float* __restrict__ hexb, const float* __restrict__ apreb,
    const float* __restrict__ hsupb)
{
    const int dirb = blockIdx.y;
    float* hex = dirb ? hexb : hexf;
    const float* apre = dirb ? apreb : apref;
    const float* hsup = dirb ? hsupb : hsupf;

    int idx = blockIdx.x * 256 + threadIdx.x;
    int bblk = idx >> 6;
    int c = (idx & 63) << 2;
    int sup = bblk >> 4;

    float4 ap = *(const float4*)(apre + (size_t)bblk * DD + c);
    float4 hs = *(const float4*)(hsup + (size_t)sup * DD + c);
    float4 hx = *(const float4*)(hex + (size_t)bblk * DD + c);
    hx.x = fmaf(ap.x, hs.x, hx.x);
    hx.y = fmaf(ap.y, hs.y, hx.y);
    hx.z = fmaf(ap.z, hs.z, hx.z);
    hx.w = fmaf(ap.w, hs.w, hx.w);
    *(float4*)(hex + (size_t)bblk * DD + c) = hx;
}

// ---------------------------------------------------------------------------
// combine: q = h_fwd + h_bwd_rev (cross-block fixup on the fly) -> fp32 qout.
// ---------------------------------------------------------------------------
__global__ void combine_kernel(
    const float* __restrict__ Af, const float* __restrict__ Bf,
    const float* __restrict__ hexf,
    const float* __restrict__ Ab, const float* __restrict__ Bb,
    const float* __restrict__ hexb,
    float* __restrict__ qout)
{
    int idx = blockIdx.x * blockDim.x + threadIdx.x;
    int t = idx >> 6;
    int c = (idx & 63) << 2;
    int tr = TT - 1 - t;
    int blf = t >> 7;
    int blb = tr >> 7;

    float4 af = *(const float4*)(Af + (size_t)t * DD + c);
    float4 bfv = *(const float4*)(Bf + (size_t)t * DD + c);
    float4 hf = *(const float4*)(hexf + (size_t)blf * DD + c);
    float4 ab = *(const float4*)(Ab + (size_t)tr * DD + c);
    float4 bb = *(const float4*)(Bb + (size_t)tr * DD + c);
    float4 hb = *(const float4*)(hexb + (size_t)blb * DD + c);

    float4 q4;
    q4.x = fmaf(af.x, hf.x, bfv.x) + fmaf(ab.x, hb.x, bb.x);
    q4.y = fmaf(af.y, hf.y, bfv.y) + fmaf(ab.y, hb.y, bb.y);
    q4.z = fmaf(af.z, hf.z, bfv.z) + fmaf(ab.z, hb.z, bb.z);
    q4.w = fmaf(af.w, hf.w, bfv.w) + fmaf(ab.w, hb.w, bb.w);

    *(float4*)(qout + (size_t)t * DD + c) = q4;
}

// ---------------------------------------------------------------------------
// Host orchestration
// ---------------------------------------------------------------------------
extern "C" void kernel_launch(void* const* d_in, const int* in_sizes, int n_in,
                              void* d_out, int out_size)
{
    const float* story    = (const float*)d_in[0];
    const float* question = (const float*)d_in[1];
    const float* Wz_f = (const float*)d_in[2];
    const float* bz_f = (const float*)d_in[3];
    const float* Wh_f = (const float*)d_in[4];
    const float* bh_f = (const float*)d_in[5];
    const float* Wz_b = (const float*)d_in[6];
    const float* bz_b = (const float*)d_in[7];
    const float* Wh_b = (const float*)d_in[8];
    const float* bh_b = (const float*)d_in[9];
    float* out = (float*)d_out;

    float *qbuf, *af, *bf, *ab, *bb;
    float *aggAf, *aggBf, *hexf, *apref, *aggAb, *aggBb, *hexb, *apreb;
    float *supAf, *supBf, *hsupf, *supAb, *supBb, *hsupb, *bheff;
    __half *wh16;
    cudaGetSymbolAddress((void**)&qbuf,  g_q);
    cudaGetSymbolAddress((void**)&af,    g_af);
    cudaGetSymbolAddress((void**)&bf,    g_bf);
    cudaGetSymbolAddress((void**)&ab,    g_ab);
    cudaGetSymbolAddress((void**)&bb,    g_bb);
    cudaGetSymbolAddress((void**)&aggAf, g_aggA_f);
    cudaGetSymbolAddress((void**)&aggBf, g_aggB_f);
    cudaGetSymbolAddress((void**)&hexf,  g_hex_f);
    cudaGetSymbolAddress((void**)&apref, g_apre_f);
    cudaGetSymbolAddress((void**)&aggAb, g_aggA_b);
    cudaGetSymbolAddress((void**)&aggBb, g_aggB_b);
    cudaGetSymbolAddress((void**)&hexb,  g_hex_b);
    cudaGetSymbolAddress((void**)&apreb, g_apre_b);
    cudaGetSymbolAddress((void**)&supAf, g_supA_f);
    cudaGetSymbolAddress((void**)&supBf, g_supB_f);
    cudaGetSymbolAddress((void**)&hsupf, g_hsup_f);
    cudaGetSymbolAddress((void**)&supAb, g_supA_b);
    cudaGetSymbolAddress((void**)&supBb, g_supB_b);
    cudaGetSymbolAddress((void**)&hsupb, g_hsup_b);
    cudaGetSymbolAddress((void**)&wh16,  g_wh16);
    cudaGetSymbolAddress((void**)&bheff, g_bheff);

    static int smem_set = 0;
    if (!smem_set) {
        cudaFuncSetAttribute(gemm_mma, cudaFuncAttributeMaxDynamicSharedMemorySize,
                             SMEM_TOTAL);
        smem_set = 1;
    }

    prep_all<<<dim3(DD, 3, 6), 256>>>(Wz_f, Wh_f, Wz_b, Wh_b,
                                      question, bh_f, bh_b, wh16, bheff);

    const int MSZ = 3 * DD * DD;

    for (int l = 0; l < LL; ++l) {
        const int uq = (l == 0) ? 0 : 1;
        const float* qp = (l == 0) ? question : qbuf;
        const int qstride = (l == 0) ? 0 : DD;
        const float* bhf_eff = (l == 0) ? bheff : bh_f + l * DD;
        const float* bhb_eff = (l == 0) ? bheff + DD : bh_b + l * DD;

        if (l < LL - 1) {
            dim3 ggrid(DD / BN, TT / BM, 2);
            gemm_mma<<<ggrid, 256, SMEM_TOTAL>>>(
                story, qp, qstride, uq, 1,
                wh16 + l * MSZ, wh16 + (3 + l) * MSZ,
                bz_f + l * DD, bhf_eff, bz_b + l * DD, bhb_eff,
                af, bf, aggAf, aggBf, ab, bb, aggAb, aggBb);

            scan2a_kernel<<<dim3(NSUP, 2), 256>>>(
                aggAf, aggBf, hexf, apref, supAf, supBf,
                aggAb, aggBb, hexb, apreb, supAb, supBb);
            scan2b_kernel<<<2, 256>>>(supAf, supBf, hsupf,
                                      supAb, supBb, hsupb, nullptr);
            scan2c_kernel<<<dim3(NB * DD / 4 / 256, 2), 256>>>(
                hexf, apref, hsupf, hexb, apreb, hsupb);

            combine_kernel<<<TT * DD / 4 / 256, 256>>>(
                af, bf, hexf, ab, bb, hexb, qbuf);
        } else {
            dim3 ggrid(DD / BN, TT / BM, 1);
            gemm_mma<<<ggrid, 256, SMEM_TOTAL>>>(
                story, qp, qstride, uq, 0,
                wh16 + l * MSZ, wh16 + l * MSZ,
                bz_f + l * DD, bhf_eff, bz_f + l * DD, bhf_eff,
                af, bf, aggAf, aggBf, af, bf, aggAf, aggBf);
            scan2a_kernel<<<dim3(NSUP, 1), 256>>>(
                aggAf, aggBf, hexf, apref, supAf, supBf,
                aggAb, aggBb, hexb, apreb, supAb, supBb);
            scan2b_kernel<<<1, 256>>>(supAf, supBf, hsupf,
                                      supAb, supBb, hsupb, out);
        }
    }
}

// round 14
// speedup vs baseline: 2.5315x; 1.0962x over previous
#include <cuda_runtime.h>
#include <cuda_bf16.h>
#include <cuda_fp16.h>
#include <stdint.h>
#include <math.h>

// Problem constants
#define TT 65536
#define DD 256
#define LL 3

// GEMM tiling (BM=128, BN=64, KC=32), fp16 single-plane operands
#define BM 128
#define BN 64
#define KC 32
#define NCHUNK (DD / KC)   // 8

#define ROWB 80                     // padded smem row stride (bytes)
#define A_TILE (128 * ROWB)         // 10240 B
#define B_TILE (64 * ROWB)          // 5120 B
#define BUFSZ  (3 * A_TILE + 3 * B_TILE)  // 46080 B
#define SM_BIAS (2 * BUFSZ)         // 92160
#define SMEM_TOTAL (SM_BIAS + 512 + 64)   // 92736 -> 2 CTAs/SM fit
#define SM_SEG (2 * 128 * 68 * 4)   // 69632 (epilogue seg aggregates)

// Scan blocking
#define CS 128
#define NB (TT / CS)   // 512
#define SBLK 16
#define NSUP (NB / SBLK)  // 32

// ---------------------------------------------------------------------------
// Scratch
// ---------------------------------------------------------------------------
__device__ __align__(256) float g_q[TT * DD];
__device__ __align__(256) float g_af[TT * DD];
__device__ __align__(256) float g_bf[TT * DD];
__device__ __align__(256) float g_ab[TT * DD];
__device__ __align__(256) float g_bb[TT * DD];
__device__ __align__(256) float g_aggA_f[NB * DD];
__device__ __align__(256) float g_aggB_f[NB * DD];
__device__ __align__(256) float g_hex_f[NB * DD];
__device__ __align__(256) float g_apre_f[NB * DD];
__device__ __align__(256) float g_aggA_b[NB * DD];
__device__ __align__(256) float g_aggB_b[NB * DD];
__device__ __align__(256) float g_hex_b[NB * DD];
__device__ __align__(256) float g_apre_b[NB * DD];
__device__ __align__(256) float g_supA_f[NSUP * DD];
__device__ __align__(256) float g_supB_f[NSUP * DD];
__device__ __align__(256) float g_hsup_f[NSUP * DD];
__device__ __align__(256) float g_supA_b[NSUP * DD];
__device__ __align__(256) float g_supB_b[NSUP * DD];
__device__ __align__(256) float g_hsup_b[NSUP * DD];
// fp16 pre-transposed weights: [5 layer-dirs][3 mats][256 n][256 k]
__device__ __align__(256) __half g_wh16[5 * 3 * DD * DD];
__device__ __align__(256) float g_bheff[2 * DD];

__device__ __forceinline__ float tanh_fast(float v) {
    float r;
    asm("tanh.approx.f32 %0, %1;" : "=f"(r) : "f"(v));
    return r;
}
__device__ __forceinline__ uint32_t smem_u32(const void* p) {
    uint32_t a;
    asm("{ .reg .u64 t; cvta.to.shared.u64 t, %1; cvt.u32.u64 %0, t; }"
        : "=r"(a) : "l"(p));
    return a;
}
__device__ __forceinline__ void ldsm4(uint32_t addr, uint32_t* r) {
    asm volatile("ldmatrix.sync.aligned.m8n8.x4.shared.b16 {%0,%1,%2,%3}, [%4];"
                 : "=r"(r[0]), "=r"(r[1]), "=r"(r[2]), "=r"(r[3]) : "r"(addr));
}
__device__ __forceinline__ void mma16816(float* c, const uint32_t* a,
                                         const uint32_t* b) {
    asm volatile(
        "mma.sync.aligned.m16n8k16.row.col.f32.f16.f16.f32 "
        "{%0,%1,%2,%3}, {%4,%5,%6,%7}, {%8,%9}, {%0,%1,%2,%3};"
        : "+f"(c[0]), "+f"(c[1]), "+f"(c[2]), "+f"(c[3])
        : "r"(a[0]), "r"(a[1]), "r"(a[2]), "r"(a[3]), "r"(b[0]), "r"(b[1]));
}
// L1-allocating 16B async copy (no register staging)
__device__ __forceinline__ void cpa16(uint32_t dst, const void* src) {
    asm volatile("cp.async.ca.shared.global [%0], [%1], 16;"
                 :: "r"(dst), "l"(src) : "memory");
}

// fp16 convert+store of a float4 (one 8B store)
__device__ __forceinline__ void h_store(float4 v, char* dst) {
    __half2 p0 = __floats2half2_rn(v.x, v.y);
    __half2 p1 = __floats2half2_rn(v.z, v.w);
    uint2 P;
    P.x = *(uint32_t*)&p0;
    P.y = *(uint32_t*)&p1;
    *(uint2*)dst = P;
}

// ---------------------------------------------------------------------------
// prep_all: z-slots 0..4 = weight transpose to fp16 [n][k]; z-slot 5 =
// layer-0 effective h-bias (bh + Whq^T q0) for both directions.
// ---------------------------------------------------------------------------
__global__ void prep_all(const float* __restrict__ Wz_f, const float* __restrict__ Wh_f,
                         const float* __restrict__ Wz_b, const float* __restrict__ Wh_b,
                         const float* __restrict__ question,
                         const float* __restrict__ bh_f, const float* __restrict__ bh_b,
                         __half* __restrict__ wh16, float* __restrict__ bheff)
{
    int n = blockIdx.x, m = blockIdx.y, s = blockIdx.z, k = threadIdx.x;
    if (s == 5) {
        if (m >= 2) return;
        __shared__ float red[256];
        const float* Wh = m ? Wh_b : Wh_f;
        const float* bh = m ? bh_b : bh_f;
        red[k] = question[k] * Wh[(DD + k) * DD + n];
        __syncthreads();
        for (int st = 128; st > 0; st >>= 1) {
            if (k < st) red[k] += red[k + st];
            __syncthreads();
        }
        if (k == 0) bheff[m * DD + n] = bh[n] + red[0];
        return;
    }
    const float* Wz;
    const float* Wh;
    if (s < 3) { Wz = Wz_f + s * DD * DD; Wh = Wh_f + s * 2 * DD * DD; }
    else       { Wz = Wz_b + (s - 3) * DD * DD; Wh = Wh_b + (s - 3) * 2 * DD * DD; }
    float v = (m == 0) ? Wz[k * DD + n]
            : (m == 1) ? Wh[k * DD + n]
                       : Wh[(DD + k) * DD + n];
    wh16[(size_t)(s * 3 + m) * DD * DD + (size_t)n * DD + k] = __float2half_rn(v);
}

// ---------------------------------------------------------------------------
// Fused GEMM (fp16 mma.sync) + activation + block-local scan.
// blockIdx.z = direction. 2 CTAs/SM (register-dieted staging: weights via
// cp.async.ca, x/q via transient load->cvt->store; no persistent prefetch).
// ---------------------------------------------------------------------------
__global__ void __launch_bounds__(256, 2) gemm_mma(
    const float* __restrict__ x, const float* __restrict__ qp, int qstride,
    int use_q, int do_store,
    const __half* __restrict__ wh_f, const __half* __restrict__ wh_b,
    const float* __restrict__ bz_f, const float* __restrict__ bh_f,
    const float* __restrict__ bz_b, const float* __restrict__ bh_b,
    float* __restrict__ outA_f, float* __restrict__ outB_f,
    float* __restrict__ aggA_f, float* __restrict__ aggB_f,
    float* __restrict__ outA_b, float* __restrict__ outB_b,
    float* __restrict__ aggA_b, float* __restrict__ aggB_b)
{
    extern __shared__ char smem[];
    const int tid = threadIdx.x;
    const int wid = tid >> 5;
    const int lane = tid & 31;
    const int wm = wid & 3;
    const int wn = wid >> 2;
    const int nbase = blockIdx.x * BN;      // N fastest -> x/q L2 reuse
    const int tbase = blockIdx.y * BM;
    const int mblk  = blockIdx.y;
    const int rev   = blockIdx.z;
    const uint32_t sb = smem_u32(smem);

    const __half* wh = rev ? wh_b : wh_f;
    const float* bz = rev ? bz_b : bz_f;
    const float* bh = rev ? bh_b : bh_f;
    float* outA = rev ? outA_b : outA_f;
    float* outB = rev ? outB_b : outB_f;
    float* aggA = rev ? aggA_b : aggA_f;
    float* aggB = rev ? aggB_b : aggB_f;

    float* bzs = (float*)(smem + SM_BIAS);
    float* bhs = bzs + 64;
    if (tid < 64) {
        bzs[tid] = bz[nbase + tid];
        bhs[tid] = bh[nbase + tid];
    }

    const __half* w3[3] = { wh, wh + DD * DD, wh + 2 * DD * DD };  // Wz, Whx, Whq
    const int np = use_q ? 3 : 2;

    float acc[2][2][4][4];
    #pragma unroll
    for (int zh = 0; zh < 2; ++zh)
        #pragma unroll
        for (int mt = 0; mt < 2; ++mt)
            #pragma unroll
            for (int nt = 0; nt < 4; ++nt)
                #pragma unroll
                for (int j = 0; j < 4; ++j) acc[zh][mt][nt][j] = 0.f;

    // --- register-free staging --------------------------------------------
    const int wrow = tid >> 2;
    const int wseg = tid & 3;

    // weights: gmem -> smem via cp.async (zero registers)
    auto stage_W = [&](int k0, int buf) {
        uint32_t base = sb + buf * BUFSZ + 3 * A_TILE;
        #pragma unroll
        for (int m3 = 0; m3 < 3; ++m3)
            if (m3 < np)
                cpa16(base + m3 * B_TILE + wrow * ROWB + wseg * 16,
                      w3[m3] + (size_t)(nbase + wrow) * DD + k0 + wseg * 8);
    };
    // x/q: transient load -> u compute -> fp16 convert -> store
    auto stage_A = [&](int k0, int buf) {
        char* base = smem + buf * BUFSZ;
        #pragma unroll
        for (int it = 0; it < 4; ++it) {
            int j = tid + it * 256;
            int m = j >> 3, kq = j & 7;
            int tg = rev ? (TT - 1 - (tbase + m)) : (tbase + m);
            float4 xv = *(const float4*)(x + (size_t)tg * DD + k0 + kq * 4);
            float4 qv = *(const float4*)(qp + (size_t)tg * qstride + k0 + kq * 4);
            float4 uv = make_float4(xv.x * qv.x, xv.y * qv.y, xv.z * qv.z, xv.w * qv.w);
            int off = m * ROWB + kq * 8;
            h_store(uv, base + 0 * A_TILE + off);
            h_store(xv, base + 1 * A_TILE + off);
            if (use_q) h_store(qv, base + 2 * A_TILE + off);
        }
    };

    stage_W(0, 0);
    stage_A(0, 0);
    asm volatile("cp.async.commit_group;" ::: "memory");
    asm volatile("cp.async.wait_group 0;" ::: "memory");
    __syncthreads();

    const int r = lane & 7, g = lane >> 3;
    #pragma unroll 1
    for (int c = 0; c < NCHUNK; ++c) {
        const uint32_t abuf = sb + (c & 1) * BUFSZ;
        const uint32_t bbuf = abuf + 3 * A_TILE;

        // kick off next chunk's weight cp.asyncs before the MMA block
        if (c < NCHUNK - 1)
            stage_W((c + 1) * KC, (c + 1) & 1);

        #pragma unroll
        for (int ks = 0; ks < 2; ++ks) {
            const uint32_t kso = ks * 32;
            uint32_t af[3][2][4];
            #pragma unroll
            for (int o = 0; o < 3; ++o)
                if (o < np) {
                    #pragma unroll
                    for (int mt = 0; mt < 2; ++mt) {
                        uint32_t addr = abuf + o * A_TILE
                            + (wm * 32 + mt * 16 + (g & 1) * 8 + r) * ROWB
                            + (g >> 1) * 16 + kso;
                        ldsm4(addr, af[o][mt]);
                    }
                }
            uint32_t bf[3][4][2];
            #pragma unroll
            for (int m3 = 0; m3 < 3; ++m3)
                if (m3 < np) {
                    #pragma unroll
                    for (int j = 0; j < 2; ++j) {
                        uint32_t tmp[4];
                        uint32_t addr = bbuf + m3 * B_TILE
                            + (wn * 32 + (2 * j + (g >> 1)) * 8 + r) * ROWB
                            + (g & 1) * 16 + kso;
                        ldsm4(addr, tmp);
                        bf[m3][2 * j][0] = tmp[0]; bf[m3][2 * j][1] = tmp[1];
                        bf[m3][2 * j + 1][0] = tmp[2]; bf[m3][2 * j + 1][1] = tmp[3];
                    }
                }
            #pragma unroll
            for (int mt = 0; mt < 2; ++mt)
                #pragma unroll
                for (int nt = 0; nt < 4; ++nt) {
                    mma16816(acc[0][mt][nt], af[0][mt], bf[0][nt]);   // U @ Wz
                    mma16816(acc[1][mt][nt], af[1][mt], bf[1][nt]);   // X @ Whx
                    if (use_q)
                        mma16816(acc[1][mt][nt], af[2][mt], bf[2][nt]); // Q @ Whq
                }
        }
        if (c < NCHUNK - 1) {
            stage_A((c + 1) * KC, (c + 1) & 1);  // LDGs hoist above MMAs
            asm volatile("cp.async.commit_group;" ::: "memory");
            asm volatile("cp.async.wait_group 0;" ::: "memory");
        }
        __syncthreads();
    }

    // --- epilogue: activations -> smem transpose ---------------------------
    float* smA = (float*)smem;              // [128][68]
    float* smB = smA + 128 * 68;
    #pragma unroll
    for (int mt = 0; mt < 2; ++mt)
        #pragma unroll
        for (int nt = 0; nt < 4; ++nt) {
            int col = wn * 32 + nt * 8 + 2 * (lane & 3);
            int row0 = wm * 32 + mt * 16 + (lane >> 2);
            #pragma unroll
            for (int h8 = 0; h8 < 2; ++h8) {
                int row = row0 + h8 * 8;
                float z0 = 0.5f * tanh_fast(0.5f * (acc[0][mt][nt][2*h8+0] + bzs[col]))   + 0.5f;
                float z1 = 0.5f * tanh_fast(0.5f * (acc[0][mt][nt][2*h8+1] + bzs[col+1])) + 0.5f;
                float t0 = tanh_fast(acc[1][mt][nt][2*h8+0] + bhs[col]);
                float t1 = tanh_fast(acc[1][mt][nt][2*h8+1] + bhs[col+1]);
                *(float2*)(smA + row * 68 + col) = make_float2(1.f - z0, 1.f - z1);
                *(float2*)(smB + row * 68 + col) = make_float2(z0 * t0, z1 * t1);
            }
        }
    __syncthreads();

    // --- fused block-local scan over 128 rows (4 segments x 32) ------------
    float* segA = (float*)(smem + SM_SEG);        // [4][64]
    float* segB = segA + 4 * 64;
    {
        const int col = tid & 63;
        const int sg = tid >> 6;
        const int rbase = sg * 32;
        float Ap = 1.f, hl = 0.f;
        #pragma unroll 8
        for (int i = 0; i < 32; ++i) {
            int off = (rbase + i) * 68 + col;
            float a = smA[off], b = smB[off];
            Ap *= a;
            hl = fmaf(a, hl, b);
            if (do_store) { smA[off] = Ap; smB[off] = hl; }
        }
        segA[sg * 64 + col] = Ap;
        segB[sg * 64 + col] = hl;
        __syncthreads();
        float Ain = 1.f, Hin = 0.f;
        #pragma unroll
        for (int s = 0; s < 3; ++s)
            if (s < sg) {
                float sa = segA[s * 64 + col], sbv = segB[s * 64 + col];
                Ain *= sa;
                Hin = fmaf(sa, Hin, sbv);
            }
        if (do_store) {
            #pragma unroll 8
            for (int i = 0; i < 32; ++i) {
                int off = (rbase + i) * 68 + col;
                float Al = smA[off], Bl = smB[off];
                smA[off] = Ain * Al;
                smB[off] = fmaf(Al, Hin, Bl);
            }
        }
        if (sg == 3) {
            aggA[(size_t)mblk * DD + nbase + col] = Ain * Ap;
            aggB[(size_t)mblk * DD + nbase + col] = fmaf(Ap, Hin, hl);
        }
    }

    if (do_store) {
        __syncthreads();
        #pragma unroll
        for (int it = 0; it < 8; ++it) {
            int j = tid + it * 256;
            int row = j >> 4, cf = j & 15;
            size_t go = (size_t)(tbase + row) * DD + nbase + cf * 4;
            *(float4*)(outA + go) = *(const float4*)(smA + row * 68 + cf * 4);
            *(float4*)(outB + go) = *(const float4*)(smB + row * 68 + cf * 4);
        }
    }
}

// ---------------------------------------------------------------------------
// scan2a: per super-block (16 blocks) local scan. grid (NSUP, ndirs).
// ---------------------------------------------------------------------------
__global__ void scan2a_kernel(
    const float* __restrict__ aggAf, const float* __restrict__ aggBf,
    float* __restrict__ hexf, float* __restrict__ apref,
    float* __restrict__ supAf, float* __restrict__ supBf,
    const float* __restrict__ aggAb, const float* __restrict__ aggBb,
    float* __restrict__ hexb, float* __restrict__ apreb,
    float* __restrict__ supAb, float* __restrict__ supBb)
{
    const int dirb = blockIdx.y;
    const float* aggA = dirb ? aggAb : aggAf;
    const float* aggB = dirb ? aggBb : aggBf;
    float* hex  = dirb ? hexb : hexf;
    float* apre = dirb ? apreb : apref;
    float* supA = dirb ? supAb : supAf;
    float* supB = dirb ? supBb : supBf;

    const int s = blockIdx.x, d = threadIdx.x;
    float a[SBLK], b[SBLK];
    #pragma unroll
    for (int i = 0; i < SBLK; ++i) {
        size_t o = (size_t)(s * SBLK + i) * DD + d;
        a[i] = aggA[o];
        b[i] = aggB[o];
    }
    float H = 0.f, A = 1.f;
    #pragma unroll
    for (int i = 0; i < SBLK; ++i) {
        size_t o = (size_t)(s * SBLK + i) * DD + d;
        hex[o] = H;
        apre[o] = A;
        H = fmaf(a[i], H, b[i]);
        A *= a[i];
    }
    supA[(size_t)s * DD + d] = A;
    supB[(size_t)s * DD + d] = H;
}

// ---------------------------------------------------------------------------
// scan2b: scan over NSUP super-aggregates; optional final-state output.
// ---------------------------------------------------------------------------
__global__ void scan2b_kernel(
    const float* __restrict__ supAf, const float* __restrict__ supBf,
    float* __restrict__ hsupf,
    const float* __restrict__ supAb, const float* __restrict__ supBb,
    float* __restrict__ hsupb,
    float* __restrict__ out)
{
    const int dirb = blockIdx.x;
    const float* supA = dirb ? supAb : supAf;
    const float* supB = dirb ? supBb : supBf;
    float* hsup = dirb ? hsupb : hsupf;
    const int d = threadIdx.x;

    float a[NSUP / 2], b[NSUP / 2];
    float H = 0.f;
    #pragma unroll
    for (int half = 0; half < 2; ++half) {
        #pragma unroll
        for (int i = 0; i < NSUP / 2; ++i) {
            size_t o = (size_t)(half * (NSUP / 2) + i) * DD + d;
            a[i] = supA[o];
            b[i] = supB[o];
        }
        #pragma unroll
        for (int i = 0; i < NSUP / 2; ++i) {
            hsup[(size_t)(half * (NSUP / 2) + i) * DD + d] = H;
            H = fmaf(a[i], H, b[i]);
        }
    }
    if (out && dirb == 0) out[d] = H;
}

// ---------------------------------------------------------------------------
// scan2c: hex[b] = APre[b] * Hsup[b/16] + hexL[b]  (in place). grid(128, 2).
// ---------------------------------------------------------------------------
__global__ void scan2c_kernel(
    float* __restrict__ hexf, const float* __restrict__ apref,
    const float* __restrict__ hsupf,
    float* __restrict__ hexb, const float* __restrict__ apreb,
    const float* __restrict__ hsupb)
{
    const int dirb = blockIdx.y;
    float* hex = dirb ? hexb : hexf;
    const float* apre = dirb ? apreb : apref;
    const float* hsup = dirb ? hsupb : hsupf;

    int idx = blockIdx.x * 256 + threadIdx.x;
    int bblk = idx >> 6;
    int c = (idx & 63) << 2;
    int sup = bblk >> 4;

    float4 ap = *(const float4*)(apre + (size_t)bblk * DD + c);
    float4 hs = *(const float4*)(hsup + (size_t)sup * DD + c);
    float4 hx = *(const float4*)(hex + (size_t)bblk * DD + c);
    hx.x = fmaf(ap.x, hs.x, hx.x);
    hx.y = fmaf(ap.y, hs.y, hx.y);
    hx.z = fmaf(ap.z, hs.z, hx.z);
    hx.w = fmaf(ap.w, hs.w, hx.w);
    *(float4*)(hex + (size_t)bblk * DD + c) = hx;
}

// ---------------------------------------------------------------------------
// combine: q = h_fwd + h_bwd_rev (cross-block fixup on the fly) -> fp32 qout.
// ---------------------------------------------------------------------------
__global__ void combine_kernel(
    const float* __restrict__ Af, const float* __restrict__ Bf,
    const float* __restrict__ hexf,
    const float* __restrict__ Ab, const float* __restrict__ Bb,
    const float* __restrict__ hexb,
    float* __restrict__ qout)
{
    int idx = blockIdx.x * blockDim.x + threadIdx.x;
    int t = idx >> 6;
    int c = (idx & 63) << 2;
    int tr = TT - 1 - t;
    int blf = t >> 7;
    int blb = tr >> 7;

    float4 af = *(const float4*)(Af + (size_t)t * DD + c);
    float4 bfv = *(const float4*)(Bf + (size_t)t * DD + c);
    float4 hf = *(const float4*)(hexf + (size_t)blf * DD + c);
    float4 ab = *(const float4*)(Ab + (size_t)tr * DD + c);
    float4 bb = *(const float4*)(Bb + (size_t)tr * DD + c);
    float4 hb = *(const float4*)(hexb + (size_t)blb * DD + c);

    float4 q4;
    q4.x = fmaf(af.x, hf.x, bfv.x) + fmaf(ab.x, hb.x, bb.x);
    q4.y = fmaf(af.y, hf.y, bfv.y) + fmaf(ab.y, hb.y, bb.y);
    q4.z = fmaf(af.z, hf.z, bfv.z) + fmaf(ab.z, hb.z, bb.z);
    q4.w = fmaf(af.w, hf.w, bfv.w) + fmaf(ab.w, hb.w, bb.w);

    *(float4*)(qout + (size_t)t * DD + c) = q4;
}

// ---------------------------------------------------------------------------
// Host orchestration
// ---------------------------------------------------------------------------
extern "C" void kernel_launch(void* const* d_in, const int* in_sizes, int n_in,
                              void* d_out, int out_size)
{
    const float* story    = (const float*)d_in[0];
    const float* question = (const float*)d_in[1];
    const float* Wz_f = (const float*)d_in[2];
    const float* bz_f = (const float*)d_in[3];
    const float* Wh_f = (const float*)d_in[4];
    const float* bh_f = (const float*)d_in[5];
    const float* Wz_b = (const float*)d_in[6];
    const float* bz_b = (const float*)d_in[7];
    const float* Wh_b = (const float*)d_in[8];
    const float* bh_b = (const float*)d_in[9];
    float* out = (float*)d_out;

    float *qbuf, *af, *bf, *ab, *bb;
    float *aggAf, *aggBf, *hexf, *apref, *aggAb, *aggBb, *hexb, *apreb;
    float *supAf, *supBf, *hsupf, *supAb, *supBb, *hsupb, *bheff;
    __half *wh16;
    cudaGetSymbolAddress((void**)&qbuf,  g_q);
    cudaGetSymbolAddress((void**)&af,    g_af);
    cudaGetSymbolAddress((void**)&bf,    g_bf);
    cudaGetSymbolAddress((void**)&ab,    g_ab);
    cudaGetSymbolAddress((void**)&bb,    g_bb);
    cudaGetSymbolAddress((void**)&aggAf, g_aggA_f);
    cudaGetSymbolAddress((void**)&aggBf, g_aggB_f);
    cudaGetSymbolAddress((void**)&hexf,  g_hex_f);
    cudaGetSymbolAddress((void**)&apref, g_apre_f);
    cudaGetSymbolAddress((void**)&aggAb, g_aggA_b);
    cudaGetSymbolAddress((void**)&aggBb, g_aggB_b);
    cudaGetSymbolAddress((void**)&hexb,  g_hex_b);
    cudaGetSymbolAddress((void**)&apreb, g_apre_b);
    cudaGetSymbolAddress((void**)&supAf, g_supA_f);
    cudaGetSymbolAddress((void**)&supBf, g_supB_f);
    cudaGetSymbolAddress((void**)&hsupf, g_hsup_f);
    cudaGetSymbolAddress((void**)&supAb, g_supA_b);
    cudaGetSymbolAddress((void**)&supBb, g_supB_b);
    cudaGetSymbolAddress((void**)&hsupb, g_hsup_b);
    cudaGetSymbolAddress((void**)&wh16,  g_wh16);
    cudaGetSymbolAddress((void**)&bheff, g_bheff);

    static int smem_set = 0;
    if (!smem_set) {
        cudaFuncSetAttribute(gemm_mma, cudaFuncAttributeMaxDynamicSharedMemorySize,
                             SMEM_TOTAL);
        smem_set = 1;
    }

    prep_all<<<dim3(DD, 3, 6), 256>>>(Wz_f, Wh_f, Wz_b, Wh_b,
                                      question, bh_f, bh_b, wh16, bheff);

    const int MSZ = 3 * DD * DD;

    for (int l = 0; l < LL; ++l) {
        const int uq = (l == 0) ? 0 : 1;
        const float* qp = (l == 0) ? question : qbuf;
        const int qstride = (l == 0) ? 0 : DD;
        const float* bhf_eff = (l == 0) ? bheff : bh_f + l * DD;
        const float* bhb_eff = (l == 0) ? bheff + DD : bh_b + l * DD;

        if (l < LL - 1) {
            dim3 ggrid(DD / BN, TT / BM, 2);
            gemm_mma<<<ggrid, 256, SMEM_TOTAL>>>(
                story, qp, qstride, uq, 1,
                wh16 + l * MSZ, wh16 + (3 + l) * MSZ,
                bz_f + l * DD, bhf_eff, bz_b + l * DD, bhb_eff,
                af, bf, aggAf, aggBf, ab, bb, aggAb, aggBb);

            scan2a_kernel<<<dim3(NSUP, 2), 256>>>(
                aggAf, aggBf, hexf, apref, supAf, supBf,
                aggAb, aggBb, hexb, apreb, supAb, supBb);
            scan2b_kernel<<<2, 256>>>(supAf, supBf, hsupf,
                                      supAb, supBb, hsupb, nullptr);
            scan2c_kernel<<<dim3(NB * DD / 4 / 256, 2), 256>>>(
                hexf, apref, hsupf, hexb, apreb, hsupb);

            combine_kernel<<<TT * DD / 4 / 256, 256>>>(
                af, bf, hexf, ab, bb, hexb, qbuf);
        } else {
            dim3 ggrid(DD / BN, TT / BM, 1);
            gemm_mma<<<ggrid, 256, SMEM_TOTAL>>>(
                story, qp, qstride, uq, 0,
                wh16 + l * MSZ, wh16 + l * MSZ,
                bz_f + l * DD, bhf_eff, bz_f + l * DD, bhf_eff,
                af, bf, aggAf, aggBf, af, bf, aggAf, aggBf);
            scan2a_kernel<<<dim3(NSUP, 1), 256>>>(
                aggAf, aggBf, hexf, apref, supAf, supBf,
                aggAb, aggBb, hexb, apreb, supAb, supBb);
            scan2b_kernel<<<1, 256>>>(supAf, supBf, hsupf,
                                      supAb, supBb, hsupb, out);
        }
    }
}

// round 15
// speedup vs baseline: 2.5694x; 1.0150x over previous
#include <cuda_runtime.h>
#include <cuda_bf16.h>
#include <cuda_fp16.h>
#include <stdint.h>
#include <math.h>

// Problem constants
#define TT 65536
#define DD 256
#define LL 3

// GEMM tiling (BM=128, BN=64, KC=32), fp16 single-plane operands
#define BM 128
#define BN 64
#define KC 32
#define NCHUNK (DD / KC)   // 8

#define ROWB 80                     // padded smem row stride (bytes)
#define A_TILE (128 * ROWB)         // 10240 B
#define B_TILE (64 * ROWB)          // 5120 B
#define BUFSZ  (3 * A_TILE + 3 * B_TILE)  // 46080 B
#define SM_BIAS (2 * BUFSZ)         // 92160
#define SMEM_TOTAL (SM_BIAS + 512 + 64)   // 92736 -> 2 CTAs/SM
#define SM_SEG (2 * 128 * 68 * 4)   // 69632 (epilogue seg aggregates)

// Scan blocking
#define CS 128
#define NB (TT / CS)   // 512
#define SBLK 16
#define NSUP (NB / SBLK)  // 32

// ---------------------------------------------------------------------------
// Scratch
// ---------------------------------------------------------------------------
__device__ __align__(256) float g_af[TT * DD];
__device__ __align__(256) float g_bf[TT * DD];
__device__ __align__(256) float g_ab[TT * DD];
__device__ __align__(256) float g_bb[TT * DD];
__device__ __align__(256) float g_aggA_f[NB * DD];
__device__ __align__(256) float g_aggB_f[NB * DD];
__device__ __align__(256) float g_hex_f[NB * DD];
__device__ __align__(256) float g_apre_f[NB * DD];
__device__ __align__(256) float g_aggA_b[NB * DD];
__device__ __align__(256) float g_aggB_b[NB * DD];
__device__ __align__(256) float g_hex_b[NB * DD];
__device__ __align__(256) float g_apre_b[NB * DD];
__device__ __align__(256) float g_supA_f[NSUP * DD];
__device__ __align__(256) float g_supB_f[NSUP * DD];
__device__ __align__(256) float g_hsup_f[NSUP * DD];
__device__ __align__(256) float g_supA_b[NSUP * DD];
__device__ __align__(256) float g_supB_b[NSUP * DD];
__device__ __align__(256) float g_hsup_b[NSUP * DD];
// fp16 A-operand planes (pre-staged)
__device__ __align__(256) __half g_uh[TT * DD];
__device__ __align__(256) __half g_xh[TT * DD];
__device__ __align__(256) __half g_qh[TT * DD];
// fp16 pre-transposed weights: [5 layer-dirs][3 mats][256 n][256 k]
__device__ __align__(256) __half g_wh16[5 * 3 * DD * DD];
__device__ __align__(256) float g_bheff[2 * DD];

__device__ __forceinline__ float tanh_fast(float v) {
    float r;
    asm("tanh.approx.f32 %0, %1;" : "=f"(r) : "f"(v));
    return r;
}
__device__ __forceinline__ uint32_t smem_u32(const void* p) {
    uint32_t a;
    asm("{ .reg .u64 t; cvta.to.shared.u64 t, %1; cvt.u32.u64 %0, t; }"
        : "=r"(a) : "l"(p));
    return a;
}
__device__ __forceinline__ void ldsm4(uint32_t addr, uint32_t* r) {
    asm volatile("ldmatrix.sync.aligned.m8n8.x4.shared.b16 {%0,%1,%2,%3}, [%4];"
                 : "=r"(r[0]), "=r"(r[1]), "=r"(r[2]), "=r"(r[3]) : "r"(addr));
}
__device__ __forceinline__ void mma16816(float* c, const uint32_t* a,
                                         const uint32_t* b) {
    asm volatile(
        "mma.sync.aligned.m16n8k16.row.col.f32.f16.f16.f32 "
        "{%0,%1,%2,%3}, {%4,%5,%6,%7}, {%8,%9}, {%0,%1,%2,%3};"
        : "+f"(c[0]), "+f"(c[1]), "+f"(c[2]), "+f"(c[3])
        : "r"(a[0]), "r"(a[1]), "r"(a[2]), "r"(a[3]), "r"(b[0]), "r"(b[1]));
}
// L1-allocating 16B async copy
__device__ __forceinline__ void cpa16(uint32_t dst, const void* src) {
    asm volatile("cp.async.ca.shared.global [%0], [%1], 16;"
                 :: "r"(dst), "l"(src) : "memory");
}

// fp16 convert+store of a float4 (one 8B store)
__device__ __forceinline__ void h_store(float4 v, char* dst) {
    __half2 p0 = __floats2half2_rn(v.x, v.y);
    __half2 p1 = __floats2half2_rn(v.z, v.w);
    uint2 P;
    P.x = *(uint32_t*)&p0;
    P.y = *(uint32_t*)&p1;
    *(uint2*)dst = P;
}

// ---------------------------------------------------------------------------
// prep_all: z-slots 0..4 = weight transpose to fp16 [n][k]; z-slot 5 =
// layer-0 effective h-bias (bh + Whq^T q0) for both directions.
// ---------------------------------------------------------------------------
__global__ void prep_all(const float* __restrict__ Wz_f, const float* __restrict__ Wh_f,
                         const float* __restrict__ Wz_b, const float* __restrict__ Wh_b,
                         const float* __restrict__ question,
                         const float* __restrict__ bh_f, const float* __restrict__ bh_b,
                         __half* __restrict__ wh16, float* __restrict__ bheff)
{
    int n = blockIdx.x, m = blockIdx.y, s = blockIdx.z, k = threadIdx.x;
    if (s == 5) {
        if (m >= 2) return;
        __shared__ float red[256];
        const float* Wh = m ? Wh_b : Wh_f;
        const float* bh = m ? bh_b : bh_f;
        red[k] = question[k] * Wh[(DD + k) * DD + n];
        __syncthreads();
        for (int st = 128; st > 0; st >>= 1) {
            if (k < st) red[k] += red[k + st];
            __syncthreads();
        }
        if (k == 0) bheff[m * DD + n] = bh[n] + red[0];
        return;
    }
    const float* Wz;
    const float* Wh;
    if (s < 3) { Wz = Wz_f + s * DD * DD; Wh = Wh_f + s * 2 * DD * DD; }
    else       { Wz = Wz_b + (s - 3) * DD * DD; Wh = Wh_b + (s - 3) * 2 * DD * DD; }
    float v = (m == 0) ? Wz[k * DD + n]
            : (m == 1) ? Wh[k * DD + n]
                       : Wh[(DD + k) * DD + n];
    wh16[(size_t)(s * 3 + m) * DD * DD + (size_t)n * DD + k] = __float2half_rn(v);
}

// ---------------------------------------------------------------------------
// prep_x: xh = fp16(story); uh = fp16(story * q0)   (layer-0 A planes)
// ---------------------------------------------------------------------------
__global__ void prep_x(const float* __restrict__ story,
                       const float* __restrict__ question,
                       __half* __restrict__ xh, __half* __restrict__ uh)
{
    int idx = blockIdx.x * 256 + threadIdx.x;   // float4 index
    int c = (idx & 63) << 2;
    float4 xv = ((const float4*)story)[idx];
    float4 qv = *(const float4*)(question + c);
    float4 uv = make_float4(xv.x * qv.x, xv.y * qv.y, xv.z * qv.z, xv.w * qv.w);
    h_store(xv, (char*)xh + (size_t)idx * 8);
    h_store(uv, (char*)uh + (size_t)idx * 8);
}

// ---------------------------------------------------------------------------
// Fused GEMM (fp16 mma.sync) + activation + block-local scan.
// All operand staging is cp.async from pre-staged fp16 planes.
// blockIdx.z = direction. 2 CTAs/SM.
// ---------------------------------------------------------------------------
__global__ void __launch_bounds__(256, 2) gemm_mma(
    const __half* __restrict__ uh, const __half* __restrict__ xh,
    const __half* __restrict__ qh,
    int use_q, int do_store,
    const __half* __restrict__ wh_f, const __half* __restrict__ wh_b,
    const float* __restrict__ bz_f, const float* __restrict__ bh_f,
    const float* __restrict__ bz_b, const float* __restrict__ bh_b,
    float* __restrict__ outA_f, float* __restrict__ outB_f,
    float* __restrict__ aggA_f, float* __restrict__ aggB_f,
    float* __restrict__ outA_b, float* __restrict__ outB_b,
    float* __restrict__ aggA_b, float* __restrict__ aggB_b)
{
    extern __shared__ char smem[];
    const int tid = threadIdx.x;
    const int wid = tid >> 5;
    const int lane = tid & 31;
    const int wm = wid & 3;
    const int wn = wid >> 2;
    const int nbase = blockIdx.x * BN;      // N fastest -> A-plane L2 reuse
    const int tbase = blockIdx.y * BM;
    const int mblk  = blockIdx.y;
    const int rev   = blockIdx.z;
    const uint32_t sb = smem_u32(smem);

    const __half* wh = rev ? wh_b : wh_f;
    const float* bz = rev ? bz_b : bz_f;
    const float* bh = rev ? bh_b : bh_f;
    float* outA = rev ? outA_b : outA_f;
    float* outB = rev ? outB_b : outB_f;
    float* aggA = rev ? aggA_b : aggA_f;
    float* aggB = rev ? aggB_b : aggB_f;

    float* bzs = (float*)(smem + SM_BIAS);
    float* bhs = bzs + 64;
    if (tid < 64) {
        bzs[tid] = bz[nbase + tid];
        bhs[tid] = bh[nbase + tid];
    }

    const __half* a3[3] = { uh, xh, qh };
    const __half* w3[3] = { wh, wh + DD * DD, wh + 2 * DD * DD };
    const int np = use_q ? 3 : 2;

    float acc[2][2][4][4];
    #pragma unroll
    for (int zh = 0; zh < 2; ++zh)
        #pragma unroll
        for (int mt = 0; mt < 2; ++mt)
            #pragma unroll
            for (int nt = 0; nt < 4; ++nt)
                #pragma unroll
                for (int j = 0; j < 4; ++j) acc[zh][mt][nt][j] = 0.f;

    // --- all-cp.async staging ---------------------------------------------
    const int wrow = tid >> 2;   // 0..63
    const int wseg = tid & 3;    // 16B segment of a 64B k-row

    auto stage = [&](int k0, int buf) {
        uint32_t abase = sb + buf * BUFSZ;
        uint32_t bbase = abase + 3 * A_TILE;
        #pragma unroll
        for (int p = 0; p < 3; ++p)
            if (p < np) {
                // A plane: 128 rows x 64B, 2 units per thread
                #pragma unroll
                for (int h = 0; h < 2; ++h) {
                    int row = wrow + h * 64;
                    int tg = rev ? (TT - 1 - (tbase + row)) : (tbase + row);
                    cpa16(abase + p * A_TILE + row * ROWB + wseg * 16,
                          a3[p] + (size_t)tg * DD + k0 + wseg * 8);
                }
                // B plane: 64 rows x 64B, 1 unit per thread
                cpa16(bbase + p * B_TILE + wrow * ROWB + wseg * 16,
                      w3[p] + (size_t)(nbase + wrow) * DD + k0 + wseg * 8);
            }
    };

    stage(0, 0);
    asm volatile("cp.async.commit_group;" ::: "memory");
    asm volatile("cp.async.wait_group 0;" ::: "memory");
    __syncthreads();

    const int r = lane & 7, g = lane >> 3;
    #pragma unroll 1
    for (int c = 0; c < NCHUNK; ++c) {
        const uint32_t abuf = sb + (c & 1) * BUFSZ;
        const uint32_t bbuf = abuf + 3 * A_TILE;

        // issue next chunk's copies before MMA block (latency covered by MMAs)
        if (c < NCHUNK - 1) {
            stage((c + 1) * KC, (c + 1) & 1);
            asm volatile("cp.async.commit_group;" ::: "memory");
        }

        #pragma unroll
        for (int ks = 0; ks < 2; ++ks) {
            const uint32_t kso = ks * 32;
            uint32_t af[3][2][4];
            #pragma unroll
            for (int o = 0; o < 3; ++o)
                if (o < np) {
                    #pragma unroll
                    for (int mt = 0; mt < 2; ++mt) {
                        uint32_t addr = abuf + o * A_TILE
                            + (wm * 32 + mt * 16 + (g & 1) * 8 + r) * ROWB
                            + (g >> 1) * 16 + kso;
                        ldsm4(addr, af[o][mt]);
                    }
                }
            uint32_t bf[3][4][2];
            #pragma unroll
            for (int m3 = 0; m3 < 3; ++m3)
                if (m3 < np) {
                    #pragma unroll
                    for (int j = 0; j < 2; ++j) {
                        uint32_t tmp[4];
                        uint32_t addr = bbuf + m3 * B_TILE
                            + (wn * 32 + (2 * j + (g >> 1)) * 8 + r) * ROWB
                            + (g & 1) * 16 + kso;
                        ldsm4(addr, tmp);
                        bf[m3][2 * j][0] = tmp[0]; bf[m3][2 * j][1] = tmp[1];
                        bf[m3][2 * j + 1][0] = tmp[2]; bf[m3][2 * j + 1][1] = tmp[3];
                    }
                }
            #pragma unroll
            for (int mt = 0; mt < 2; ++mt)
                #pragma unroll
                for (int nt = 0; nt < 4; ++nt) {
                    mma16816(acc[0][mt][nt], af[0][mt], bf[0][nt]);   // U @ Wz
                    mma16816(acc[1][mt][nt], af[1][mt], bf[1][nt]);   // X @ Whx
                    if (use_q)
                        mma16816(acc[1][mt][nt], af[2][mt], bf[2][nt]); // Q @ Whq
                }
        }
        if (c < NCHUNK - 1)
            asm volatile("cp.async.wait_group 0;" ::: "memory");
        __syncthreads();
    }

    // --- epilogue: activations -> smem transpose ---------------------------
    float* smA = (float*)smem;              // [128][68]
    float* smB = smA + 128 * 68;
    #pragma unroll
    for (int mt = 0; mt < 2; ++mt)
        #pragma unroll
        for (int nt = 0; nt < 4; ++nt) {
            int col = wn * 32 + nt * 8 + 2 * (lane & 3);
            int row0 = wm * 32 + mt * 16 + (lane >> 2);
            #pragma unroll
            for (int h8 = 0; h8 < 2; ++h8) {
                int row = row0 + h8 * 8;
                float z0 = 0.5f * tanh_fast(0.5f * (acc[0][mt][nt][2*h8+0] + bzs[col]))   + 0.5f;
                float z1 = 0.5f * tanh_fast(0.5f * (acc[0][mt][nt][2*h8+1] + bzs[col+1])) + 0.5f;
                float t0 = tanh_fast(acc[1][mt][nt][2*h8+0] + bhs[col]);
                float t1 = tanh_fast(acc[1][mt][nt][2*h8+1] + bhs[col+1]);
                *(float2*)(smA + row * 68 + col) = make_float2(1.f - z0, 1.f - z1);
                *(float2*)(smB + row * 68 + col) = make_float2(z0 * t0, z1 * t1);
            }
        }
    __syncthreads();

    // --- fused block-local scan over 128 rows (4 segments x 32) ------------
    float* segA = (float*)(smem + SM_SEG);        // [4][64]
    float* segB = segA + 4 * 64;
    {
        const int col = tid & 63;
        const int sg = tid >> 6;
        const int rbase = sg * 32;
        float Ap = 1.f, hl = 0.f;
        #pragma unroll 8
        for (int i = 0; i < 32; ++i) {
            int off = (rbase + i) * 68 + col;
            float a = smA[off], b = smB[off];
            Ap *= a;
            hl = fmaf(a, hl, b);
            if (do_store) { smA[off] = Ap; smB[off] = hl; }
        }
        segA[sg * 64 + col] = Ap;
        segB[sg * 64 + col] = hl;
        __syncthreads();
        float Ain = 1.f, Hin = 0.f;
        #pragma unroll
        for (int s = 0; s < 3; ++s)
            if (s < sg) {
                float sa = segA[s * 64 + col], sbv = segB[s * 64 + col];
                Ain *= sa;
                Hin = fmaf(sa, Hin, sbv);
            }
        if (do_store) {
            #pragma unroll 8
            for (int i = 0; i < 32; ++i) {
                int off = (rbase + i) * 68 + col;
                float Al = smA[off], Bl = smB[off];
                smA[off] = Ain * Al;
                smB[off] = fmaf(Al, Hin, Bl);
            }
        }
        if (sg == 3) {
            aggA[(size_t)mblk * DD + nbase + col] = Ain * Ap;
            aggB[(size_t)mblk * DD + nbase + col] = fmaf(Ap, Hin, hl);
        }
    }

    if (do_store) {
        __syncthreads();
        #pragma unroll
        for (int it = 0; it < 8; ++it) {
            int j = tid + it * 256;
            int row = j >> 4, cf = j & 15;
            size_t go = (size_t)(tbase + row) * DD + nbase + cf * 4;
            *(float4*)(outA + go) = *(const float4*)(smA + row * 68 + cf * 4);
            *(float4*)(outB + go) = *(const float4*)(smB + row * 68 + cf * 4);
        }
    }
}

// ---------------------------------------------------------------------------
// scan2a: per super-block (16 blocks) local scan. grid (NSUP, ndirs).
// ---------------------------------------------------------------------------
__global__ void scan2a_kernel(
    const float* __restrict__ aggAf, const float* __restrict__ aggBf,
    float* __restrict__ hexf, float* __restrict__ apref,
    float* __restrict__ supAf, float* __restrict__ supBf,
    const float* __restrict__ aggAb, const float* __restrict__ aggBb,
    float* __restrict__ hexb, float* __restrict__ apreb,
    float* __restrict__ supAb, float* __restrict__ supBb)
{
    const int dirb = blockIdx.y;
    const float* aggA = dirb ? aggAb : aggAf;
    const float* aggB = dirb ? aggBb : aggBf;
    float* hex  = dirb ? hexb : hexf;
    float* apre = dirb ? apreb : apref;
    float* supA = dirb ? supAb : supAf;
    float* supB = dirb ? supBb : supBf;

    const int s = blockIdx.x, d = threadIdx.x;
    float a[SBLK], b[SBLK];
    #pragma unroll
    for (int i = 0; i < SBLK; ++i) {
        size_t o = (size_t)(s * SBLK + i) * DD + d;
        a[i] = aggA[o];
        b[i] = aggB[o];
    }
    float H = 0.f, A = 1.f;
    #pragma unroll
    for (int i = 0; i < SBLK; ++i) {
        size_t o = (size_t)(s * SBLK + i) * DD + d;
        hex[o] = H;
        apre[o] = A;
        H = fmaf(a[i], H, b[i]);
        A *= a[i];
    }
    supA[(size_t)s * DD + d] = A;
    supB[(size_t)s * DD + d] = H;
}

// ---------------------------------------------------------------------------
// scan2b: scan over NSUP super-aggregates; optional final-state output.
// ---------------------------------------------------------------------------
__global__ void scan2b_kernel(
    const float* __restrict__ supAf, const float* __restrict__ supBf,
    float* __restrict__ hsupf,
    const float* __restrict__ supAb, const float* __restrict__ supBb,
    float* __restrict__ hsupb,
    float* __restrict__ out)
{
    const int dirb = blockIdx.x;
    const float* supA = dirb ? supAb : supAf;
    const float* supB = dirb ? supBb : supBf;
    float* hsup = dirb ? hsupb : hsupf;
    const int d = threadIdx.x;

    float a[NSUP / 2], b[NSUP / 2];
    float H = 0.f;
    #pragma unroll
    for (int half = 0; half < 2; ++half) {
        #pragma unroll
        for (int i = 0; i < NSUP / 2; ++i) {
            size_t o = (size_t)(half * (NSUP / 2) + i) * DD + d;
            a[i] = supA[o];
            b[i] = supB[o];
        }
        #pragma unroll
        for (int i = 0; i < NSUP / 2; ++i) {
            hsup[(size_t)(half * (NSUP / 2) + i) * DD + d] = H;
            H = fmaf(a[i], H, b[i]);
        }
    }
    if (out && dirb == 0) out[d] = H;
}

// ---------------------------------------------------------------------------
// scan2c: hex[b] = APre[b] * Hsup[b/16] + hexL[b]  (in place). grid(128, 2).
// ---------------------------------------------------------------------------
__global__ void scan2c_kernel(
    float* __restrict__ hexf, const float* __restrict__ apref,
    const float* __restrict__ hsupf,
    float* __restrict__ hexb, const float* __restrict__ apreb,
    const float* __restrict__ hsupb)
{
    const int dirb = blockIdx.y;
    float* hex = dirb ? hexb : hexf;
    const float* apre = dirb ? apreb : apref;
    const float* hsup = dirb ? hsupb : hsupf;

    int idx = blockIdx.x * 256 + threadIdx.x;
    int bblk = idx >> 6;
    int c = (idx & 63) << 2;
    int sup = bblk >> 4;

    float4 ap = *(const float4*)(apre + (size_t)bblk * DD + c);
    float4 hs = *(const float4*)(hsup + (size_t)sup * DD + c);
    float4 hx = *(const float4*)(hex + (size_t)bblk * DD + c);
    hx.x = fmaf(ap.x, hs.x, hx.x);
    hx.y = fmaf(ap.y, hs.y, hx.y);
    hx.z = fmaf(ap.z, hs.z, hx.z);
    hx.w = fmaf(ap.w, hs.w, hx.w);
    *(float4*)(hex + (size_t)bblk * DD + c) = hx;
}

// ---------------------------------------------------------------------------
// combine: q = h_fwd + h_bwd_rev (fixup on the fly); writes fp16 qh and
// uh = story*q directly (next layer's A planes).
// ---------------------------------------------------------------------------
__global__ void combine_kernel(
    const float* __restrict__ Af, const float* __restrict__ Bf,
    const float* __restrict__ hexf,
    const float* __restrict__ Ab, const float* __restrict__ Bb,
    const float* __restrict__ hexb,
    const float* __restrict__ story,
    __half* __restrict__ qh, __half* __restrict__ uh)
{
    int idx = blockIdx.x * blockDim.x + threadIdx.x;   // float4 index
    int t = idx >> 6;
    int c = (idx & 63) << 2;
    int tr = TT - 1 - t;
    int blf = t >> 7;
    int blb = tr >> 7;

    float4 af = *(const float4*)(Af + (size_t)t * DD + c);
    float4 bfv = *(const float4*)(Bf + (size_t)t * DD + c);
    float4 hf = *(const float4*)(hexf + (size_t)blf * DD + c);
    float4 ab = *(const float4*)(Ab + (size_t)tr * DD + c);
    float4 bb = *(const float4*)(Bb + (size_t)tr * DD + c);
    float4 hb = *(const float4*)(hexb + (size_t)blb * DD + c);

    float4 q4;
    q4.x = fmaf(af.x, hf.x, bfv.x) + fmaf(ab.x, hb.x, bb.x);
    q4.y = fmaf(af.y, hf.y, bfv.y) + fmaf(ab.y, hb.y, bb.y);
    q4.z = fmaf(af.z, hf.z, bfv.z) + fmaf(ab.z, hb.z, bb.z);
    q4.w = fmaf(af.w, hf.w, bfv.w) + fmaf(ab.w, hb.w, bb.w);

    float4 xv = *(const float4*)(story + (size_t)t * DD + c);
    float4 u4 = make_float4(xv.x * q4.x, xv.y * q4.y, xv.z * q4.z, xv.w * q4.w);

    h_store(q4, (char*)qh + (size_t)idx * 8);
    h_store(u4, (char*)uh + (size_t)idx * 8);
}

// ---------------------------------------------------------------------------
// Host orchestration
// ---------------------------------------------------------------------------
extern "C" void kernel_launch(void* const* d_in, const int* in_sizes, int n_in,
                              void* d_out, int out_size)
{
    const float* story    = (const float*)d_in[0];
    const float* question = (const float*)d_in[1];
    const float* Wz_f = (const float*)d_in[2];
    const float* bz_f = (const float*)d_in[3];
    const float* Wh_f = (const float*)d_in[4];
    const float* bh_f = (const float*)d_in[5];
    const float* Wz_b = (const float*)d_in[6];
    const float* bz_b = (const float*)d_in[7];
    const float* Wh_b = (const float*)d_in[8];
    const float* bh_b = (const float*)d_in[9];
    float* out = (float*)d_out;

    float *af, *bf, *ab, *bb;
    float *aggAf, *aggBf, *hexf, *apref, *aggAb, *aggBb, *hexb, *apreb;
    float *supAf, *supBf, *hsupf, *supAb, *supBb, *hsupb, *bheff;
    __half *wh16, *uhp, *xhp, *qhp;
    cudaGetSymbolAddress((void**)&af,    g_af);
    cudaGetSymbolAddress((void**)&bf,    g_bf);
    cudaGetSymbolAddress((void**)&ab,    g_ab);
    cudaGetSymbolAddress((void**)&bb,    g_bb);
    cudaGetSymbolAddress((void**)&aggAf, g_aggA_f);
    cudaGetSymbolAddress((void**)&aggBf, g_aggB_f);
    cudaGetSymbolAddress((void**)&hexf,  g_hex_f);
    cudaGetSymbolAddress((void**)&apref, g_apre_f);
    cudaGetSymbolAddress((void**)&aggAb, g_aggA_b);
    cudaGetSymbolAddress((void**)&aggBb, g_aggB_b);
    cudaGetSymbolAddress((void**)&hexb,  g_hex_b);
    cudaGetSymbolAddress((void**)&apreb, g_apre_b);
    cudaGetSymbolAddress((void**)&supAf, g_supA_f);
    cudaGetSymbolAddress((void**)&supBf, g_supB_f);
    cudaGetSymbolAddress((void**)&hsupf, g_hsup_f);
    cudaGetSymbolAddress((void**)&supAb, g_supA_b);
    cudaGetSymbolAddress((void**)&supBb, g_supB_b);
    cudaGetSymbolAddress((void**)&hsupb, g_hsup_b);
    cudaGetSymbolAddress((void**)&wh16,  g_wh16);
    cudaGetSymbolAddress((void**)&uhp,   g_uh);
    cudaGetSymbolAddress((void**)&xhp,   g_xh);
    cudaGetSymbolAddress((void**)&qhp,   g_qh);
    cudaGetSymbolAddress((void**)&bheff, g_bheff);

    static int smem_set = 0;
    if (!smem_set) {
        cudaFuncSetAttribute(gemm_mma, cudaFuncAttributeMaxDynamicSharedMemorySize,
                             SMEM_TOTAL);
        smem_set = 1;
    }

    prep_all<<<dim3(DD, 3, 6), 256>>>(Wz_f, Wh_f, Wz_b, Wh_b,
                                      question, bh_f, bh_b, wh16, bheff);
    prep_x<<<TT * DD / 4 / 256, 256>>>(story, question, xhp, uhp);

    const int MSZ = 3 * DD * DD;

    for (int l = 0; l < LL; ++l) {
        const int uq = (l == 0) ? 0 : 1;
        const float* bhf_eff = (l == 0) ? bheff : bh_f + l * DD;
        const float* bhb_eff = (l == 0) ? bheff + DD : bh_b + l * DD;

        if (l < LL - 1) {
            dim3 ggrid(DD / BN, TT / BM, 2);
            gemm_mma<<<ggrid, 256, SMEM_TOTAL>>>(
                uhp, xhp, qhp, uq, 1,
                wh16 + l * MSZ, wh16 + (3 + l) * MSZ,
                bz_f + l * DD, bhf_eff, bz_b + l * DD, bhb_eff,
                af, bf, aggAf, aggBf, ab, bb, aggAb, aggBb);

            scan2a_kernel<<<dim3(NSUP, 2), 256>>>(
                aggAf, aggBf, hexf, apref, supAf, supBf,
                aggAb, aggBb, hexb, apreb, supAb, supBb);
            scan2b_kernel<<<2, 256>>>(supAf, supBf, hsupf,
                                      supAb, supBb, hsupb, nullptr);
            scan2c_kernel<<<dim3(NB * DD / 4 / 256, 2), 256>>>(
                hexf, apref, hsupf, hexb, apreb, hsupb);

            combine_kernel<<<TT * DD / 4 / 256, 256>>>(
                af, bf, hexf, ab, bb, hexb, story, qhp, uhp);
        } else {
            dim3 ggrid(DD / BN, TT / BM, 1);
            gemm_mma<<<ggrid, 256, SMEM_TOTAL>>>(
                uhp, xhp, qhp, uq, 0,
                wh16 + l * MSZ, wh16 + l * MSZ,
                bz_f + l * DD, bhf_eff, bz_f + l * DD, bhf_eff,
                af, bf, aggAf, aggBf, af, bf, aggAf, aggBf);
            scan2a_kernel<<<dim3(NSUP, 1), 256>>>(
                aggAf, aggBf, hexf, apref, supAf, supBf,
                aggAb, aggBb, hexb, apreb, supAb, supBb);
            scan2b_kernel<<<1, 256>>>(supAf, supBf, hsupf,
                                      supAb, supBb, hsupb, out);
        }
    }
}

// round 16
// speedup vs baseline: 2.7346x; 1.0643x over previous
#include <cuda_runtime.h>
#include <cuda_bf16.h>
#include <cuda_fp16.h>
#include <stdint.h>
#include <math.h>

// Problem constants
#define TT 65536
#define DD 256
#define LL 3

// GEMM tiling (BM=128, BN=64, KC=32), fp16 single-plane operands
#define BM 128
#define BN 64
#define KC 32
#define NCHUNK (DD / KC)   // 8

#define ROWB 80                     // padded smem row stride (bytes)
#define A_TILE (128 * ROWB)         // 10240 B
#define B_TILE (64 * ROWB)          // 5120 B
#define BUFSZ  (3 * A_TILE + 3 * B_TILE)  // 46080 B
#define SM_BIAS (2 * BUFSZ)         // 92160
#define SMEM_TOTAL (SM_BIAS + 512 + 64)   // 92736 -> 2 CTAs/SM
#define SM_SEG (2 * 128 * 68 * 4)   // 69632 (epilogue seg aggregates)

// Scan blocking
#define CS 128
#define NB (TT / CS)   // 512
#define SBLK 16
#define NSUP (NB / SBLK)  // 32

// ---------------------------------------------------------------------------
// Scratch
// ---------------------------------------------------------------------------
// fp16 per-timestep intermediates (Aprefix, h_local) per direction
__device__ __align__(256) __half g_af[TT * DD];
__device__ __align__(256) __half g_bf[TT * DD];
__device__ __align__(256) __half g_ab[TT * DD];
__device__ __align__(256) __half g_bb[TT * DD];
__device__ __align__(256) float g_aggA_f[NB * DD];
__device__ __align__(256) float g_aggB_f[NB * DD];
__device__ __align__(256) float g_hex_f[NB * DD];
__device__ __align__(256) float g_apre_f[NB * DD];
__device__ __align__(256) float g_aggA_b[NB * DD];
__device__ __align__(256) float g_aggB_b[NB * DD];
__device__ __align__(256) float g_hex_b[NB * DD];
__device__ __align__(256) float g_apre_b[NB * DD];
__device__ __align__(256) float g_supA_f[NSUP * DD];
__device__ __align__(256) float g_supB_f[NSUP * DD];
__device__ __align__(256) float g_hsup_f[NSUP * DD];
__device__ __align__(256) float g_supA_b[NSUP * DD];
__device__ __align__(256) float g_supB_b[NSUP * DD];
__device__ __align__(256) float g_hsup_b[NSUP * DD];
// fp16 A-operand planes (pre-staged)
__device__ __align__(256) __half g_uh[TT * DD];
__device__ __align__(256) __half g_xh[TT * DD];
__device__ __align__(256) __half g_qh[TT * DD];
// fp16 pre-transposed weights: [5 layer-dirs][3 mats][256 n][256 k]
__device__ __align__(256) __half g_wh16[5 * 3 * DD * DD];
__device__ __align__(256) float g_bheff[2 * DD];

__device__ __forceinline__ float tanh_fast(float v) {
    float r;
    asm("tanh.approx.f32 %0, %1;" : "=f"(r) : "f"(v));
    return r;
}
__device__ __forceinline__ uint32_t smem_u32(const void* p) {
    uint32_t a;
    asm("{ .reg .u64 t; cvta.to.shared.u64 t, %1; cvt.u32.u64 %0, t; }"
        : "=r"(a) : "l"(p));
    return a;
}
__device__ __forceinline__ void ldsm4(uint32_t addr, uint32_t* r) {
    asm volatile("ldmatrix.sync.aligned.m8n8.x4.shared.b16 {%0,%1,%2,%3}, [%4];"
                 : "=r"(r[0]), "=r"(r[1]), "=r"(r[2]), "=r"(r[3]) : "r"(addr));
}
__device__ __forceinline__ void mma16816(float* c, const uint32_t* a,
                                         const uint32_t* b) {
    asm volatile(
        "mma.sync.aligned.m16n8k16.row.col.f32.f16.f16.f32 "
        "{%0,%1,%2,%3}, {%4,%5,%6,%7}, {%8,%9}, {%0,%1,%2,%3};"
        : "+f"(c[0]), "+f"(c[1]), "+f"(c[2]), "+f"(c[3])
        : "r"(a[0]), "r"(a[1]), "r"(a[2]), "r"(a[3]), "r"(b[0]), "r"(b[1]));
}
// L1-allocating 16B async copy
__device__ __forceinline__ void cpa16(uint32_t dst, const void* src) {
    asm volatile("cp.async.ca.shared.global [%0], [%1], 16;"
                 :: "r"(dst), "l"(src) : "memory");
}

// fp16 convert+store of a float4 (one 8B store)
__device__ __forceinline__ void h_store(float4 v, char* dst) {
    __half2 p0 = __floats2half2_rn(v.x, v.y);
    __half2 p1 = __floats2half2_rn(v.z, v.w);
    uint2 P;
    P.x = *(uint32_t*)&p0;
    P.y = *(uint32_t*)&p1;
    *(uint2*)dst = P;
}
// fp16 load of 4 values -> float4
__device__ __forceinline__ float4 h_load(const char* src) {
    uint2 P = *(const uint2*)src;
    __half2 p0 = *(__half2*)&P.x;
    __half2 p1 = *(__half2*)&P.y;
    float2 f0 = __half22float2(p0);
    float2 f1 = __half22float2(p1);
    return make_float4(f0.x, f0.y, f1.x, f1.y);
}
// 8 fp32 -> 8 fp16, one 16B store
__device__ __forceinline__ void h_store8(const float* v, char* dst) {
    __half2 p0 = __floats2half2_rn(v[0], v[1]);
    __half2 p1 = __floats2half2_rn(v[2], v[3]);
    __half2 p2 = __floats2half2_rn(v[4], v[5]);
    __half2 p3 = __floats2half2_rn(v[6], v[7]);
    uint4 P;
    P.x = *(uint32_t*)&p0;
    P.y = *(uint32_t*)&p1;
    P.z = *(uint32_t*)&p2;
    P.w = *(uint32_t*)&p3;
    *(uint4*)dst = P;
}

// ---------------------------------------------------------------------------
// prep_all: z-slots 0..4 = weight transpose to fp16 [n][k]; z-slot 5 =
// layer-0 effective h-bias (bh + Whq^T q0) for both directions.
// ---------------------------------------------------------------------------
__global__ void prep_all(const float* __restrict__ Wz_f, const float* __restrict__ Wh_f,
                         const float* __restrict__ Wz_b, const float* __restrict__ Wh_b,
                         const float* __restrict__ question,
                         const float* __restrict__ bh_f, const float* __restrict__ bh_b,
                         __half* __restrict__ wh16, float* __restrict__ bheff)
{
    int n = blockIdx.x, m = blockIdx.y, s = blockIdx.z, k = threadIdx.x;
    if (s == 5) {
        if (m >= 2) return;
        __shared__ float red[256];
        const float* Wh = m ? Wh_b : Wh_f;
        const float* bh = m ? bh_b : bh_f;
        red[k] = question[k] * Wh[(DD + k) * DD + n];
        __syncthreads();
        for (int st = 128; st > 0; st >>= 1) {
            if (k < st) red[k] += red[k + st];
            __syncthreads();
        }
        if (k == 0) bheff[m * DD + n] = bh[n] + red[0];
        return;
    }
    const float* Wz;
    const float* Wh;
    if (s < 3) { Wz = Wz_f + s * DD * DD; Wh = Wh_f + s * 2 * DD * DD; }
    else       { Wz = Wz_b + (s - 3) * DD * DD; Wh = Wh_b + (s - 3) * 2 * DD * DD; }
    float v = (m == 0) ? Wz[k * DD + n]
            : (m == 1) ? Wh[k * DD + n]
                       : Wh[(DD + k) * DD + n];
    wh16[(size_t)(s * 3 + m) * DD * DD + (size_t)n * DD + k] = __float2half_rn(v);
}

// ---------------------------------------------------------------------------
// prep_x: xh = fp16(story); uh = fp16(story * q0)   (layer-0 A planes)
// ---------------------------------------------------------------------------
__global__ void prep_x(const float* __restrict__ story,
                       const float* __restrict__ question,
                       __half* __restrict__ xh, __half* __restrict__ uh)
{
    int idx = blockIdx.x * 256 + threadIdx.x;   // float4 index
    int c = (idx & 63) << 2;
    float4 xv = ((const float4*)story)[idx];
    float4 qv = *(const float4*)(question + c);
    float4 uv = make_float4(xv.x * qv.x, xv.y * qv.y, xv.z * qv.z, xv.w * qv.w);
    h_store(xv, (char*)xh + (size_t)idx * 8);
    h_store(uv, (char*)uh + (size_t)idx * 8);
}

// ---------------------------------------------------------------------------
// Fused GEMM (fp16 mma.sync) + activation + block-local scan.
// All operand staging is cp.async from pre-staged fp16 planes.
// Outputs (Aprefix, h_local) stored as fp16. blockIdx.z = direction.
// ---------------------------------------------------------------------------
__global__ void __launch_bounds__(256, 2) gemm_mma(
    const __half* __restrict__ uh, const __half* __restrict__ xh,
    const __half* __restrict__ qh,
    int use_q, int do_store,
    const __half* __restrict__ wh_f, const __half* __restrict__ wh_b,
    const float* __restrict__ bz_f, const float* __restrict__ bh_f,
    const float* __restrict__ bz_b, const float* __restrict__ bh_b,
    __half* __restrict__ outA_f, __half* __restrict__ outB_f,
    float* __restrict__ aggA_f, float* __restrict__ aggB_f,
    __half* __restrict__ outA_b, __half* __restrict__ outB_b,
    float* __restrict__ aggA_b, float* __restrict__ aggB_b)
{
    extern __shared__ char smem[];
    const int tid = threadIdx.x;
    const int wid = tid >> 5;
    const int lane = tid & 31;
    const int wm = wid & 3;
    const int wn = wid >> 2;
    const int nbase = blockIdx.x * BN;      // N fastest -> A-plane L2 reuse
    const int tbase = blockIdx.y * BM;
    const int mblk  = blockIdx.y;
    const int rev   = blockIdx.z;
    const uint32_t sb = smem_u32(smem);

    const __half* wh = rev ? wh_b : wh_f;
    const float* bz = rev ? bz_b : bz_f;
    const float* bh = rev ? bh_b : bh_f;
    __half* outA = rev ? outA_b : outA_f;
    __half* outB = rev ? outB_b : outB_f;
    float* aggA = rev ? aggA_b : aggA_f;
    float* aggB = rev ? aggB_b : aggB_f;

    float* bzs = (float*)(smem + SM_BIAS);
    float* bhs = bzs + 64;
    if (tid < 64) {
        bzs[tid] = bz[nbase + tid];
        bhs[tid] = bh[nbase + tid];
    }

    const __half* a3[3] = { uh, xh, qh };
    const __half* w3[3] = { wh, wh + DD * DD, wh + 2 * DD * DD };
    const int np = use_q ? 3 : 2;

    float acc[2][2][4][4];
    #pragma unroll
    for (int zh = 0; zh < 2; ++zh)
        #pragma unroll
        for (int mt = 0; mt < 2; ++mt)
            #pragma unroll
            for (int nt = 0; nt < 4; ++nt)
                #pragma unroll
                for (int j = 0; j < 4; ++j) acc[zh][mt][nt][j] = 0.f;

    // --- all-cp.async staging ---------------------------------------------
    const int wrow = tid >> 2;   // 0..63
    const int wseg = tid & 3;    // 16B segment of a 64B k-row

    auto stage = [&](int k0, int buf) {
        uint32_t abase = sb + buf * BUFSZ;
        uint32_t bbase = abase + 3 * A_TILE;
        #pragma unroll
        for (int p = 0; p < 3; ++p)
            if (p < np) {
                #pragma unroll
                for (int h = 0; h < 2; ++h) {
                    int row = wrow + h * 64;
                    int tg = rev ? (TT - 1 - (tbase + row)) : (tbase + row);
                    cpa16(abase + p * A_TILE + row * ROWB + wseg * 16,
                          a3[p] + (size_t)tg * DD + k0 + wseg * 8);
                }
                cpa16(bbase + p * B_TILE + wrow * ROWB + wseg * 16,
                      w3[p] + (size_t)(nbase + wrow) * DD + k0 + wseg * 8);
            }
    };

    stage(0, 0);
    asm volatile("cp.async.commit_group;" ::: "memory");
    asm volatile("cp.async.wait_group 0;" ::: "memory");
    __syncthreads();

    const int r = lane & 7, g = lane >> 3;
    #pragma unroll 1
    for (int c = 0; c < NCHUNK; ++c) {
        const uint32_t abuf = sb + (c & 1) * BUFSZ;
        const uint32_t bbuf = abuf + 3 * A_TILE;

        if (c < NCHUNK - 1) {
            stage((c + 1) * KC, (c + 1) & 1);
            asm volatile("cp.async.commit_group;" ::: "memory");
        }

        #pragma unroll
        for (int ks = 0; ks < 2; ++ks) {
            const uint32_t kso = ks * 32;
            uint32_t af[3][2][4];
            #pragma unroll
            for (int o = 0; o < 3; ++o)
                if (o < np) {
                    #pragma unroll
                    for (int mt = 0; mt < 2; ++mt) {
                        uint32_t addr = abuf + o * A_TILE
                            + (wm * 32 + mt * 16 + (g & 1) * 8 + r) * ROWB
                            + (g >> 1) * 16 + kso;
                        ldsm4(addr, af[o][mt]);
                    }
                }
            uint32_t bf[3][4][2];
            #pragma unroll
            for (int m3 = 0; m3 < 3; ++m3)
                if (m3 < np) {
                    #pragma unroll
                    for (int j = 0; j < 2; ++j) {
                        uint32_t tmp[4];
                        uint32_t addr = bbuf + m3 * B_TILE
                            + (wn * 32 + (2 * j + (g >> 1)) * 8 + r) * ROWB
                            + (g & 1) * 16 + kso;
                        ldsm4(addr, tmp);
                        bf[m3][2 * j][0] = tmp[0]; bf[m3][2 * j][1] = tmp[1];
                        bf[m3][2 * j + 1][0] = tmp[2]; bf[m3][2 * j + 1][1] = tmp[3];
                    }
                }
            #pragma unroll
            for (int mt = 0; mt < 2; ++mt)
                #pragma unroll
                for (int nt = 0; nt < 4; ++nt) {
                    mma16816(acc[0][mt][nt], af[0][mt], bf[0][nt]);   // U @ Wz
                    mma16816(acc[1][mt][nt], af[1][mt], bf[1][nt]);   // X @ Whx
                    if (use_q)
                        mma16816(acc[1][mt][nt], af[2][mt], bf[2][nt]); // Q @ Whq
                }
        }
        if (c < NCHUNK - 1)
            asm volatile("cp.async.wait_group 0;" ::: "memory");
        __syncthreads();
    }

    // --- epilogue: activations -> smem transpose ---------------------------
    float* smA = (float*)smem;              // [128][68]
    float* smB = smA + 128 * 68;
    #pragma unroll
    for (int mt = 0; mt < 2; ++mt)
        #pragma unroll
        for (int nt = 0; nt < 4; ++nt) {
            int col = wn * 32 + nt * 8 + 2 * (lane & 3);
            int row0 = wm * 32 + mt * 16 + (lane >> 2);
            #pragma unroll
            for (int h8 = 0; h8 < 2; ++h8) {
                int row = row0 + h8 * 8;
                float z0 = 0.5f * tanh_fast(0.5f * (acc[0][mt][nt][2*h8+0] + bzs[col]))   + 0.5f;
                float z1 = 0.5f * tanh_fast(0.5f * (acc[0][mt][nt][2*h8+1] + bzs[col+1])) + 0.5f;
                float t0 = tanh_fast(acc[1][mt][nt][2*h8+0] + bhs[col]);
                float t1 = tanh_fast(acc[1][mt][nt][2*h8+1] + bhs[col+1]);
                *(float2*)(smA + row * 68 + col) = make_float2(1.f - z0, 1.f - z1);
                *(float2*)(smB + row * 68 + col) = make_float2(z0 * t0, z1 * t1);
            }
        }
    __syncthreads();

    // --- fused block-local scan over 128 rows (4 segments x 32) ------------
    float* segA = (float*)(smem + SM_SEG);        // [4][64]
    float* segB = segA + 4 * 64;
    {
        const int col = tid & 63;
        const int sg = tid >> 6;
        const int rbase = sg * 32;
        float Ap = 1.f, hl = 0.f;
        #pragma unroll 8
        for (int i = 0; i < 32; ++i) {
            int off = (rbase + i) * 68 + col;
            float a = smA[off], b = smB[off];
            Ap *= a;
            hl = fmaf(a, hl, b);
            if (do_store) { smA[off] = Ap; smB[off] = hl; }
        }
        segA[sg * 64 + col] = Ap;
        segB[sg * 64 + col] = hl;
        __syncthreads();
        float Ain = 1.f, Hin = 0.f;
        #pragma unroll
        for (int s = 0; s < 3; ++s)
            if (s < sg) {
                float sa = segA[s * 64 + col], sbv = segB[s * 64 + col];
                Ain *= sa;
                Hin = fmaf(sa, Hin, sbv);
            }
        if (do_store) {
            #pragma unroll 8
            for (int i = 0; i < 32; ++i) {
                int off = (rbase + i) * 68 + col;
                float Al = smA[off], Bl = smB[off];
                smA[off] = Ain * Al;
                smB[off] = fmaf(Al, Hin, Bl);
            }
        }
        if (sg == 3) {
            aggA[(size_t)mblk * DD + nbase + col] = Ain * Ap;
            aggB[(size_t)mblk * DD + nbase + col] = fmaf(Ap, Hin, hl);
        }
    }

    if (do_store) {
        __syncthreads();
        // fp16 stores: 128 rows x 64 cols x 2B = 16KB per plane, 4 uint4/thread
        #pragma unroll
        for (int it = 0; it < 4; ++it) {
            int j = tid + it * 256;
            int row = j >> 3, seg = j & 7;   // 8 halfs (16B) per segment
            size_t go = (size_t)(tbase + row) * DD + nbase + seg * 8;
            h_store8(smA + row * 68 + seg * 8, (char*)(outA + go));
            h_store8(smB + row * 68 + seg * 8, (char*)(outB + go));
        }
    }
}

// ---------------------------------------------------------------------------
// scan2a: per super-block (16 blocks) local scan. grid (NSUP, ndirs).
// ---------------------------------------------------------------------------
__global__ void scan2a_kernel(
    const float* __restrict__ aggAf, const float* __restrict__ aggBf,
    float* __restrict__ hexf, float* __restrict__ apref,
    float* __restrict__ supAf, float* __restrict__ supBf,
    const float* __restrict__ aggAb, const float* __restrict__ aggBb,
    float* __restrict__ hexb, float* __restrict__ apreb,
    float* __restrict__ supAb, float* __restrict__ supBb)
{
    const int dirb = blockIdx.y;
    const float* aggA = dirb ? aggAb : aggAf;
    const float* aggB = dirb ? aggBb : aggBf;
    float* hex  = dirb ? hexb : hexf;
    float* apre = dirb ? apreb : apref;
    float* supA = dirb ? supAb : supAf;
    float* supB = dirb ? supBb : supBf;

    const int s = blockIdx.x, d = threadIdx.x;
    float a[SBLK], b[SBLK];
    #pragma unroll
    for (int i = 0; i < SBLK; ++i) {
        size_t o = (size_t)(s * SBLK + i) * DD + d;
        a[i] = aggA[o];
        b[i] = aggB[o];
    }
    float H = 0.f, A = 1.f;
    #pragma unroll
    for (int i = 0; i < SBLK; ++i) {
        size_t o = (size_t)(s * SBLK + i) * DD + d;
        hex[o] = H;
        apre[o] = A;
        H = fmaf(a[i], H, b[i]);
        A *= a[i];
    }
    supA[(size_t)s * DD + d] = A;
    supB[(size_t)s * DD + d] = H;
}

// ---------------------------------------------------------------------------
// scan2b: scan over NSUP super-aggregates; optional final-state output.
// ---------------------------------------------------------------------------
__global__ void scan2b_kernel(
    const float* __restrict__ supAf, const float* __restrict__ supBf,
    float* __restrict__ hsupf,
    const float* __restrict__ supAb, const float* __restrict__ supBb,
    float* __restrict__ hsupb,
    float* __restrict__ out)
{
    const int dirb = blockIdx.x;
    const float* supA = dirb ? supAb : supAf;
    const float* supB = dirb ? supBb : supBf;
    float* hsup = dirb ? hsupb : hsupf;
    const int d = threadIdx.x;

    float a[NSUP / 2], b[NSUP / 2];
    float H = 0.f;
    #pragma unroll
    for (int half = 0; half < 2; ++half) {
        #pragma unroll
        for (int i = 0; i < NSUP / 2; ++i) {
            size_t o = (size_t)(half * (NSUP / 2) + i) * DD + d;
            a[i] = supA[o];
            b[i] = supB[o];
        }
        #pragma unroll
        for (int i = 0; i < NSUP / 2; ++i) {
            hsup[(size_t)(half * (NSUP / 2) + i) * DD + d] = H;
            H = fmaf(a[i], H, b[i]);
        }
    }
    if (out && dirb == 0) out[d] = H;
}

// ---------------------------------------------------------------------------
// scan2c: hex[b] = APre[b] * Hsup[b/16] + hexL[b]  (in place). grid(128, 2).
// ---------------------------------------------------------------------------
__global__ void scan2c_kernel(
    float* __restrict__ hexf, const float* __restrict__ apref,
    const float* __restrict__ hsupf,
    float* __restrict__ hexb, const float* __restrict__ apreb,
    const float* __restrict__ hsupb)
{
    const int dirb = blockIdx.y;
    float* hex = dirb ? hexb : hexf;
    const float* apre = dirb ? apreb : apref;
    const float* hsup = dirb ? hsupb : hsupf;

    int idx = blockIdx.x * 256 + threadIdx.x;
    int bblk = idx >> 6;
    int c = (idx & 63) << 2;
    int sup = bblk >> 4;

    float4 ap = *(const float4*)(apre + (size_t)bblk * DD + c);
    float4 hs = *(const float4*)(hsup + (size_t)sup * DD + c);
    float4 hx = *(const float4*)(hex + (size_t)bblk * DD + c);
    hx.x = fmaf(ap.x, hs.x, hx.x);
    hx.y = fmaf(ap.y, hs.y, hx.y);
    hx.z = fmaf(ap.z, hs.z, hx.z);
    hx.w = fmaf(ap.w, hs.w, hx.w);
    *(float4*)(hex + (size_t)bblk * DD + c) = hx;
}

// ---------------------------------------------------------------------------
// combine: q = h_fwd + h_bwd_rev (fixup on the fly); fp16 intermediates in,
// fp16 (qh, uh = story*q) out.
// ---------------------------------------------------------------------------
__global__ void combine_kernel(
    const __half* __restrict__ Af, const __half* __restrict__ Bf,
    const float* __restrict__ hexf,
    const __half* __restrict__ Ab, const __half* __restrict__ Bb,
    const float* __restrict__ hexb,
    const float* __restrict__ story,
    __half* __restrict__ qh, __half* __restrict__ uh)
{
    int idx = blockIdx.x * blockDim.x + threadIdx.x;   // 4-elem group index
    int t = idx >> 6;
    int c = (idx & 63) << 2;
    int tr = TT - 1 - t;
    int blf = t >> 7;
    int blb = tr >> 7;

    float4 af = h_load((const char*)(Af + (size_t)t * DD + c));
    float4 bfv = h_load((const char*)(Bf + (size_t)t * DD + c));
    float4 hf = *(const float4*)(hexf + (size_t)blf * DD + c);
    float4 ab = h_load((const char*)(Ab + (size_t)tr * DD + c));
    float4 bb = h_load((const char*)(Bb + (size_t)tr * DD + c));
    float4 hb = *(const float4*)(hexb + (size_t)blb * DD + c);

    float4 q4;
    q4.x = fmaf(af.x, hf.x, bfv.x) + fmaf(ab.x, hb.x, bb.x);
    q4.y = fmaf(af.y, hf.y, bfv.y) + fmaf(ab.y, hb.y, bb.y);
    q4.z = fmaf(af.z, hf.z, bfv.z) + fmaf(ab.z, hb.z, bb.z);
    q4.w = fmaf(af.w, hf.w, bfv.w) + fmaf(ab.w, hb.w, bb.w);

    float4 xv = *(const float4*)(story + (size_t)t * DD + c);
    float4 u4 = make_float4(xv.x * q4.x, xv.y * q4.y, xv.z * q4.z, xv.w * q4.w);

    h_store(q4, (char*)(qh + (size_t)idx * 4));
    h_store(u4, (char*)(uh + (size_t)idx * 4));
}

// ---------------------------------------------------------------------------
// Host orchestration
// ---------------------------------------------------------------------------
extern "C" void kernel_launch(void* const* d_in, const int* in_sizes, int n_in,
                              void* d_out, int out_size)
{
    const float* story    = (const float*)d_in[0];
    const float* question = (const float*)d_in[1];
    const float* Wz_f = (const float*)d_in[2];
    const float* bz_f = (const float*)d_in[3];
    const float* Wh_f = (const float*)d_in[4];
    const float* bh_f = (const float*)d_in[5];
    const float* Wz_b = (const float*)d_in[6];
    const float* bz_b = (const float*)d_in[7];
    const float* Wh_b = (const float*)d_in[8];
    const float* bh_b = (const float*)d_in[9];
    float* out = (float*)d_out;

    __half *af, *bf, *ab, *bb;
    float *aggAf, *aggBf, *hexf, *apref, *aggAb, *aggBb, *hexb, *apreb;
    float *supAf, *supBf, *hsupf, *supAb, *supBb, *hsupb, *bheff;
    __half *wh16, *uhp, *xhp, *qhp;
    cudaGetSymbolAddress((void**)&af,    g_af);
    cudaGetSymbolAddress((void**)&bf,    g_bf);
    cudaGetSymbolAddress((void**)&ab,    g_ab);
    cudaGetSymbolAddress((void**)&bb,    g_bb);
    cudaGetSymbolAddress((void**)&aggAf, g_aggA_f);
    cudaGetSymbolAddress((void**)&aggBf, g_aggB_f);
    cudaGetSymbolAddress((void**)&hexf,  g_hex_f);
    cudaGetSymbolAddress((void**)&apref, g_apre_f);
    cudaGetSymbolAddress((void**)&aggAb, g_aggA_b);
    cudaGetSymbolAddress((void**)&aggBb, g_aggB_b);
    cudaGetSymbolAddress((void**)&hexb,  g_hex_b);
    cudaGetSymbolAddress((void**)&apreb, g_apre_b);
    cudaGetSymbolAddress((void**)&supAf, g_supA_f);
    cudaGetSymbolAddress((void**)&supBf, g_supB_f);
    cudaGetSymbolAddress((void**)&hsupf, g_hsup_f);
    cudaGetSymbolAddress((void**)&supAb, g_supA_b);
    cudaGetSymbolAddress((void**)&supBb, g_supB_b);
    cudaGetSymbolAddress((void**)&hsupb, g_hsup_b);
    cudaGetSymbolAddress((void**)&wh16,  g_wh16);
    cudaGetSymbolAddress((void**)&uhp,   g_uh);
    cudaGetSymbolAddress((void**)&xhp,   g_xh);
    cudaGetSymbolAddress((void**)&qhp,   g_qh);
    cudaGetSymbolAddress((void**)&bheff, g_bheff);

    static int smem_set = 0;
    if (!smem_set) {
        cudaFuncSetAttribute(gemm_mma, cudaFuncAttributeMaxDynamicSharedMemorySize,
                             SMEM_TOTAL);
        smem_set = 1;
    }

    prep_all<<<dim3(DD, 3, 6), 256>>>(Wz_f, Wh_f, Wz_b, Wh_b,
                                      question, bh_f, bh_b, wh16, bheff);
    prep_x<<<TT * DD / 4 / 256, 256>>>(story, question, xhp, uhp);

    const int MSZ = 3 * DD * DD;

    for (int l = 0; l < LL; ++l) {
        const int uq = (l == 0) ? 0 : 1;
        const float* bhf_eff = (l == 0) ? bheff : bh_f + l * DD;
        const float* bhb_eff = (l == 0) ? bheff + DD : bh_b + l * DD;

        if (l < LL - 1) {
            dim3 ggrid(DD / BN, TT / BM, 2);
            gemm_mma<<<ggrid, 256, SMEM_TOTAL>>>(
                uhp, xhp, qhp, uq, 1,
                wh16 + l * MSZ, wh16 + (3 + l) * MSZ,
                bz_f + l * DD, bhf_eff, bz_b + l * DD, bhb_eff,
                af, bf, aggAf, aggBf, ab, bb, aggAb, aggBb);

            scan2a_kernel<<<dim3(NSUP, 2), 256>>>(
                aggAf, aggBf, hexf, apref, supAf, supBf,
                aggAb, aggBb, hexb, apreb, supAb, supBb);
            scan2b_kernel<<<2, 256>>>(supAf, supBf, hsupf,
                                      supAb, supBb, hsupb, nullptr);
            scan2c_kernel<<<dim3(NB * DD / 4 / 256, 2), 256>>>(
                hexf, apref, hsupf, hexb, apreb, hsupb);

            combine_kernel<<<TT * DD / 4 / 256, 256>>>(
                af, bf, hexf, ab, bb, hexb, story, qhp, uhp);
        } else {
            dim3 ggrid(DD / BN, TT / BM, 1);
            gemm_mma<<<ggrid, 256, SMEM_TOTAL>>>(
                uhp, xhp, qhp, uq, 0,
                wh16 + l * MSZ, wh16 + l * MSZ,
                bz_f + l * DD, bhf_eff, bz_f + l * DD, bhf_eff,
                af, bf, aggAf, aggBf, af, bf, aggAf, aggBf);
            scan2a_kernel<<<dim3(NSUP, 1), 256>>>(
                aggAf, aggBf, hexf, apref, supAf, supBf,
                aggAb, aggBb, hexb, apreb, supAb, supBb);
            scan2b_kernel<<<1, 256>>>(supAf, supBf, hsupf,
                                      supAb, supBb, hsupb, out);
        }
    }
}